// round 2
// baseline (speedup 1.0000x reference)
#include <cuda_runtime.h>

// Fixed problem shape (per dataset)
#define NHEADS 16
#define HDIM   64
#define DMODEL 1024
#define BATCH  2
#define SEQ    2048
#define BSROWS (BATCH*SEQ)   // 4096

// Scratch for Q,K,V in [B, N, S, H] layout (allowed: __device__ globals)
__device__ float g_q[BATCH*NHEADS*SEQ*HDIM];
__device__ float g_k[BATCH*NHEADS*SEQ*HDIM];
__device__ float g_v[BATCH*NHEADS*SEQ*HDIM];

// ---------------------------------------------------------------------------
// Kernel 1: QKV projection GEMM.  z = 0/1/2 -> Q/K/V.
// C[m,n] = X[m,:] @ W[:,n] + bias[n], written into [B,N,S,H] scratch.
// 64x64 tile, BK=16, 256 threads, 4x4 per-thread register tile.
// ---------------------------------------------------------------------------
__global__ __launch_bounds__(256) void qkv_proj_kernel(
    const float* __restrict__ from_t, const float* __restrict__ to_t,
    const float* __restrict__ Wq, const float* __restrict__ bq,
    const float* __restrict__ Wk, const float* __restrict__ bk,
    const float* __restrict__ Wv, const float* __restrict__ bv)
{
    __shared__ float As[16][68];   // [k][m], padded
    __shared__ float Bs[16][68];   // [k][n], padded

    const int z = blockIdx.z;
    const float* X    = (z == 0) ? from_t : to_t;
    const float* W    = (z == 0) ? Wq : (z == 1 ? Wk : Wv);
    const float* bias = (z == 0) ? bq : (z == 1 ? bk : bv);
    float* dst        = (z == 0) ? g_q : (z == 1 ? g_k : g_v);

    const int m0 = blockIdx.y * 64;
    const int n0 = blockIdx.x * 64;
    const int tid = threadIdx.x;
    const int tx = tid & 15;       // n direction
    const int ty = tid >> 4;       // m direction

    // A-tile loader mapping: 64 rows x 16 k, float4 along k (transposed store)
    const int am = tid >> 2;
    const int ak = (tid & 3) * 4;
    // B-tile loader mapping: 16 k x 64 n, float4 along n
    const int bkr = tid >> 4;
    const int bn  = (tid & 15) * 4;

    float acc[4][4] = {};

    for (int k0 = 0; k0 < DMODEL; k0 += 16) {
        float4 a4 = *(const float4*)&X[(m0 + am) * DMODEL + k0 + ak];
        As[ak + 0][am] = a4.x;
        As[ak + 1][am] = a4.y;
        As[ak + 2][am] = a4.z;
        As[ak + 3][am] = a4.w;
        *(float4*)&Bs[bkr][bn] = *(const float4*)&W[(k0 + bkr) * DMODEL + n0 + bn];
        __syncthreads();

        #pragma unroll
        for (int k = 0; k < 16; k++) {
            float4 a = *(float4*)&As[k][ty * 4];
            float4 b = *(float4*)&Bs[k][tx * 4];
            acc[0][0] += a.x * b.x; acc[0][1] += a.x * b.y; acc[0][2] += a.x * b.z; acc[0][3] += a.x * b.w;
            acc[1][0] += a.y * b.x; acc[1][1] += a.y * b.y; acc[1][2] += a.y * b.z; acc[1][3] += a.y * b.w;
            acc[2][0] += a.z * b.x; acc[2][1] += a.z * b.y; acc[2][2] += a.z * b.z; acc[2][3] += a.z * b.w;
            acc[3][0] += a.w * b.x; acc[3][1] += a.w * b.y; acc[3][2] += a.w * b.z; acc[3][3] += a.w * b.w;
        }
        __syncthreads();
    }

    // Epilogue: bias add, scatter into [B,N,S,H]
    float4 bb = *(const float4*)&bias[n0 + tx * 4];
    const float bias_j[4] = {bb.x, bb.y, bb.z, bb.w};
    #pragma unroll
    for (int i = 0; i < 4; i++) {
        int m = m0 + ty * 4 + i;
        int b = m >> 11;          // m / SEQ
        int s = m & (SEQ - 1);
        #pragma unroll
        for (int j = 0; j < 4; j++) {
            int n = n0 + tx * 4 + j;
            int head = n >> 6;
            int h = n & 63;
            dst[((b * NHEADS + head) * SEQ + s) * HDIM + h] = acc[i][j] + bias_j[j];
        }
    }
}

// ---------------------------------------------------------------------------
// Kernel 2: flash attention (fp32, online softmax), one block per
// (b, head, 64-row f-tile). Streams K/V in 64-row chunks.
// ---------------------------------------------------------------------------
__global__ __launch_bounds__(256) void attn_kernel(
    const int* __restrict__ mask, float* __restrict__ out)
{
    extern __shared__ float sm[];
    float* Qt    = sm;                 // [64][68]  Qt[h][f]
    float* Kt    = Qt + 64 * 68;       // [64][68]  Kt[h][t]
    float* Vs    = Kt + 64 * 68;       // [64][68]  Vs[t][h]
    float* St    = Vs + 64 * 68;       // [64][68]  St[t][f]  (scores, then P)
    float* row_m = St + 64 * 68;       // [64]
    float* row_l = row_m + 64;         // [64]
    float* row_a = row_l + 64;         // [64]

    const int f0   = blockIdx.x * 64;
    const int head = blockIdx.y;
    const int b    = blockIdx.z;
    const int tid  = threadIdx.x;
    const int tx = tid & 15;   // t (phase S) / h (phase O)
    const int ty = tid >> 4;   // f

    const float* Qg = g_q + (b * NHEADS + head) * SEQ * HDIM;
    const float* Kg = g_k + (b * NHEADS + head) * SEQ * HDIM;
    const float* Vg = g_v + (b * NHEADS + head) * SEQ * HDIM;

    // loader mapping: row = tid/4, columns lq + {0,16,32,48} (4 float4s/thread
    // -> full 64x64 tile with 256 threads)
    const int lm = tid >> 2;
    const int lq = (tid & 3) * 4;

    {   // load Q tile transposed: Qt[h][f]
        #pragma unroll
        for (int cc = 0; cc < 4; cc++) {
            int col = lq + cc * 16;
            float4 q4 = *(const float4*)&Qg[(f0 + lm) * HDIM + col];
            Qt[(col + 0) * 68 + lm] = q4.x;
            Qt[(col + 1) * 68 + lm] = q4.y;
            Qt[(col + 2) * 68 + lm] = q4.z;
            Qt[(col + 3) * 68 + lm] = q4.w;
        }
    }
    if (tid < 64) { row_m[tid] = -1e30f; row_l[tid] = 0.0f; }

    float o[4][4] = {};

    // stats-pass mapping: 4 threads per f-row, each covers 16 t's
    const int fq = tid >> 2;
    const int qq = tid & 3;

    for (int t0 = 0; t0 < SEQ; t0 += 64) {
        __syncthreads();   // previous chunk fully consumed

        {   // load K transposed + V direct (full 64x64 tiles)
            #pragma unroll
            for (int cc = 0; cc < 4; cc++) {
                int col = lq + cc * 16;
                float4 k4 = *(const float4*)&Kg[(t0 + lm) * HDIM + col];
                Kt[(col + 0) * 68 + lm] = k4.x;
                Kt[(col + 1) * 68 + lm] = k4.y;
                Kt[(col + 2) * 68 + lm] = k4.z;
                Kt[(col + 3) * 68 + lm] = k4.w;
                *(float4*)&Vs[lm * 68 + col] = *(const float4*)&Vg[(t0 + lm) * HDIM + col];
            }
        }
        __syncthreads();

        // S[f][t] = sum_h Q[f][h] * K[t][h]
        float c[4][4] = {};
        #pragma unroll 16
        for (int h = 0; h < 64; h++) {
            float4 a = *(float4*)&Qt[h * 68 + ty * 4];
            float4 v = *(float4*)&Kt[h * 68 + tx * 4];
            c[0][0] += a.x * v.x; c[0][1] += a.x * v.y; c[0][2] += a.x * v.z; c[0][3] += a.x * v.w;
            c[1][0] += a.y * v.x; c[1][1] += a.y * v.y; c[1][2] += a.y * v.z; c[1][3] += a.y * v.w;
            c[2][0] += a.z * v.x; c[2][1] += a.z * v.y; c[2][2] += a.z * v.z; c[2][3] += a.z * v.w;
            c[3][0] += a.w * v.x; c[3][1] += a.w * v.y; c[3][2] += a.w * v.z; c[3][3] += a.w * v.w;
        }

        // scale + additive mask
        #pragma unroll
        for (int i = 0; i < 4; i++) {
            int f = f0 + ty * 4 + i;
            int4 mk = *(const int4*)&mask[(b * SEQ + f) * SEQ + t0 + tx * 4];
            c[i][0] = c[i][0] * 0.125f + (1.0f - (float)mk.x) * -10000.0f;
            c[i][1] = c[i][1] * 0.125f + (1.0f - (float)mk.y) * -10000.0f;
            c[i][2] = c[i][2] * 0.125f + (1.0f - (float)mk.z) * -10000.0f;
            c[i][3] = c[i][3] * 0.125f + (1.0f - (float)mk.w) * -10000.0f;
        }
        // store transposed: St[t][f]
        #pragma unroll
        for (int j = 0; j < 4; j++) {
            *(float4*)&St[(tx * 4 + j) * 68 + ty * 4] =
                make_float4(c[0][j], c[1][j], c[2][j], c[3][j]);
        }
        __syncthreads();

        // row max over this chunk
        float lmax = -1e30f;
        #pragma unroll
        for (int s = 0; s < 16; s++)
            lmax = fmaxf(lmax, St[(qq * 16 + s) * 68 + fq]);
        lmax = fmaxf(lmax, __shfl_xor_sync(0xffffffffu, lmax, 1));
        lmax = fmaxf(lmax, __shfl_xor_sync(0xffffffffu, lmax, 2));
        if (qq == 0) {
            float mo = row_m[fq];
            float mn = fmaxf(mo, lmax);
            row_a[fq] = __expf(mo - mn);
            row_m[fq] = mn;
        }
        __syncthreads();

        // exponentiate + partial row sums
        float mn = row_m[fq];
        float ps = 0.0f;
        #pragma unroll
        for (int s = 0; s < 16; s++) {
            int idx = (qq * 16 + s) * 68 + fq;
            float p = __expf(St[idx] - mn);
            St[idx] = p;
            ps += p;
        }
        ps += __shfl_xor_sync(0xffffffffu, ps, 1);
        ps += __shfl_xor_sync(0xffffffffu, ps, 2);
        if (qq == 0) row_l[fq] = row_l[fq] * row_a[fq] + ps;
        __syncthreads();

        // rescale O, then O += P @ V
        float al0 = row_a[ty * 4 + 0];
        float al1 = row_a[ty * 4 + 1];
        float al2 = row_a[ty * 4 + 2];
        float al3 = row_a[ty * 4 + 3];
        #pragma unroll
        for (int j = 0; j < 4; j++) {
            o[0][j] *= al0; o[1][j] *= al1; o[2][j] *= al2; o[3][j] *= al3;
        }
        #pragma unroll 16
        for (int t = 0; t < 64; t++) {
            float4 a = *(float4*)&St[t * 68 + ty * 4];   // P^T[t][f..]
            float4 v = *(float4*)&Vs[t * 68 + tx * 4];   // V[t][h..]
            o[0][0] += a.x * v.x; o[0][1] += a.x * v.y; o[0][2] += a.x * v.z; o[0][3] += a.x * v.w;
            o[1][0] += a.y * v.x; o[1][1] += a.y * v.y; o[1][2] += a.y * v.z; o[1][3] += a.y * v.w;
            o[2][0] += a.z * v.x; o[2][1] += a.z * v.y; o[2][2] += a.z * v.z; o[2][3] += a.z * v.w;
            o[3][0] += a.w * v.x; o[3][1] += a.w * v.y; o[3][2] += a.w * v.z; o[3][3] += a.w * v.w;
        }
    }

    // final normalize + write out[b, f, head*64 + h]
    #pragma unroll
    for (int i = 0; i < 4; i++) {
        int f = f0 + ty * 4 + i;
        float inv = 1.0f / row_l[ty * 4 + i];
        float4 r = make_float4(o[i][0] * inv, o[i][1] * inv, o[i][2] * inv, o[i][3] * inv);
        *(float4*)&out[(b * SEQ + f) * DMODEL + head * HDIM + tx * 4] = r;
    }
}

// ---------------------------------------------------------------------------
extern "C" void kernel_launch(void* const* d_in, const int* in_sizes, int n_in,
                              void* d_out, int out_size)
{
    const float* from_t = (const float*)d_in[0];
    const float* to_t   = (const float*)d_in[1];
    const int*   mask   = (const int*)  d_in[2];
    const float* Wq = (const float*)d_in[3];
    const float* bq = (const float*)d_in[4];
    const float* Wk = (const float*)d_in[5];
    const float* bk = (const float*)d_in[6];
    const float* Wv = (const float*)d_in[7];
    const float* bv = (const float*)d_in[8];
    float* out = (float*)d_out;

    // QKV projections: 16 n-tiles x 64 m-tiles x 3 matrices
    dim3 pgrid(DMODEL / 64, BSROWS / 64, 3);
    qkv_proj_kernel<<<pgrid, 256>>>(from_t, to_t, Wq, bq, Wk, bk, Wv, bv);

    // Flash attention
    const int smem_bytes = (4 * 64 * 68 + 3 * 64) * sizeof(float);  // 70400
    cudaFuncSetAttribute(attn_kernel,
                         cudaFuncAttributeMaxDynamicSharedMemorySize, smem_bytes);
    dim3 agrid(SEQ / 64, NHEADS, BATCH);
    attn_kernel<<<agrid, 256, smem_bytes>>>(mask, out);
}

// round 3
// speedup vs baseline: 2.0408x; 2.0408x over previous
#include <cuda_runtime.h>
#include <cuda_bf16.h>
#include <cstdint>

#define NHEADS 16
#define HDIM   64
#define DMODEL 1024
#define BATCH  2
#define SEQ    2048
#define BSROWS (BATCH*SEQ)   // 4096

// Scratch for Q,K,V in [B, N, S, H] layout
__device__ float g_q[BATCH*NHEADS*SEQ*HDIM];
__device__ float g_k[BATCH*NHEADS*SEQ*HDIM];
__device__ float g_v[BATCH*NHEADS*SEQ*HDIM];

// ---------------------------------------------------------------------------
// helpers: bf16x3 split + m16n8k16 bf16 mma
// ---------------------------------------------------------------------------
__device__ __forceinline__ void split_pair(float x, float y, uint32_t& hi, uint32_t& lo)
{
    __nv_bfloat16 xh = __float2bfloat16(x);
    __nv_bfloat16 yh = __float2bfloat16(y);
    __nv_bfloat16 xl = __float2bfloat16(x - __bfloat162float(xh));
    __nv_bfloat16 yl = __float2bfloat16(y - __bfloat162float(yh));
    __nv_bfloat162 h2 = __halves2bfloat162(xh, yh);   // .x = low 16 bits (k even)
    __nv_bfloat162 l2 = __halves2bfloat162(xl, yl);
    hi = *reinterpret_cast<uint32_t*>(&h2);
    lo = *reinterpret_cast<uint32_t*>(&l2);
}

__device__ __forceinline__ void mma_bf16(float* d,
    uint32_t a0, uint32_t a1, uint32_t a2, uint32_t a3,
    uint32_t b0, uint32_t b1)
{
    asm volatile(
        "mma.sync.aligned.m16n8k16.row.col.f32.bf16.bf16.f32 "
        "{%0,%1,%2,%3}, {%4,%5,%6,%7}, {%8,%9}, {%0,%1,%2,%3};\n"
        : "+f"(d[0]), "+f"(d[1]), "+f"(d[2]), "+f"(d[3])
        : "r"(a0), "r"(a1), "r"(a2), "r"(a3), "r"(b0), "r"(b1));
}

// ---------------------------------------------------------------------------
// Kernel 1: QKV projection, bf16x3 tensor-core GEMM.
// Block tile M=128, N=64, K-iter=32. 8 warps (4m x 2n), warp tile 32x32.
// smem holds packed bf16-pair u32 arrays: A[m][k/2], B[n][k/2] (hi & lo).
// ---------------------------------------------------------------------------
__global__ __launch_bounds__(256) void qkv_proj_kernel(
    const float* __restrict__ from_t, const float* __restrict__ to_t,
    const float* __restrict__ Wq, const float* __restrict__ bq,
    const float* __restrict__ Wk, const float* __restrict__ bk,
    const float* __restrict__ Wv, const float* __restrict__ bv)
{
    // stride 20 u32 (K/2=16 + pad): 20*g mod 32 spaced by 4 -> conflict-free frags
    __shared__ uint32_t AH[128*20], AL[128*20];
    __shared__ uint32_t BH[64*20],  BL[64*20];

    const int z = blockIdx.z;
    const float* X    = (z == 0) ? from_t : to_t;
    const float* W    = (z == 0) ? Wq : (z == 1 ? Wk : Wv);
    const float* bias = (z == 0) ? bq : (z == 1 ? bk : bv);
    float* dst        = (z == 0) ? g_q : (z == 1 ? g_k : g_v);

    const int m0 = blockIdx.y * 128;
    const int n0 = blockIdx.x * 64;
    const int tid  = threadIdx.x;
    const int wid  = tid >> 5;
    const int lane = tid & 31;
    const int g  = lane >> 2;
    const int tg = lane & 3;
    const int wm = (wid >> 1) * 32;   // warp m offset (0..96)
    const int wn = (wid & 1) * 32;    // warp n offset (0 or 32)

    // B loader mapping (transpose k-major): kp = k-pair idx, n4 = n group of 4
    const int kp = tid & 15;
    const int n4 = tid >> 4;

    float acc[2][4][4] = {};

    for (int k0 = 0; k0 < DMODEL; k0 += 32) {
        // --- load A tile 128x32, split to bf16 hi/lo pairs ---
        #pragma unroll
        for (int p = 0; p < 4; p++) {
            int idx = tid + p * 256;
            int r = idx >> 3;
            int c = (idx & 7) * 4;
            float4 a = *(const float4*)&X[(m0 + r) * DMODEL + k0 + c];
            uint32_t h0, l0, h1, l1;
            split_pair(a.x, a.y, h0, l0);
            split_pair(a.z, a.w, h1, l1);
            AH[r*20 + (c>>1)]     = h0;  AH[r*20 + (c>>1) + 1] = h1;
            AL[r*20 + (c>>1)]     = l0;  AL[r*20 + (c>>1) + 1] = l1;
        }
        // --- load B tile 32k x 64n, transposed to [n][k/2] pairs ---
        {
            float4 w0 = *(const float4*)&W[(k0 + 2*kp)     * DMODEL + n0 + n4*4];
            float4 w1 = *(const float4*)&W[(k0 + 2*kp + 1) * DMODEL + n0 + n4*4];
            float r0[4] = {w0.x, w0.y, w0.z, w0.w};
            float r1[4] = {w1.x, w1.y, w1.z, w1.w};
            #pragma unroll
            for (int j = 0; j < 4; j++) {
                uint32_t hi, lo;
                split_pair(r0[j], r1[j], hi, lo);    // pair along k
                BH[(n4*4 + j)*20 + kp] = hi;
                BL[(n4*4 + j)*20 + kp] = lo;
            }
        }
        __syncthreads();

        #pragma unroll
        for (int ks = 0; ks < 2; ks++) {
            int kb = ks * 8;
            uint32_t ah[2][4], al[2][4];
            #pragma unroll
            for (int mi = 0; mi < 2; mi++) {
                int r = wm + mi*16;
                ah[mi][0] = AH[(r+g)*20   + kb+tg];
                ah[mi][1] = AH[(r+g+8)*20 + kb+tg];
                ah[mi][2] = AH[(r+g)*20   + kb+tg+4];
                ah[mi][3] = AH[(r+g+8)*20 + kb+tg+4];
                al[mi][0] = AL[(r+g)*20   + kb+tg];
                al[mi][1] = AL[(r+g+8)*20 + kb+tg];
                al[mi][2] = AL[(r+g)*20   + kb+tg+4];
                al[mi][3] = AL[(r+g+8)*20 + kb+tg+4];
            }
            #pragma unroll
            for (int ni = 0; ni < 4; ni++) {
                int n = wn + ni*8 + g;
                uint32_t bh0 = BH[n*20 + kb+tg], bh1 = BH[n*20 + kb+tg+4];
                uint32_t bl0 = BL[n*20 + kb+tg], bl1 = BL[n*20 + kb+tg+4];
                #pragma unroll
                for (int mi = 0; mi < 2; mi++) {
                    mma_bf16(acc[mi][ni], ah[mi][0],ah[mi][1],ah[mi][2],ah[mi][3], bh0, bh1);
                    mma_bf16(acc[mi][ni], ah[mi][0],ah[mi][1],ah[mi][2],ah[mi][3], bl0, bl1);
                    mma_bf16(acc[mi][ni], al[mi][0],al[mi][1],al[mi][2],al[mi][3], bh0, bh1);
                }
            }
        }
        __syncthreads();
    }

    // --- epilogue: bias + scatter to [B,N,S,H] scratch ---
    const int head = n0 >> 6;           // N-tile aligned to head boundary
    #pragma unroll
    for (int ni = 0; ni < 4; ni++) {
        int h = wn + ni*8 + 2*tg;       // local head dim (even)
        float2 b2 = *(const float2*)&bias[n0 + h];
        #pragma unroll
        for (int mi = 0; mi < 2; mi++) {
            int r0 = m0 + wm + mi*16 + g;
            int r1 = r0 + 8;
            int b0i = r0 >> 11, s0 = r0 & (SEQ-1);
            int b1i = r1 >> 11, s1 = r1 & (SEQ-1);
            float2 v0 = make_float2(acc[mi][ni][0] + b2.x, acc[mi][ni][1] + b2.y);
            float2 v1 = make_float2(acc[mi][ni][2] + b2.x, acc[mi][ni][3] + b2.y);
            *(float2*)&dst[((b0i*NHEADS + head)*SEQ + s0)*HDIM + h] = v0;
            *(float2*)&dst[((b1i*NHEADS + head)*SEQ + s1)*HDIM + h] = v1;
        }
    }
}

// ---------------------------------------------------------------------------
// Kernel 2: flash attention with bf16x3 tensor cores.
// Block: 128 f-rows x (64 h). 8 warps, warp owns 16 f-rows x full 64 t-chunk
// -> softmax stats are warp-local (quad shfl only).
// ---------------------------------------------------------------------------
#define ATTN_STRIDE 36   // u32 stride for [row][k/2] arrays (K/2=32 + pad)

__global__ __launch_bounds__(256) void attn_kernel(
    const int* __restrict__ mask, float* __restrict__ out)
{
    extern __shared__ uint32_t smu[];
    uint32_t* QH = smu;               // 128*36
    uint32_t* QL = QH + 128*36;
    uint32_t* KH = QL + 128*36;       // 64*36  [t][h/2]
    uint32_t* KL = KH + 64*36;
    uint32_t* VH = KL + 64*36;        // 64*36  [h][t/2]  (transposed)
    uint32_t* VL = VH + 64*36;
    uint32_t* PH = VL + 64*36;        // 128*36 [f][t/2]
    uint32_t* PL = PH + 128*36;

    const int f0   = blockIdx.x * 128;
    const int head = blockIdx.y;
    const int b    = blockIdx.z;
    const int tid  = threadIdx.x;
    const int wid  = tid >> 5;
    const int lane = tid & 31;
    const int g  = lane >> 2;
    const int tg = lane & 3;
    const int fb = wid * 16;          // warp's f-row base within block

    const float* Qg = g_q + (b*NHEADS + head)*SEQ*HDIM;
    const float* Kg = g_k + (b*NHEADS + head)*SEQ*HDIM;
    const float* Vg = g_v + (b*NHEADS + head)*SEQ*HDIM;

    // --- load Q tile 128x64, split ---
    #pragma unroll
    for (int p = 0; p < 8; p++) {
        int idx = tid + p * 256;
        int r = idx >> 4;
        int c = (idx & 15) * 4;
        float4 q = *(const float4*)&Qg[(f0 + r)*HDIM + c];
        uint32_t h0, l0, h1, l1;
        split_pair(q.x, q.y, h0, l0);
        split_pair(q.z, q.w, h1, l1);
        QH[r*ATTN_STRIDE + (c>>1)]     = h0;  QH[r*ATTN_STRIDE + (c>>1)+1] = h1;
        QL[r*ATTN_STRIDE + (c>>1)]     = l0;  QL[r*ATTN_STRIDE + (c>>1)+1] = l1;
    }

    float m0 = -1e30f, m1 = -1e30f;   // row maxes (rows fb+g, fb+g+8)
    float l0s = 0.0f, l1s = 0.0f;     // row sums
    float O[8][4] = {};

    const int frow0 = f0 + fb + g;
    const int frow1 = frow0 + 8;

    for (int t0 = 0; t0 < SEQ; t0 += 64) {
        __syncthreads();   // prev K/V fully consumed

        // --- load K tile 64x64 -> [t][h/2] pairs ---
        #pragma unroll
        for (int p = 0; p < 4; p++) {
            int idx = tid + p * 256;
            int r = idx >> 4;
            int c = (idx & 15) * 4;
            float4 k = *(const float4*)&Kg[(t0 + r)*HDIM + c];
            uint32_t h0, l0, h1, l1;
            split_pair(k.x, k.y, h0, l0);
            split_pair(k.z, k.w, h1, l1);
            KH[r*ATTN_STRIDE + (c>>1)]   = h0;  KH[r*ATTN_STRIDE + (c>>1)+1] = h1;
            KL[r*ATTN_STRIDE + (c>>1)]   = l0;  KL[r*ATTN_STRIDE + (c>>1)+1] = l1;
        }
        // --- load V tile 64x64 transposed -> [h][t/2] pairs ---
        #pragma unroll
        for (int p = 0; p < 2; p++) {
            int idx = tid + p * 256;
            int tp = idx & 31;        // t-pair index
            int h4 = idx >> 5;        // h group of 4 (0..15)
            float4 r0 = *(const float4*)&Vg[(t0 + 2*tp    )*HDIM + h4*4];
            float4 r1 = *(const float4*)&Vg[(t0 + 2*tp + 1)*HDIM + h4*4];
            float a[4] = {r0.x, r0.y, r0.z, r0.w};
            float c[4] = {r1.x, r1.y, r1.z, r1.w};
            #pragma unroll
            for (int j = 0; j < 4; j++) {
                uint32_t hi, lo;
                split_pair(a[j], c[j], hi, lo);   // pair along t
                VH[(h4*4 + j)*ATTN_STRIDE + tp] = hi;
                VL[(h4*4 + j)*ATTN_STRIDE + tp] = lo;
            }
        }
        __syncthreads();

        // --- S = Q K^T (bf16x3), warp: 16f x 64t ---
        float s[8][4] = {};
        #pragma unroll
        for (int ks = 0; ks < 4; ks++) {
            int kb = ks * 8;
            uint32_t ah0 = QH[(fb+g)*ATTN_STRIDE   + kb+tg];
            uint32_t ah1 = QH[(fb+g+8)*ATTN_STRIDE + kb+tg];
            uint32_t ah2 = QH[(fb+g)*ATTN_STRIDE   + kb+tg+4];
            uint32_t ah3 = QH[(fb+g+8)*ATTN_STRIDE + kb+tg+4];
            uint32_t al0 = QL[(fb+g)*ATTN_STRIDE   + kb+tg];
            uint32_t al1 = QL[(fb+g+8)*ATTN_STRIDE + kb+tg];
            uint32_t al2 = QL[(fb+g)*ATTN_STRIDE   + kb+tg+4];
            uint32_t al3 = QL[(fb+g+8)*ATTN_STRIDE + kb+tg+4];
            #pragma unroll
            for (int nt = 0; nt < 8; nt++) {
                int tr = nt*8 + g;
                uint32_t bh0 = KH[tr*ATTN_STRIDE + kb+tg], bh1 = KH[tr*ATTN_STRIDE + kb+tg+4];
                uint32_t bl0 = KL[tr*ATTN_STRIDE + kb+tg], bl1 = KL[tr*ATTN_STRIDE + kb+tg+4];
                mma_bf16(s[nt], ah0,ah1,ah2,ah3, bh0,bh1);
                mma_bf16(s[nt], ah0,ah1,ah2,ah3, bl0,bl1);
                mma_bf16(s[nt], al0,al1,al2,al3, bh0,bh1);
            }
        }

        // --- scale + additive mask, track chunk row max ---
        float rmax0 = -1e30f, rmax1 = -1e30f;
        #pragma unroll
        for (int nt = 0; nt < 8; nt++) {
            int tc = t0 + nt*8 + 2*tg;
            int2 mk0 = *(const int2*)&mask[(b*SEQ + frow0)*SEQ + tc];
            int2 mk1 = *(const int2*)&mask[(b*SEQ + frow1)*SEQ + tc];
            s[nt][0] = s[nt][0]*0.125f + (1.0f - (float)mk0.x) * -10000.0f;
            s[nt][1] = s[nt][1]*0.125f + (1.0f - (float)mk0.y) * -10000.0f;
            s[nt][2] = s[nt][2]*0.125f + (1.0f - (float)mk1.x) * -10000.0f;
            s[nt][3] = s[nt][3]*0.125f + (1.0f - (float)mk1.y) * -10000.0f;
            rmax0 = fmaxf(rmax0, fmaxf(s[nt][0], s[nt][1]));
            rmax1 = fmaxf(rmax1, fmaxf(s[nt][2], s[nt][3]));
        }
        rmax0 = fmaxf(rmax0, __shfl_xor_sync(0xffffffffu, rmax0, 1));
        rmax0 = fmaxf(rmax0, __shfl_xor_sync(0xffffffffu, rmax0, 2));
        rmax1 = fmaxf(rmax1, __shfl_xor_sync(0xffffffffu, rmax1, 1));
        rmax1 = fmaxf(rmax1, __shfl_xor_sync(0xffffffffu, rmax1, 2));

        float mn0 = fmaxf(m0, rmax0), mn1 = fmaxf(m1, rmax1);
        float a0 = __expf(m0 - mn0), a1 = __expf(m1 - mn1);
        m0 = mn0; m1 = mn1;

        __syncwarp();   // PH/PL reads from prior chunk's PV done across warp

        // --- exponentiate, partial sums, write P (split) ---
        float ps0 = 0.0f, ps1 = 0.0f;
        #pragma unroll
        for (int nt = 0; nt < 8; nt++) {
            float p00 = __expf(s[nt][0] - mn0);
            float p01 = __expf(s[nt][1] - mn0);
            float p10 = __expf(s[nt][2] - mn1);
            float p11 = __expf(s[nt][3] - mn1);
            ps0 += p00 + p01;
            ps1 += p10 + p11;
            uint32_t hi, lo;
            split_pair(p00, p01, hi, lo);
            PH[(fb+g)*ATTN_STRIDE + nt*4+tg] = hi;
            PL[(fb+g)*ATTN_STRIDE + nt*4+tg] = lo;
            split_pair(p10, p11, hi, lo);
            PH[(fb+g+8)*ATTN_STRIDE + nt*4+tg] = hi;
            PL[(fb+g+8)*ATTN_STRIDE + nt*4+tg] = lo;
        }
        ps0 += __shfl_xor_sync(0xffffffffu, ps0, 1);
        ps0 += __shfl_xor_sync(0xffffffffu, ps0, 2);
        ps1 += __shfl_xor_sync(0xffffffffu, ps1, 1);
        ps1 += __shfl_xor_sync(0xffffffffu, ps1, 2);
        l0s = l0s * a0 + ps0;
        l1s = l1s * a1 + ps1;

        // rescale O
        #pragma unroll
        for (int ht = 0; ht < 8; ht++) {
            O[ht][0] *= a0; O[ht][1] *= a0;
            O[ht][2] *= a1; O[ht][3] *= a1;
        }
        __syncwarp();   // P visible warp-wide

        // --- O += P V (bf16x3) ---
        #pragma unroll
        for (int ks = 0; ks < 4; ks++) {
            int kb = ks * 8;
            uint32_t ah0 = PH[(fb+g)*ATTN_STRIDE   + kb+tg];
            uint32_t ah1 = PH[(fb+g+8)*ATTN_STRIDE + kb+tg];
            uint32_t ah2 = PH[(fb+g)*ATTN_STRIDE   + kb+tg+4];
            uint32_t ah3 = PH[(fb+g+8)*ATTN_STRIDE + kb+tg+4];
            uint32_t al0 = PL[(fb+g)*ATTN_STRIDE   + kb+tg];
            uint32_t al1 = PL[(fb+g+8)*ATTN_STRIDE + kb+tg];
            uint32_t al2 = PL[(fb+g)*ATTN_STRIDE   + kb+tg+4];
            uint32_t al3 = PL[(fb+g+8)*ATTN_STRIDE + kb+tg+4];
            #pragma unroll
            for (int ht = 0; ht < 8; ht++) {
                int hr = ht*8 + g;
                uint32_t bh0 = VH[hr*ATTN_STRIDE + kb+tg], bh1 = VH[hr*ATTN_STRIDE + kb+tg+4];
                uint32_t bl0 = VL[hr*ATTN_STRIDE + kb+tg], bl1 = VL[hr*ATTN_STRIDE + kb+tg+4];
                mma_bf16(O[ht], ah0,ah1,ah2,ah3, bh0,bh1);
                mma_bf16(O[ht], ah0,ah1,ah2,ah3, bl0,bl1);
                mma_bf16(O[ht], al0,al1,al2,al3, bh0,bh1);
            }
        }
    }

    // --- final normalize + write out[b, f, head*64 + h] ---
    float inv0 = 1.0f / l0s;
    float inv1 = 1.0f / l1s;
    #pragma unroll
    for (int ht = 0; ht < 8; ht++) {
        int h = ht*8 + 2*tg;
        float2 r0 = make_float2(O[ht][0]*inv0, O[ht][1]*inv0);
        float2 r1 = make_float2(O[ht][2]*inv1, O[ht][3]*inv1);
        *(float2*)&out[(b*SEQ + frow0)*DMODEL + head*HDIM + h] = r0;
        *(float2*)&out[(b*SEQ + frow1)*DMODEL + head*HDIM + h] = r1;
    }
}

// ---------------------------------------------------------------------------
extern "C" void kernel_launch(void* const* d_in, const int* in_sizes, int n_in,
                              void* d_out, int out_size)
{
    const float* from_t = (const float*)d_in[0];
    const float* to_t   = (const float*)d_in[1];
    const int*   mask   = (const int*)  d_in[2];
    const float* Wq = (const float*)d_in[3];
    const float* bq = (const float*)d_in[4];
    const float* Wk = (const float*)d_in[5];
    const float* bk = (const float*)d_in[6];
    const float* Wv = (const float*)d_in[7];
    const float* bv = (const float*)d_in[8];
    float* out = (float*)d_out;

    dim3 pgrid(DMODEL / 64, BSROWS / 128, 3);
    qkv_proj_kernel<<<pgrid, 256>>>(from_t, to_t, Wq, bq, Wk, bk, Wv, bv);

    // attn smem: (2*128*36 + 4*64*36 + 2*128*36) u32 = 27648 u32 = 110592 B
    const int smem_bytes = 27648 * 4;
    cudaFuncSetAttribute(attn_kernel,
                         cudaFuncAttributeMaxDynamicSharedMemorySize, smem_bytes);
    dim3 agrid(SEQ / 128, NHEADS, BATCH);
    attn_kernel<<<agrid, 256, smem_bytes>>>(mask, out);
}

// round 4
// speedup vs baseline: 2.3009x; 1.1275x over previous
#include <cuda_runtime.h>
#include <cuda_bf16.h>
#include <cstdint>

#define NHEADS 16
#define HDIM   64
#define DMODEL 1024
#define BATCH  2
#define SEQ    2048
#define BSROWS 4096          // BATCH*SEQ
#define HP     32            // HDIM/2  (bf16 pairs per head row)
#define KPD    512           // DMODEL/2

// --- packed bf16 hi/lo global scratch ---------------------------------------
__device__ uint32_t g_xh[2*BSROWS*KPD],  g_xl[2*BSROWS*KPD];     // from(0)+to(1), [m][k/2]
__device__ uint32_t g_wh[3*KPD*DMODEL],  g_wl[3*KPD*DMODEL];     // [z][k/2][n]
__device__ uint32_t g_qh[BATCH*NHEADS*SEQ*HP], g_ql[BATCH*NHEADS*SEQ*HP];   // [bh][s][h/2]
__device__ uint32_t g_kh[BATCH*NHEADS*SEQ*HP], g_kl[BATCH*NHEADS*SEQ*HP];   // [bh][s][h/2]
__device__ uint32_t g_vh[BATCH*NHEADS*SEQ*HP], g_vl[BATCH*NHEADS*SEQ*HP];   // [bh][s][h/2]
__device__ uint32_t g_vth[BATCH*NHEADS*HDIM*(SEQ/2)], g_vtl[BATCH*NHEADS*HDIM*(SEQ/2)]; // [bh][h][s/2]

// ---------------------------------------------------------------------------
__device__ __forceinline__ void split_pair(float x, float y, uint32_t& hi, uint32_t& lo)
{
    __nv_bfloat16 xh = __float2bfloat16(x);
    __nv_bfloat16 yh = __float2bfloat16(y);
    __nv_bfloat16 xl = __float2bfloat16(x - __bfloat162float(xh));
    __nv_bfloat16 yl = __float2bfloat16(y - __bfloat162float(yh));
    __nv_bfloat162 h2 = __halves2bfloat162(xh, yh);
    __nv_bfloat162 l2 = __halves2bfloat162(xl, yl);
    hi = *reinterpret_cast<uint32_t*>(&h2);
    lo = *reinterpret_cast<uint32_t*>(&l2);
}

__device__ __forceinline__ void mma_bf16(float* d,
    uint32_t a0, uint32_t a1, uint32_t a2, uint32_t a3,
    uint32_t b0, uint32_t b1)
{
    asm volatile(
        "mma.sync.aligned.m16n8k16.row.col.f32.bf16.bf16.f32 "
        "{%0,%1,%2,%3}, {%4,%5,%6,%7}, {%8,%9}, {%0,%1,%2,%3};\n"
        : "+f"(d[0]), "+f"(d[1]), "+f"(d[2]), "+f"(d[3])
        : "r"(a0), "r"(a1), "r"(a2), "r"(a3), "r"(b0), "r"(b1));
}

// ---------------------------------------------------------------------------
// Prep 1: split X (from rows 0..4095, to rows 4096..8191) into bf16 pairs
// ---------------------------------------------------------------------------
__global__ __launch_bounds__(256) void pack_x_kernel(
    const float* __restrict__ from_t, const float* __restrict__ to_t)
{
    int r = blockIdx.x;                 // 0..8191
    int c4 = threadIdx.x;               // 0..255 (float4 index)
    const float* src = (r < BSROWS) ? (from_t + r*DMODEL)
                                    : (to_t + (r - BSROWS)*DMODEL);
    float4 f = *(const float4*)&src[c4*4];
    uint32_t h0,l0,h1,l1;
    split_pair(f.x, f.y, h0, l0);
    split_pair(f.z, f.w, h1, l1);
    uint2 h2 = make_uint2(h0, h1), l2 = make_uint2(l0, l1);
    *(uint2*)&g_xh[r*KPD + c4*2] = h2;
    *(uint2*)&g_xl[r*KPD + c4*2] = l2;
}

// ---------------------------------------------------------------------------
// Prep 2: pack W (3 matrices) into [k/2][n] bf16-pair layout
// ---------------------------------------------------------------------------
__global__ __launch_bounds__(256) void pack_w_kernel(
    const float* __restrict__ Wq, const float* __restrict__ Wk,
    const float* __restrict__ Wv)
{
    int gid = blockIdx.x * 256 + threadIdx.x;       // over 3*512*1024
    int z = gid >> 19;
    int rem = gid & ((1<<19)-1);
    int kp = rem >> 10;
    int n  = rem & 1023;
    const float* W = (z == 0) ? Wq : (z == 1 ? Wk : Wv);
    float w0 = W[(2*kp)*DMODEL + n];
    float w1 = W[(2*kp+1)*DMODEL + n];
    uint32_t hi, lo;
    split_pair(w0, w1, hi, lo);
    g_wh[gid] = hi;
    g_wl[gid] = lo;
}

// ---------------------------------------------------------------------------
// Kernel: QKV projection GEMM on packed bf16 operands (bf16x3).
// Block 128m x 64n, 8 warps (4m x 2n), warp 32x32, K-iter 32.
// ---------------------------------------------------------------------------
__global__ __launch_bounds__(256) void qkv_proj_kernel(
    const float* __restrict__ bq, const float* __restrict__ bk,
    const float* __restrict__ bv)
{
    __shared__ uint32_t AH[128*20], AL[128*20];   // [m][k/2] stride 20
    __shared__ uint32_t BH[16*68],  BL[16*68];    // [k/2][n] stride 68

    const int z = blockIdx.z;
    const uint32_t* Xh = g_xh + (z == 0 ? 0 : BSROWS*KPD);
    const uint32_t* Xl = g_xl + (z == 0 ? 0 : BSROWS*KPD);
    const uint32_t* Wh = g_wh + z*KPD*DMODEL;
    const uint32_t* Wl = g_wl + z*KPD*DMODEL;
    const float* bias  = (z == 0) ? bq : (z == 1 ? bk : bv);
    uint32_t* dsth = (z == 0) ? g_qh : (z == 1 ? g_kh : g_vh);
    uint32_t* dstl = (z == 0) ? g_ql : (z == 1 ? g_kl : g_vl);

    const int m0 = blockIdx.y * 128;
    const int n0 = blockIdx.x * 64;
    const int tid  = threadIdx.x;
    const int wid  = tid >> 5;
    const int lane = tid & 31;
    const int g  = lane >> 2;
    const int tg = lane & 3;
    const int wm = (wid >> 1) * 32;
    const int wn = (wid & 1) * 32;

    const int ar = tid >> 2;        // 0..63
    const int aq = (tid & 3) * 4;   // uint4 col within 16 pairs
    const int bkp = tid >> 4;       // 0..15
    const int bq4 = (tid & 15) * 4;

    float acc[2][4][4] = {};

    for (int k0 = 0; k0 < DMODEL; k0 += 32) {
        int kp0 = k0 >> 1;
        *(uint4*)&AH[ar*20 + aq]       = *(const uint4*)&Xh[(m0+ar)*KPD + kp0 + aq];
        *(uint4*)&AH[(ar+64)*20 + aq]  = *(const uint4*)&Xh[(m0+ar+64)*KPD + kp0 + aq];
        *(uint4*)&AL[ar*20 + aq]       = *(const uint4*)&Xl[(m0+ar)*KPD + kp0 + aq];
        *(uint4*)&AL[(ar+64)*20 + aq]  = *(const uint4*)&Xl[(m0+ar+64)*KPD + kp0 + aq];
        *(uint4*)&BH[bkp*68 + bq4]     = *(const uint4*)&Wh[(kp0+bkp)*DMODEL + n0 + bq4];
        *(uint4*)&BL[bkp*68 + bq4]     = *(const uint4*)&Wl[(kp0+bkp)*DMODEL + n0 + bq4];
        __syncthreads();

        #pragma unroll
        for (int ks = 0; ks < 2; ks++) {
            int kb = ks * 8;
            uint32_t ah[2][4], al[2][4];
            #pragma unroll
            for (int mi = 0; mi < 2; mi++) {
                int r = wm + mi*16;
                ah[mi][0] = AH[(r+g)*20   + kb+tg];
                ah[mi][1] = AH[(r+g+8)*20 + kb+tg];
                ah[mi][2] = AH[(r+g)*20   + kb+tg+4];
                ah[mi][3] = AH[(r+g+8)*20 + kb+tg+4];
                al[mi][0] = AL[(r+g)*20   + kb+tg];
                al[mi][1] = AL[(r+g+8)*20 + kb+tg];
                al[mi][2] = AL[(r+g)*20   + kb+tg+4];
                al[mi][3] = AL[(r+g+8)*20 + kb+tg+4];
            }
            #pragma unroll
            for (int ni = 0; ni < 4; ni++) {
                int n = wn + ni*8 + g;
                uint32_t bh0 = BH[(kb+tg)*68 + n],   bh1 = BH[(kb+tg+4)*68 + n];
                uint32_t bl0 = BL[(kb+tg)*68 + n],   bl1 = BL[(kb+tg+4)*68 + n];
                #pragma unroll
                for (int mi = 0; mi < 2; mi++) {
                    mma_bf16(acc[mi][ni], ah[mi][0],ah[mi][1],ah[mi][2],ah[mi][3], bh0, bh1);
                    mma_bf16(acc[mi][ni], ah[mi][0],ah[mi][1],ah[mi][2],ah[mi][3], bl0, bl1);
                    mma_bf16(acc[mi][ni], al[mi][0],al[mi][1],al[mi][2],al[mi][3], bh0, bh1);
                }
            }
        }
        __syncthreads();
    }

    // epilogue: bias, split to bf16 hi/lo pairs, write packed scratch [bh][s][h/2]
    const int head = n0 >> 6;
    #pragma unroll
    for (int ni = 0; ni < 4; ni++) {
        int h = wn + ni*8 + 2*tg;          // even head-dim index
        int hp = h >> 1;
        float2 b2 = *(const float2*)&bias[n0 + h];
        #pragma unroll
        for (int mi = 0; mi < 2; mi++) {
            int r0 = m0 + wm + mi*16 + g;
            int r1 = r0 + 8;
            int b0i = r0 >> 11, s0 = r0 & (SEQ-1);
            int b1i = r1 >> 11, s1 = r1 & (SEQ-1);
            uint32_t hi, lo;
            split_pair(acc[mi][ni][0] + b2.x, acc[mi][ni][1] + b2.y, hi, lo);
            dsth[((b0i*NHEADS + head)*SEQ + s0)*HP + hp] = hi;
            dstl[((b0i*NHEADS + head)*SEQ + s0)*HP + hp] = lo;
            split_pair(acc[mi][ni][2] + b2.x, acc[mi][ni][3] + b2.y, hi, lo);
            dsth[((b1i*NHEADS + head)*SEQ + s1)*HP + hp] = hi;
            dstl[((b1i*NHEADS + head)*SEQ + s1)*HP + hp] = lo;
        }
    }
}

// ---------------------------------------------------------------------------
// Prep 3: transpose V scratch [bh][s][h/2] -> [bh][h][s/2] (pair along t)
// ---------------------------------------------------------------------------
__global__ __launch_bounds__(256) void v_transpose_kernel()
{
    int bh  = blockIdx.x;               // 0..31
    int spb = blockIdx.y * 128;         // s-pair base
    int base = bh * SEQ * HP;
    int obase = bh * HDIM * (SEQ/2);
    for (int i = threadIdx.x; i < HDIM*128; i += 256) {
        int h  = i >> 7;
        int sp = spb + (i & 127);
        int hp = h >> 1;
        uint32_t sel = (h & 1) ? 0x7632u : 0x5410u;
        uint32_t u0 = g_vh[base + (2*sp)*HP + hp];
        uint32_t u1 = g_vh[base + (2*sp+1)*HP + hp];
        g_vth[obase + h*(SEQ/2) + sp] = __byte_perm(u0, u1, sel);
        uint32_t v0 = g_vl[base + (2*sp)*HP + hp];
        uint32_t v1 = g_vl[base + (2*sp+1)*HP + hp];
        g_vtl[obase + h*(SEQ/2) + sp] = __byte_perm(v0, v1, sel);
    }
}

// ---------------------------------------------------------------------------
// Kernel: flash attention, bf16x3 tensor cores, Q + P fully register-resident.
// Block: 128 f-rows, 8 warps, warp = 16f x full 64t chunk (warp-local stats).
// ---------------------------------------------------------------------------
__global__ __launch_bounds__(256, 2) void attn_kernel(
    const int* __restrict__ mask, float* __restrict__ out)
{
    __shared__ uint32_t KH[64*36], KL[64*36];   // [t][h/2] stride 36
    __shared__ uint32_t VH[64*36], VL[64*36];   // [h][t/2] stride 36

    const int f0   = blockIdx.x * 128;
    const int head = blockIdx.y;
    const int b    = blockIdx.z;
    const int bh   = b*NHEADS + head;
    const int tid  = threadIdx.x;
    const int lane = tid & 31;
    const int g  = lane >> 2;
    const int tg = lane & 3;
    const int fb = (tid >> 5) * 16;

    const int frow0 = f0 + fb + g;
    const int frow1 = frow0 + 8;

    // --- preload Q fragments (register-resident for whole kernel) ---
    uint32_t qh[4][4], ql[4][4];
    {
        const uint32_t* qph = g_qh + bh*SEQ*HP;
        const uint32_t* qpl = g_ql + bh*SEQ*HP;
        int q0 = frow0*HP, q1 = frow1*HP;
        #pragma unroll
        for (int ks = 0; ks < 4; ks++) {
            int kb = ks*8 + tg;
            qh[ks][0] = qph[q0 + kb];   qh[ks][1] = qph[q1 + kb];
            qh[ks][2] = qph[q0 + kb+4]; qh[ks][3] = qph[q1 + kb+4];
            ql[ks][0] = qpl[q0 + kb];   ql[ks][1] = qpl[q1 + kb];
            ql[ks][2] = qpl[q0 + kb+4]; ql[ks][3] = qpl[q1 + kb+4];
        }
    }

    const uint32_t* kbh = g_kh + bh*SEQ*HP;
    const uint32_t* kbl = g_kl + bh*SEQ*HP;
    const uint32_t* vbh = g_vth + bh*HDIM*(SEQ/2);
    const uint32_t* vbl = g_vtl + bh*HDIM*(SEQ/2);

    float m0 = -1e30f, m1 = -1e30f;
    float l0s = 0.0f, l1s = 0.0f;
    float O[8][4] = {};

    const int cr  = tid >> 3;        // copy row 0..31 -> rows cr, cr+32
    const int cc4 = (tid & 7) * 4;   // uint4 col

    for (int t0 = 0; t0 < SEQ; t0 += 64) {
        __syncthreads();
        // --- copy K tile [t][h/2] and V tile [h][t/2] (straight packed copies) ---
        {
            int sp0 = t0 >> 1;
            *(uint4*)&KH[cr*36 + cc4]      = *(const uint4*)&kbh[(t0+cr)*HP + cc4];
            *(uint4*)&KH[(cr+32)*36 + cc4] = *(const uint4*)&kbh[(t0+cr+32)*HP + cc4];
            *(uint4*)&KL[cr*36 + cc4]      = *(const uint4*)&kbl[(t0+cr)*HP + cc4];
            *(uint4*)&KL[(cr+32)*36 + cc4] = *(const uint4*)&kbl[(t0+cr+32)*HP + cc4];
            *(uint4*)&VH[cr*36 + cc4]      = *(const uint4*)&vbh[cr*(SEQ/2) + sp0 + cc4];
            *(uint4*)&VH[(cr+32)*36 + cc4] = *(const uint4*)&vbh[(cr+32)*(SEQ/2) + sp0 + cc4];
            *(uint4*)&VL[cr*36 + cc4]      = *(const uint4*)&vbl[cr*(SEQ/2) + sp0 + cc4];
            *(uint4*)&VL[(cr+32)*36 + cc4] = *(const uint4*)&vbl[(cr+32)*(SEQ/2) + sp0 + cc4];
        }
        __syncthreads();

        // --- S = Q K^T ---
        float s[8][4] = {};
        #pragma unroll
        for (int ks = 0; ks < 4; ks++) {
            int kb = ks * 8;
            #pragma unroll
            for (int nt = 0; nt < 8; nt++) {
                int tr = nt*8 + g;
                uint32_t bh0 = KH[tr*36 + kb+tg], bh1 = KH[tr*36 + kb+tg+4];
                uint32_t bl0 = KL[tr*36 + kb+tg], bl1 = KL[tr*36 + kb+tg+4];
                mma_bf16(s[nt], qh[ks][0],qh[ks][1],qh[ks][2],qh[ks][3], bh0, bh1);
                mma_bf16(s[nt], qh[ks][0],qh[ks][1],qh[ks][2],qh[ks][3], bl0, bl1);
                mma_bf16(s[nt], ql[ks][0],ql[ks][1],ql[ks][2],ql[ks][3], bh0, bh1);
            }
        }

        // --- scale + mask + chunk row max ---
        float rmax0 = -1e30f, rmax1 = -1e30f;
        #pragma unroll
        for (int nt = 0; nt < 8; nt++) {
            int tc = t0 + nt*8 + 2*tg;
            int2 mk0 = *(const int2*)&mask[(b*SEQ + frow0)*SEQ + tc];
            int2 mk1 = *(const int2*)&mask[(b*SEQ + frow1)*SEQ + tc];
            s[nt][0] = s[nt][0]*0.125f + (1.0f - (float)mk0.x) * -10000.0f;
            s[nt][1] = s[nt][1]*0.125f + (1.0f - (float)mk0.y) * -10000.0f;
            s[nt][2] = s[nt][2]*0.125f + (1.0f - (float)mk1.x) * -10000.0f;
            s[nt][3] = s[nt][3]*0.125f + (1.0f - (float)mk1.y) * -10000.0f;
            rmax0 = fmaxf(rmax0, fmaxf(s[nt][0], s[nt][1]));
            rmax1 = fmaxf(rmax1, fmaxf(s[nt][2], s[nt][3]));
        }
        rmax0 = fmaxf(rmax0, __shfl_xor_sync(0xffffffffu, rmax0, 1));
        rmax0 = fmaxf(rmax0, __shfl_xor_sync(0xffffffffu, rmax0, 2));
        rmax1 = fmaxf(rmax1, __shfl_xor_sync(0xffffffffu, rmax1, 1));
        rmax1 = fmaxf(rmax1, __shfl_xor_sync(0xffffffffu, rmax1, 2));

        float mn0 = fmaxf(m0, rmax0), mn1 = fmaxf(m1, rmax1);
        float a0 = __expf(m0 - mn0),  a1 = __expf(m1 - mn1);
        m0 = mn0; m1 = mn1;

        // --- exp + pack P fragments in registers (C->A fragment reuse) ---
        uint32_t ph0[8], ph1[8], pl0[8], pl1[8];
        float ps0 = 0.0f, ps1 = 0.0f;
        #pragma unroll
        for (int nt = 0; nt < 8; nt++) {
            float p00 = __expf(s[nt][0] - mn0);
            float p01 = __expf(s[nt][1] - mn0);
            float p10 = __expf(s[nt][2] - mn1);
            float p11 = __expf(s[nt][3] - mn1);
            ps0 += p00 + p01;
            ps1 += p10 + p11;
            split_pair(p00, p01, ph0[nt], pl0[nt]);
            split_pair(p10, p11, ph1[nt], pl1[nt]);
        }
        ps0 += __shfl_xor_sync(0xffffffffu, ps0, 1);
        ps0 += __shfl_xor_sync(0xffffffffu, ps0, 2);
        ps1 += __shfl_xor_sync(0xffffffffu, ps1, 1);
        ps1 += __shfl_xor_sync(0xffffffffu, ps1, 2);
        l0s = l0s * a0 + ps0;
        l1s = l1s * a1 + ps1;

        #pragma unroll
        for (int ht = 0; ht < 8; ht++) {
            O[ht][0] *= a0; O[ht][1] *= a0;
            O[ht][2] *= a1; O[ht][3] *= a1;
        }

        // --- O += P V ---
        #pragma unroll
        for (int ks = 0; ks < 4; ks++) {
            int kb = ks * 8;
            uint32_t ah0 = ph0[2*ks],   ah1 = ph1[2*ks];
            uint32_t ah2 = ph0[2*ks+1], ah3 = ph1[2*ks+1];
            uint32_t al0 = pl0[2*ks],   al1 = pl1[2*ks];
            uint32_t al2 = pl0[2*ks+1], al3 = pl1[2*ks+1];
            #pragma unroll
            for (int ht = 0; ht < 8; ht++) {
                int hr = ht*8 + g;
                uint32_t bh0 = VH[hr*36 + kb+tg], bh1 = VH[hr*36 + kb+tg+4];
                uint32_t bl0 = VL[hr*36 + kb+tg], bl1 = VL[hr*36 + kb+tg+4];
                mma_bf16(O[ht], ah0,ah1,ah2,ah3, bh0, bh1);
                mma_bf16(O[ht], ah0,ah1,ah2,ah3, bl0, bl1);
                mma_bf16(O[ht], al0,al1,al2,al3, bh0, bh1);
            }
        }
    }

    // --- normalize + write out ---
    float inv0 = 1.0f / l0s;
    float inv1 = 1.0f / l1s;
    #pragma unroll
    for (int ht = 0; ht < 8; ht++) {
        int h = ht*8 + 2*tg;
        float2 r0 = make_float2(O[ht][0]*inv0, O[ht][1]*inv0);
        float2 r1 = make_float2(O[ht][2]*inv1, O[ht][3]*inv1);
        *(float2*)&out[(b*SEQ + frow0)*DMODEL + head*HDIM + h] = r0;
        *(float2*)&out[(b*SEQ + frow1)*DMODEL + head*HDIM + h] = r1;
    }
}

// ---------------------------------------------------------------------------
extern "C" void kernel_launch(void* const* d_in, const int* in_sizes, int n_in,
                              void* d_out, int out_size)
{
    const float* from_t = (const float*)d_in[0];
    const float* to_t   = (const float*)d_in[1];
    const int*   mask   = (const int*)  d_in[2];
    const float* Wq = (const float*)d_in[3];
    const float* bq = (const float*)d_in[4];
    const float* Wk = (const float*)d_in[5];
    const float* bk = (const float*)d_in[6];
    const float* Wv = (const float*)d_in[7];
    const float* bv = (const float*)d_in[8];
    float* out = (float*)d_out;

    pack_x_kernel<<<2*BSROWS, 256>>>(from_t, to_t);
    pack_w_kernel<<<3*KPD*DMODEL/256, 256>>>(Wq, Wk, Wv);

    dim3 pgrid(DMODEL/64, BSROWS/128, 3);
    qkv_proj_kernel<<<pgrid, 256>>>(bq, bk, bv);

    v_transpose_kernel<<<dim3(BATCH*NHEADS, 8), 256>>>();

    dim3 agrid(SEQ/128, NHEADS, BATCH);
    attn_kernel<<<agrid, 256>>>(mask, out);
}

// round 5
// speedup vs baseline: 2.5982x; 1.1292x over previous
#include <cuda_runtime.h>
#include <cuda_bf16.h>
#include <cstdint>

#define NHEADS 16
#define HDIM   64
#define DMODEL 1024
#define BATCH  2
#define SEQ    2048
#define BSROWS 4096          // BATCH*SEQ
#define HP     32            // HDIM/2  (bf16 pairs per head row)
#define KPD    512           // DMODEL/2

// --- packed bf16 hi/lo global scratch ---------------------------------------
__device__ uint32_t g_xh[2*BSROWS*KPD],  g_xl[2*BSROWS*KPD];     // from(0)+to(1), [m][k/2]
__device__ uint32_t g_wh[3*KPD*DMODEL],  g_wl[3*KPD*DMODEL];     // [z][k/2][n]
__device__ uint32_t g_qh[BATCH*NHEADS*SEQ*HP], g_ql[BATCH*NHEADS*SEQ*HP];   // [bh][s][h/2]
__device__ uint32_t g_kh[BATCH*NHEADS*SEQ*HP], g_kl[BATCH*NHEADS*SEQ*HP];   // [bh][s][h/2]
__device__ uint32_t g_vh[BATCH*NHEADS*SEQ*HP], g_vl[BATCH*NHEADS*SEQ*HP];   // [bh][s][h/2]
__device__ unsigned char g_mflag[BATCH*16*32];   // [b][f-tile(128)][t-chunk(64)] all-ones flag

// ---------------------------------------------------------------------------
__device__ __forceinline__ void split_pair(float x, float y, uint32_t& hi, uint32_t& lo)
{
    __nv_bfloat16 xh = __float2bfloat16(x);
    __nv_bfloat16 yh = __float2bfloat16(y);
    __nv_bfloat16 xl = __float2bfloat16(x - __bfloat162float(xh));
    __nv_bfloat16 yl = __float2bfloat16(y - __bfloat162float(yh));
    __nv_bfloat162 h2 = __halves2bfloat162(xh, yh);
    __nv_bfloat162 l2 = __halves2bfloat162(xl, yl);
    hi = *reinterpret_cast<uint32_t*>(&h2);
    lo = *reinterpret_cast<uint32_t*>(&l2);
}

__device__ __forceinline__ void mma_bf16(float* d,
    uint32_t a0, uint32_t a1, uint32_t a2, uint32_t a3,
    uint32_t b0, uint32_t b1)
{
    asm volatile(
        "mma.sync.aligned.m16n8k16.row.col.f32.bf16.bf16.f32 "
        "{%0,%1,%2,%3}, {%4,%5,%6,%7}, {%8,%9}, {%0,%1,%2,%3};\n"
        : "+f"(d[0]), "+f"(d[1]), "+f"(d[2]), "+f"(d[3])
        : "r"(a0), "r"(a1), "r"(a2), "r"(a3), "r"(b0), "r"(b1));
}

__device__ __forceinline__ void ldsm_x4(uint32_t& r0, uint32_t& r1,
                                        uint32_t& r2, uint32_t& r3, uint32_t addr)
{
    asm volatile("ldmatrix.sync.aligned.m8n8.x4.shared.b16 {%0,%1,%2,%3}, [%4];\n"
        : "=r"(r0), "=r"(r1), "=r"(r2), "=r"(r3) : "r"(addr));
}

__device__ __forceinline__ void ldsm_x4_trans(uint32_t& r0, uint32_t& r1,
                                              uint32_t& r2, uint32_t& r3, uint32_t addr)
{
    asm volatile("ldmatrix.sync.aligned.m8n8.x4.trans.shared.b16 {%0,%1,%2,%3}, [%4];\n"
        : "=r"(r0), "=r"(r1), "=r"(r2), "=r"(r3) : "r"(addr));
}

// ---------------------------------------------------------------------------
// Prep 1: split X (from rows 0..4095, to rows 4096..8191) into bf16 pairs
// ---------------------------------------------------------------------------
__global__ __launch_bounds__(256) void pack_x_kernel(
    const float* __restrict__ from_t, const float* __restrict__ to_t)
{
    int r = blockIdx.x;
    int c4 = threadIdx.x;
    const float* src = (r < BSROWS) ? (from_t + r*DMODEL)
                                    : (to_t + (r - BSROWS)*DMODEL);
    float4 f = *(const float4*)&src[c4*4];
    uint32_t h0,l0,h1,l1;
    split_pair(f.x, f.y, h0, l0);
    split_pair(f.z, f.w, h1, l1);
    *(uint2*)&g_xh[r*KPD + c4*2] = make_uint2(h0, h1);
    *(uint2*)&g_xl[r*KPD + c4*2] = make_uint2(l0, l1);
}

// ---------------------------------------------------------------------------
// Prep 2: pack W (3 matrices) into [k/2][n] bf16-pair layout
// ---------------------------------------------------------------------------
__global__ __launch_bounds__(256) void pack_w_kernel(
    const float* __restrict__ Wq, const float* __restrict__ Wk,
    const float* __restrict__ Wv)
{
    int gid = blockIdx.x * 256 + threadIdx.x;
    int z = gid >> 19;
    int rem = gid & ((1<<19)-1);
    int kp = rem >> 10;
    int n  = rem & 1023;
    const float* W = (z == 0) ? Wq : (z == 1 ? Wk : Wv);
    float w0 = W[(2*kp)*DMODEL + n];
    float w1 = W[(2*kp+1)*DMODEL + n];
    uint32_t hi, lo;
    split_pair(w0, w1, hi, lo);
    g_wh[gid] = hi;
    g_wl[gid] = lo;
}

// ---------------------------------------------------------------------------
// Prep 3: per-(b, 128f-tile, 64t-chunk) all-ones mask flags
// ---------------------------------------------------------------------------
__global__ __launch_bounds__(256) void mask_flags_kernel(const int* __restrict__ mask)
{
    int b  = blockIdx.z;
    int f  = blockIdx.y*128 + (threadIdx.x >> 1);
    int tc = blockIdx.x*64  + (threadIdx.x & 1)*32;
    const int4* p = (const int4*)&mask[(b*SEQ + f)*SEQ + tc];
    int ok = 1;
    #pragma unroll
    for (int i = 0; i < 8; i++) {
        int4 v = p[i];
        ok &= (v.x == 1) & (v.y == 1) & (v.z == 1) & (v.w == 1);
    }
    ok = __syncthreads_and(ok);
    if (threadIdx.x == 0)
        g_mflag[(b*16 + blockIdx.y)*32 + blockIdx.x] = (unsigned char)ok;
}

// ---------------------------------------------------------------------------
// Kernel: QKV projection GEMM on packed bf16 operands (bf16x3).
// ---------------------------------------------------------------------------
__global__ __launch_bounds__(256) void qkv_proj_kernel(
    const float* __restrict__ bq, const float* __restrict__ bk,
    const float* __restrict__ bv)
{
    __shared__ uint32_t AH[128*20], AL[128*20];   // [m][k/2] stride 20
    __shared__ uint32_t BH[16*68],  BL[16*68];    // [k/2][n] stride 68

    const int z = blockIdx.z;
    const uint32_t* Xh = g_xh + (z == 0 ? 0 : BSROWS*KPD);
    const uint32_t* Xl = g_xl + (z == 0 ? 0 : BSROWS*KPD);
    const uint32_t* Wh = g_wh + z*KPD*DMODEL;
    const uint32_t* Wl = g_wl + z*KPD*DMODEL;
    const float* bias  = (z == 0) ? bq : (z == 1 ? bk : bv);
    uint32_t* dsth = (z == 0) ? g_qh : (z == 1 ? g_kh : g_vh);
    uint32_t* dstl = (z == 0) ? g_ql : (z == 1 ? g_kl : g_vl);

    const int m0 = blockIdx.y * 128;
    const int n0 = blockIdx.x * 64;
    const int tid  = threadIdx.x;
    const int wid  = tid >> 5;
    const int lane = tid & 31;
    const int g  = lane >> 2;
    const int tg = lane & 3;
    const int wm = (wid >> 1) * 32;
    const int wn = (wid & 1) * 32;

    const int ar = tid >> 2;
    const int aq = (tid & 3) * 4;
    const int bkp = tid >> 4;
    const int bq4 = (tid & 15) * 4;

    float acc[2][4][4] = {};

    for (int k0 = 0; k0 < DMODEL; k0 += 32) {
        int kp0 = k0 >> 1;
        *(uint4*)&AH[ar*20 + aq]       = *(const uint4*)&Xh[(m0+ar)*KPD + kp0 + aq];
        *(uint4*)&AH[(ar+64)*20 + aq]  = *(const uint4*)&Xh[(m0+ar+64)*KPD + kp0 + aq];
        *(uint4*)&AL[ar*20 + aq]       = *(const uint4*)&Xl[(m0+ar)*KPD + kp0 + aq];
        *(uint4*)&AL[(ar+64)*20 + aq]  = *(const uint4*)&Xl[(m0+ar+64)*KPD + kp0 + aq];
        *(uint4*)&BH[bkp*68 + bq4]     = *(const uint4*)&Wh[(kp0+bkp)*DMODEL + n0 + bq4];
        *(uint4*)&BL[bkp*68 + bq4]     = *(const uint4*)&Wl[(kp0+bkp)*DMODEL + n0 + bq4];
        __syncthreads();

        #pragma unroll
        for (int ks = 0; ks < 2; ks++) {
            int kb = ks * 8;
            uint32_t ah[2][4], al[2][4];
            #pragma unroll
            for (int mi = 0; mi < 2; mi++) {
                int r = wm + mi*16;
                ah[mi][0] = AH[(r+g)*20   + kb+tg];
                ah[mi][1] = AH[(r+g+8)*20 + kb+tg];
                ah[mi][2] = AH[(r+g)*20   + kb+tg+4];
                ah[mi][3] = AH[(r+g+8)*20 + kb+tg+4];
                al[mi][0] = AL[(r+g)*20   + kb+tg];
                al[mi][1] = AL[(r+g+8)*20 + kb+tg];
                al[mi][2] = AL[(r+g)*20   + kb+tg+4];
                al[mi][3] = AL[(r+g+8)*20 + kb+tg+4];
            }
            #pragma unroll
            for (int ni = 0; ni < 4; ni++) {
                int n = wn + ni*8 + g;
                uint32_t bh0 = BH[(kb+tg)*68 + n],   bh1 = BH[(kb+tg+4)*68 + n];
                uint32_t bl0 = BL[(kb+tg)*68 + n],   bl1 = BL[(kb+tg+4)*68 + n];
                #pragma unroll
                for (int mi = 0; mi < 2; mi++) {
                    mma_bf16(acc[mi][ni], ah[mi][0],ah[mi][1],ah[mi][2],ah[mi][3], bh0, bh1);
                    mma_bf16(acc[mi][ni], ah[mi][0],ah[mi][1],ah[mi][2],ah[mi][3], bl0, bl1);
                    mma_bf16(acc[mi][ni], al[mi][0],al[mi][1],al[mi][2],al[mi][3], bh0, bh1);
                }
            }
        }
        __syncthreads();
    }

    const int head = n0 >> 6;
    #pragma unroll
    for (int ni = 0; ni < 4; ni++) {
        int h = wn + ni*8 + 2*tg;
        int hp = h >> 1;
        float2 b2 = *(const float2*)&bias[n0 + h];
        #pragma unroll
        for (int mi = 0; mi < 2; mi++) {
            int r0 = m0 + wm + mi*16 + g;
            int r1 = r0 + 8;
            int b0i = r0 >> 11, s0 = r0 & (SEQ-1);
            int b1i = r1 >> 11, s1 = r1 & (SEQ-1);
            uint32_t hi, lo;
            split_pair(acc[mi][ni][0] + b2.x, acc[mi][ni][1] + b2.y, hi, lo);
            dsth[((b0i*NHEADS + head)*SEQ + s0)*HP + hp] = hi;
            dstl[((b0i*NHEADS + head)*SEQ + s0)*HP + hp] = lo;
            split_pair(acc[mi][ni][2] + b2.x, acc[mi][ni][3] + b2.y, hi, lo);
            dsth[((b1i*NHEADS + head)*SEQ + s1)*HP + hp] = hi;
            dstl[((b1i*NHEADS + head)*SEQ + s1)*HP + hp] = lo;
        }
    }
}

// ---------------------------------------------------------------------------
// Kernel: flash attention, bf16x3 tensor cores.
// Q + P register-resident, K/V fragments via ldmatrix (V via .trans — no
// gmem transpose needed), per-chunk mask skip via g_mflag.
// ---------------------------------------------------------------------------
__global__ __launch_bounds__(256, 2) void attn_kernel(
    const int* __restrict__ mask, float* __restrict__ out)
{
    __shared__ uint32_t KH[64*36], KL[64*36];   // [t][h/2] stride 36
    __shared__ uint32_t VH[64*36], VL[64*36];   // [t][h/2] stride 36

    const int f0   = blockIdx.x * 128;
    const int head = blockIdx.y;
    const int b    = blockIdx.z;
    const int bh   = b*NHEADS + head;
    const int tid  = threadIdx.x;
    const int lane = tid & 31;
    const int g  = lane >> 2;
    const int tg = lane & 3;
    const int fb = (tid >> 5) * 16;

    const int frow0 = f0 + fb + g;
    const int frow1 = frow0 + 8;

    // ldmatrix per-lane offsets (u32 units, before *4 for bytes)
    // K (normal): m = lane/8: m0/m1 -> rows (l&7), cols kb / kb+4 ; m2/m3 -> rows +8
    const int koffK = ((((lane>>4)&1)*8 + (lane&7))*36 + ((lane>>3)&1)*4);
    // V (trans):  m0/m1 -> rows (l&7)/+8 at col c ; m2/m3 -> col c+4
    const int koffV = ((((lane>>3)&1)*8 + (lane&7))*36 + ((lane>>4)&1)*4);

    const uint32_t khB = (uint32_t)__cvta_generic_to_shared(KH);
    const uint32_t klB = (uint32_t)__cvta_generic_to_shared(KL);
    const uint32_t vhB = (uint32_t)__cvta_generic_to_shared(VH);
    const uint32_t vlB = (uint32_t)__cvta_generic_to_shared(VL);

    // --- preload Q fragments ---
    uint32_t qh[4][4], ql[4][4];
    {
        const uint32_t* qph = g_qh + bh*SEQ*HP;
        const uint32_t* qpl = g_ql + bh*SEQ*HP;
        int q0 = frow0*HP, q1 = frow1*HP;
        #pragma unroll
        for (int ks = 0; ks < 4; ks++) {
            int kb = ks*8 + tg;
            qh[ks][0] = qph[q0 + kb];   qh[ks][1] = qph[q1 + kb];
            qh[ks][2] = qph[q0 + kb+4]; qh[ks][3] = qph[q1 + kb+4];
            ql[ks][0] = qpl[q0 + kb];   ql[ks][1] = qpl[q1 + kb];
            ql[ks][2] = qpl[q0 + kb+4]; ql[ks][3] = qpl[q1 + kb+4];
        }
    }

    const uint32_t* kbh = g_kh + bh*SEQ*HP;
    const uint32_t* kbl = g_kl + bh*SEQ*HP;
    const uint32_t* vbh = g_vh + bh*SEQ*HP;
    const uint32_t* vbl = g_vl + bh*SEQ*HP;
    const unsigned char* mfl = &g_mflag[(b*16 + blockIdx.x)*32];

    float m0 = -1e30f, m1 = -1e30f;
    float l0s = 0.0f, l1s = 0.0f;
    float O[8][4] = {};

    const int cr  = tid >> 3;
    const int cc4 = (tid & 7) * 4;

    for (int t0 = 0; t0 < SEQ; t0 += 64) {
        __syncthreads();
        {
            *(uint4*)&KH[cr*36 + cc4]      = *(const uint4*)&kbh[(t0+cr)*HP + cc4];
            *(uint4*)&KH[(cr+32)*36 + cc4] = *(const uint4*)&kbh[(t0+cr+32)*HP + cc4];
            *(uint4*)&KL[cr*36 + cc4]      = *(const uint4*)&kbl[(t0+cr)*HP + cc4];
            *(uint4*)&KL[(cr+32)*36 + cc4] = *(const uint4*)&kbl[(t0+cr+32)*HP + cc4];
            *(uint4*)&VH[cr*36 + cc4]      = *(const uint4*)&vbh[(t0+cr)*HP + cc4];
            *(uint4*)&VH[(cr+32)*36 + cc4] = *(const uint4*)&vbh[(t0+cr+32)*HP + cc4];
            *(uint4*)&VL[cr*36 + cc4]      = *(const uint4*)&vbl[(t0+cr)*HP + cc4];
            *(uint4*)&VL[(cr+32)*36 + cc4] = *(const uint4*)&vbl[(t0+cr+32)*HP + cc4];
        }
        __syncthreads();

        // --- S = Q K^T ---
        float s[8][4] = {};
        #pragma unroll
        for (int ks = 0; ks < 4; ks++) {
            int kb = ks * 8;
            #pragma unroll
            for (int ntp = 0; ntp < 4; ntp++) {
                uint32_t off = (uint32_t)(ntp*16*36 + koffK + kb) * 4u;
                uint32_t h0,h1,h2,h3, x0,x1,x2,x3;
                ldsm_x4(h0,h1,h2,h3, khB + off);
                ldsm_x4(x0,x1,x2,x3, klB + off);
                mma_bf16(s[2*ntp],   qh[ks][0],qh[ks][1],qh[ks][2],qh[ks][3], h0, h1);
                mma_bf16(s[2*ntp],   qh[ks][0],qh[ks][1],qh[ks][2],qh[ks][3], x0, x1);
                mma_bf16(s[2*ntp],   ql[ks][0],ql[ks][1],ql[ks][2],ql[ks][3], h0, h1);
                mma_bf16(s[2*ntp+1], qh[ks][0],qh[ks][1],qh[ks][2],qh[ks][3], h2, h3);
                mma_bf16(s[2*ntp+1], qh[ks][0],qh[ks][1],qh[ks][2],qh[ks][3], x2, x3);
                mma_bf16(s[2*ntp+1], ql[ks][0],ql[ks][1],ql[ks][2],ql[ks][3], h2, h3);
            }
        }

        // --- scale + mask (skippable) + chunk row max ---
        float rmax0 = -1e30f, rmax1 = -1e30f;
        if (mfl[t0 >> 6]) {
            #pragma unroll
            for (int nt = 0; nt < 8; nt++) {
                s[nt][0] *= 0.125f; s[nt][1] *= 0.125f;
                s[nt][2] *= 0.125f; s[nt][3] *= 0.125f;
                rmax0 = fmaxf(rmax0, fmaxf(s[nt][0], s[nt][1]));
                rmax1 = fmaxf(rmax1, fmaxf(s[nt][2], s[nt][3]));
            }
        } else {
            #pragma unroll
            for (int nt = 0; nt < 8; nt++) {
                int tc = t0 + nt*8 + 2*tg;
                int2 mk0 = *(const int2*)&mask[(b*SEQ + frow0)*SEQ + tc];
                int2 mk1 = *(const int2*)&mask[(b*SEQ + frow1)*SEQ + tc];
                s[nt][0] = s[nt][0]*0.125f + (1.0f - (float)mk0.x) * -10000.0f;
                s[nt][1] = s[nt][1]*0.125f + (1.0f - (float)mk0.y) * -10000.0f;
                s[nt][2] = s[nt][2]*0.125f + (1.0f - (float)mk1.x) * -10000.0f;
                s[nt][3] = s[nt][3]*0.125f + (1.0f - (float)mk1.y) * -10000.0f;
                rmax0 = fmaxf(rmax0, fmaxf(s[nt][0], s[nt][1]));
                rmax1 = fmaxf(rmax1, fmaxf(s[nt][2], s[nt][3]));
            }
        }
        rmax0 = fmaxf(rmax0, __shfl_xor_sync(0xffffffffu, rmax0, 1));
        rmax0 = fmaxf(rmax0, __shfl_xor_sync(0xffffffffu, rmax0, 2));
        rmax1 = fmaxf(rmax1, __shfl_xor_sync(0xffffffffu, rmax1, 1));
        rmax1 = fmaxf(rmax1, __shfl_xor_sync(0xffffffffu, rmax1, 2));

        float mn0 = fmaxf(m0, rmax0), mn1 = fmaxf(m1, rmax1);
        float a0 = __expf(m0 - mn0),  a1 = __expf(m1 - mn1);
        m0 = mn0; m1 = mn1;

        // --- exp + pack P fragments in registers ---
        uint32_t ph0[8], ph1[8], pl0[8], pl1[8];
        float ps0 = 0.0f, ps1 = 0.0f;
        #pragma unroll
        for (int nt = 0; nt < 8; nt++) {
            float p00 = __expf(s[nt][0] - mn0);
            float p01 = __expf(s[nt][1] - mn0);
            float p10 = __expf(s[nt][2] - mn1);
            float p11 = __expf(s[nt][3] - mn1);
            ps0 += p00 + p01;
            ps1 += p10 + p11;
            split_pair(p00, p01, ph0[nt], pl0[nt]);
            split_pair(p10, p11, ph1[nt], pl1[nt]);
        }
        ps0 += __shfl_xor_sync(0xffffffffu, ps0, 1);
        ps0 += __shfl_xor_sync(0xffffffffu, ps0, 2);
        ps1 += __shfl_xor_sync(0xffffffffu, ps1, 1);
        ps1 += __shfl_xor_sync(0xffffffffu, ps1, 2);
        l0s = l0s * a0 + ps0;
        l1s = l1s * a1 + ps1;

        #pragma unroll
        for (int ht = 0; ht < 8; ht++) {
            O[ht][0] *= a0; O[ht][1] *= a0;
            O[ht][2] *= a1; O[ht][3] *= a1;
        }

        // --- O += P V (V fragments via trans ldmatrix on [t][h/2] tile) ---
        #pragma unroll
        for (int ks = 0; ks < 4; ks++) {
            uint32_t ah0 = ph0[2*ks],   ah1 = ph1[2*ks];
            uint32_t ah2 = ph0[2*ks+1], ah3 = ph1[2*ks+1];
            uint32_t al0 = pl0[2*ks],   al1 = pl1[2*ks];
            uint32_t al2 = pl0[2*ks+1], al3 = pl1[2*ks+1];
            #pragma unroll
            for (int htp = 0; htp < 4; htp++) {
                uint32_t off = (uint32_t)(ks*16*36 + htp*8 + koffV) * 4u;
                uint32_t h0,h1,h2,h3, x0,x1,x2,x3;
                ldsm_x4_trans(h0,h1,h2,h3, vhB + off);
                ldsm_x4_trans(x0,x1,x2,x3, vlB + off);
                mma_bf16(O[2*htp],   ah0,ah1,ah2,ah3, h0, h1);
                mma_bf16(O[2*htp],   ah0,ah1,ah2,ah3, x0, x1);
                mma_bf16(O[2*htp],   al0,al1,al2,al3, h0, h1);
                mma_bf16(O[2*htp+1], ah0,ah1,ah2,ah3, h2, h3);
                mma_bf16(O[2*htp+1], ah0,ah1,ah2,ah3, x2, x3);
                mma_bf16(O[2*htp+1], al0,al1,al2,al3, h2, h3);
            }
        }
    }

    // --- normalize + write out ---
    float inv0 = 1.0f / l0s;
    float inv1 = 1.0f / l1s;
    #pragma unroll
    for (int ht = 0; ht < 8; ht++) {
        int h = ht*8 + 2*tg;
        float2 r0 = make_float2(O[ht][0]*inv0, O[ht][1]*inv0);
        float2 r1 = make_float2(O[ht][2]*inv1, O[ht][3]*inv1);
        *(float2*)&out[(b*SEQ + frow0)*DMODEL + head*HDIM + h] = r0;
        *(float2*)&out[(b*SEQ + frow1)*DMODEL + head*HDIM + h] = r1;
    }
}

// ---------------------------------------------------------------------------
extern "C" void kernel_launch(void* const* d_in, const int* in_sizes, int n_in,
                              void* d_out, int out_size)
{
    const float* from_t = (const float*)d_in[0];
    const float* to_t   = (const float*)d_in[1];
    const int*   mask   = (const int*)  d_in[2];
    const float* Wq = (const float*)d_in[3];
    const float* bq = (const float*)d_in[4];
    const float* Wk = (const float*)d_in[5];
    const float* bk = (const float*)d_in[6];
    const float* Wv = (const float*)d_in[7];
    const float* bv = (const float*)d_in[8];
    float* out = (float*)d_out;

    pack_x_kernel<<<2*BSROWS, 256>>>(from_t, to_t);
    pack_w_kernel<<<3*KPD*DMODEL/256, 256>>>(Wq, Wk, Wv);
    mask_flags_kernel<<<dim3(32, 16, BATCH), 256>>>(mask);

    dim3 pgrid(DMODEL/64, BSROWS/128, 3);
    qkv_proj_kernel<<<pgrid, 256>>>(bq, bk, bv);

    dim3 agrid(SEQ/128, NHEADS, BATCH);
    attn_kernel<<<agrid, 256>>>(mask, out);
}

// round 6
// speedup vs baseline: 2.8913x; 1.1128x over previous
#include <cuda_runtime.h>
#include <cuda_bf16.h>
#include <cstdint>

#define NHEADS 16
#define HDIM   64
#define DMODEL 1024
#define BATCH  2
#define SEQ    2048
#define BSROWS 4096          // BATCH*SEQ
#define HP     32            // HDIM/2  (bf16 pairs per head row)
#define KPD    512           // DMODEL/2

// --- packed bf16 hi/lo global scratch ---------------------------------------
__device__ uint32_t g_xh[2*BSROWS*KPD],  g_xl[2*BSROWS*KPD];     // from(0)+to(1), [m][k/2]
__device__ uint32_t g_wh[3*DMODEL*KPD],  g_wl[3*DMODEL*KPD];     // [z][n][k/2]  (transposed!)
__device__ uint32_t g_qh[BATCH*NHEADS*SEQ*HP], g_ql[BATCH*NHEADS*SEQ*HP];   // [bh][s][h/2]
__device__ uint32_t g_kh[BATCH*NHEADS*SEQ*HP], g_kl[BATCH*NHEADS*SEQ*HP];
__device__ uint32_t g_vh[BATCH*NHEADS*SEQ*HP], g_vl[BATCH*NHEADS*SEQ*HP];
__device__ unsigned char g_mflag[BATCH*16*32];   // [b][f-tile(128)][t-chunk(64)]

// ---------------------------------------------------------------------------
__device__ __forceinline__ void split_pair(float x, float y, uint32_t& hi, uint32_t& lo)
{
    __nv_bfloat16 xh = __float2bfloat16(x);
    __nv_bfloat16 yh = __float2bfloat16(y);
    __nv_bfloat16 xl = __float2bfloat16(x - __bfloat162float(xh));
    __nv_bfloat16 yl = __float2bfloat16(y - __bfloat162float(yh));
    __nv_bfloat162 h2 = __halves2bfloat162(xh, yh);
    __nv_bfloat162 l2 = __halves2bfloat162(xl, yl);
    hi = *reinterpret_cast<uint32_t*>(&h2);
    lo = *reinterpret_cast<uint32_t*>(&l2);
}

__device__ __forceinline__ void mma_bf16(float* d,
    uint32_t a0, uint32_t a1, uint32_t a2, uint32_t a3,
    uint32_t b0, uint32_t b1)
{
    asm volatile(
        "mma.sync.aligned.m16n8k16.row.col.f32.bf16.bf16.f32 "
        "{%0,%1,%2,%3}, {%4,%5,%6,%7}, {%8,%9}, {%0,%1,%2,%3};\n"
        : "+f"(d[0]), "+f"(d[1]), "+f"(d[2]), "+f"(d[3])
        : "r"(a0), "r"(a1), "r"(a2), "r"(a3), "r"(b0), "r"(b1));
}

__device__ __forceinline__ void ldsm_x4(uint32_t& r0, uint32_t& r1,
                                        uint32_t& r2, uint32_t& r3, uint32_t addr)
{
    asm volatile("ldmatrix.sync.aligned.m8n8.x4.shared.b16 {%0,%1,%2,%3}, [%4];\n"
        : "=r"(r0), "=r"(r1), "=r"(r2), "=r"(r3) : "r"(addr));
}

__device__ __forceinline__ void ldsm_x4_trans(uint32_t& r0, uint32_t& r1,
                                              uint32_t& r2, uint32_t& r3, uint32_t addr)
{
    asm volatile("ldmatrix.sync.aligned.m8n8.x4.trans.shared.b16 {%0,%1,%2,%3}, [%4];\n"
        : "=r"(r0), "=r"(r1), "=r"(r2), "=r"(r3) : "r"(addr));
}

// ---------------------------------------------------------------------------
// Prep 1: split X (from rows 0..4095, to rows 4096..8191) into bf16 pairs
// ---------------------------------------------------------------------------
__global__ __launch_bounds__(256) void pack_x_kernel(
    const float* __restrict__ from_t, const float* __restrict__ to_t)
{
    int r = blockIdx.x;
    int c4 = threadIdx.x;
    const float* src = (r < BSROWS) ? (from_t + r*DMODEL)
                                    : (to_t + (r - BSROWS)*DMODEL);
    float4 f = *(const float4*)&src[c4*4];
    uint32_t h0,l0,h1,l1;
    split_pair(f.x, f.y, h0, l0);
    split_pair(f.z, f.w, h1, l1);
    *(uint2*)&g_xh[r*KPD + c4*2] = make_uint2(h0, h1);
    *(uint2*)&g_xl[r*KPD + c4*2] = make_uint2(l0, l1);
}

// ---------------------------------------------------------------------------
// Prep 2: pack W into transposed [z][n][k/2] bf16-pair layout (smem transpose)
// Block handles a 64k x 64n tile. Reads coalesced rows, writes coalesced
// along k-pairs.
// ---------------------------------------------------------------------------
__global__ __launch_bounds__(256) void pack_w_kernel(
    const float* __restrict__ Wq, const float* __restrict__ Wk,
    const float* __restrict__ Wv)
{
    __shared__ float T[64][65];
    const int z  = blockIdx.z;
    const int kt = blockIdx.y * 64;     // k base
    const int nt = blockIdx.x * 64;     // n base
    const float* W = (z == 0) ? Wq : (z == 1 ? Wk : Wv);

    #pragma unroll
    for (int p = 0; p < 4; p++) {
        int idx = threadIdx.x + p*256;
        int kr = idx >> 4;
        int c4 = (idx & 15) * 4;
        float4 v = *(const float4*)&W[(kt+kr)*DMODEL + nt + c4];
        T[kr][c4+0] = v.x; T[kr][c4+1] = v.y;
        T[kr][c4+2] = v.z; T[kr][c4+3] = v.w;
    }
    __syncthreads();

    const int kt2 = kt >> 1;
    #pragma unroll
    for (int p = 0; p < 8; p++) {
        int o = threadIdx.x + p*256;
        int n  = o >> 5;       // 0..63
        int kp = o & 31;       // 0..31
        uint32_t hi, lo;
        split_pair(T[2*kp][n], T[2*kp+1][n], hi, lo);
        int gidx = (z*DMODEL + nt + n)*KPD + kt2 + kp;
        g_wh[gidx] = hi;
        g_wl[gidx] = lo;
    }
}

// ---------------------------------------------------------------------------
// Prep 3: per-(b, 128f-tile, 64t-chunk) all-ones mask flags
// ---------------------------------------------------------------------------
__global__ __launch_bounds__(256) void mask_flags_kernel(const int* __restrict__ mask)
{
    int b  = blockIdx.z;
    int f  = blockIdx.y*128 + (threadIdx.x >> 1);
    int tc = blockIdx.x*64  + (threadIdx.x & 1)*32;
    const int4* p = (const int4*)&mask[(b*SEQ + f)*SEQ + tc];
    int ok = 1;
    #pragma unroll
    for (int i = 0; i < 8; i++) {
        int4 v = p[i];
        ok &= (v.x == 1) & (v.y == 1) & (v.z == 1) & (v.w == 1);
    }
    ok = __syncthreads_and(ok);
    if (threadIdx.x == 0)
        g_mflag[(b*16 + blockIdx.y)*32 + blockIdx.x] = (unsigned char)ok;
}

// ---------------------------------------------------------------------------
// Kernel: QKV projection GEMM, bf16x3, ldmatrix fragments, double-buffered.
// Block 128m x 64n, 8 warps (4m x 2n), warp 32x32, K-step 32.
// Dynamic smem: 2 stages x (AH 2560 | AL 2560 | BH 1280 | BL 1280) u32.
// ---------------------------------------------------------------------------
#define PSTG 7680            // u32 per stage
#define PA_L 2560
#define PB_H 5120
#define PB_L 6400

__global__ __launch_bounds__(256, 2) void qkv_proj_kernel(
    const float* __restrict__ bq, const float* __restrict__ bk,
    const float* __restrict__ bv)
{
    extern __shared__ uint32_t dsm[];

    const int z = blockIdx.z;
    const uint32_t* Xh = g_xh + (z == 0 ? 0 : BSROWS*KPD);
    const uint32_t* Xl = g_xl + (z == 0 ? 0 : BSROWS*KPD);
    const uint32_t* Wh = g_wh + z*DMODEL*KPD;
    const uint32_t* Wl = g_wl + z*DMODEL*KPD;
    const float* bias  = (z == 0) ? bq : (z == 1 ? bk : bv);
    uint32_t* dsth = (z == 0) ? g_qh : (z == 1 ? g_kh : g_vh);
    uint32_t* dstl = (z == 0) ? g_ql : (z == 1 ? g_kl : g_vl);

    const int m0 = blockIdx.y * 128;
    const int n0 = blockIdx.x * 64;
    const int tid  = threadIdx.x;
    const int wid  = tid >> 5;
    const int lane = tid & 31;
    const int g  = lane >> 2;
    const int tg = lane & 3;
    const int wm = (wid >> 1) * 32;
    const int wn = (wid & 1) * 32;

    // loaders
    const int ar = tid >> 2;          // A row (0..63), also +64
    const int aq = (tid & 3) * 4;     // uint4 col within 16 k-pairs
    const int br = tid >> 2;          // B n-row (0..63)
    const int bq4 = (tid & 3) * 4;

    // ldmatrix per-lane offset (u32): rows lane&15, col half (lane>>4)*4
    const int koffA = (lane & 15)*20 + (lane >> 4)*4;
    const uint32_t sBase = (uint32_t)__cvta_generic_to_shared(dsm);

    float acc[2][4][4] = {};

    // --- fill stage 0 ---
    {
        uint32_t* sb = dsm;
        *(uint4*)&sb[ar*20 + aq]             = *(const uint4*)&Xh[(m0+ar)*KPD + aq];
        *(uint4*)&sb[(ar+64)*20 + aq]        = *(const uint4*)&Xh[(m0+ar+64)*KPD + aq];
        *(uint4*)&sb[PA_L + ar*20 + aq]      = *(const uint4*)&Xl[(m0+ar)*KPD + aq];
        *(uint4*)&sb[PA_L + (ar+64)*20 + aq] = *(const uint4*)&Xl[(m0+ar+64)*KPD + aq];
        *(uint4*)&sb[PB_H + br*20 + bq4]     = *(const uint4*)&Wh[(n0+br)*KPD + bq4];
        *(uint4*)&sb[PB_L + br*20 + bq4]     = *(const uint4*)&Wl[(n0+br)*KPD + bq4];
    }
    __syncthreads();

    for (int it = 0; it < 32; it++) {
        const bool pf = (it + 1) < 32;
        uint4 pa0h, pa1h, pa0l, pa1l, pb4h, pb4l;
        if (pf) {
            int kq = (it+1)*16;
            pa0h = *(const uint4*)&Xh[(m0+ar)*KPD + kq + aq];
            pa1h = *(const uint4*)&Xh[(m0+ar+64)*KPD + kq + aq];
            pa0l = *(const uint4*)&Xl[(m0+ar)*KPD + kq + aq];
            pa1l = *(const uint4*)&Xl[(m0+ar+64)*KPD + kq + aq];
            pb4h = *(const uint4*)&Wh[(n0+br)*KPD + kq + bq4];
            pb4l = *(const uint4*)&Wl[(n0+br)*KPD + kq + bq4];
        }

        const uint32_t aB = sBase + (uint32_t)((it & 1) * PSTG) * 4u;
        #pragma unroll
        for (int ks = 0; ks < 2; ks++) {
            int kb = ks * 8;
            uint32_t ah[2][4], al[2][4], bh[2][4], bl[2][4];
            #pragma unroll
            for (int mi = 0; mi < 2; mi++) {
                uint32_t off = (uint32_t)((wm + mi*16)*20 + kb + koffA) * 4u;
                ldsm_x4(ah[mi][0], ah[mi][1], ah[mi][2], ah[mi][3], aB + off);
                ldsm_x4(al[mi][0], al[mi][1], al[mi][2], al[mi][3], aB + PA_L*4u + off);
            }
            #pragma unroll
            for (int nip = 0; nip < 2; nip++) {
                uint32_t off = (uint32_t)((wn + nip*16)*20 + kb + koffA) * 4u;
                ldsm_x4(bh[nip][0], bh[nip][1], bh[nip][2], bh[nip][3], aB + PB_H*4u + off);
                ldsm_x4(bl[nip][0], bl[nip][1], bl[nip][2], bl[nip][3], aB + PB_L*4u + off);
            }
            #pragma unroll
            for (int nip = 0; nip < 2; nip++) {
                #pragma unroll
                for (int j = 0; j < 2; j++) {
                    int ni = nip*2 + j;
                    uint32_t b0h = bh[nip][j], b1h = bh[nip][2+j];
                    uint32_t b0l = bl[nip][j], b1l = bl[nip][2+j];
                    #pragma unroll
                    for (int mi = 0; mi < 2; mi++) {
                        mma_bf16(acc[mi][ni], ah[mi][0],ah[mi][1],ah[mi][2],ah[mi][3], b0h, b1h);
                        mma_bf16(acc[mi][ni], ah[mi][0],ah[mi][1],ah[mi][2],ah[mi][3], b0l, b1l);
                        mma_bf16(acc[mi][ni], al[mi][0],al[mi][1],al[mi][2],al[mi][3], b0h, b1h);
                    }
                }
            }
        }

        if (pf) {
            uint32_t* ns = dsm + ((it+1) & 1) * PSTG;
            *(uint4*)&ns[ar*20 + aq]             = pa0h;
            *(uint4*)&ns[(ar+64)*20 + aq]        = pa1h;
            *(uint4*)&ns[PA_L + ar*20 + aq]      = pa0l;
            *(uint4*)&ns[PA_L + (ar+64)*20 + aq] = pa1l;
            *(uint4*)&ns[PB_H + br*20 + bq4]     = pb4h;
            *(uint4*)&ns[PB_L + br*20 + bq4]     = pb4l;
        }
        __syncthreads();
    }

    // --- epilogue: bias, split, write packed scratch [bh][s][h/2] ---
    const int head = n0 >> 6;
    #pragma unroll
    for (int ni = 0; ni < 4; ni++) {
        int h = wn + ni*8 + 2*tg;
        int hp = h >> 1;
        float2 b2 = *(const float2*)&bias[n0 + h];
        #pragma unroll
        for (int mi = 0; mi < 2; mi++) {
            int r0 = m0 + wm + mi*16 + g;
            int r1 = r0 + 8;
            int b0i = r0 >> 11, s0 = r0 & (SEQ-1);
            int b1i = r1 >> 11, s1 = r1 & (SEQ-1);
            uint32_t hi, lo;
            split_pair(acc[mi][ni][0] + b2.x, acc[mi][ni][1] + b2.y, hi, lo);
            dsth[((b0i*NHEADS + head)*SEQ + s0)*HP + hp] = hi;
            dstl[((b0i*NHEADS + head)*SEQ + s0)*HP + hp] = lo;
            split_pair(acc[mi][ni][2] + b2.x, acc[mi][ni][3] + b2.y, hi, lo);
            dsth[((b1i*NHEADS + head)*SEQ + s1)*HP + hp] = hi;
            dstl[((b1i*NHEADS + head)*SEQ + s1)*HP + hp] = lo;
        }
    }
}

// ---------------------------------------------------------------------------
// Kernel: flash attention, bf16x3 tensor cores (unchanged from R5).
// ---------------------------------------------------------------------------
__global__ __launch_bounds__(256, 2) void attn_kernel(
    const int* __restrict__ mask, float* __restrict__ out)
{
    __shared__ uint32_t KH[64*36], KL[64*36];   // [t][h/2] stride 36
    __shared__ uint32_t VH[64*36], VL[64*36];   // [t][h/2] stride 36

    const int f0   = blockIdx.x * 128;
    const int head = blockIdx.y;
    const int b    = blockIdx.z;
    const int bh   = b*NHEADS + head;
    const int tid  = threadIdx.x;
    const int lane = tid & 31;
    const int g  = lane >> 2;
    const int tg = lane & 3;
    const int fb = (tid >> 5) * 16;

    const int frow0 = f0 + fb + g;
    const int frow1 = frow0 + 8;

    const int koffK = ((((lane>>4)&1)*8 + (lane&7))*36 + ((lane>>3)&1)*4);
    const int koffV = ((((lane>>3)&1)*8 + (lane&7))*36 + ((lane>>4)&1)*4);

    const uint32_t khB = (uint32_t)__cvta_generic_to_shared(KH);
    const uint32_t klB = (uint32_t)__cvta_generic_to_shared(KL);
    const uint32_t vhB = (uint32_t)__cvta_generic_to_shared(VH);
    const uint32_t vlB = (uint32_t)__cvta_generic_to_shared(VL);

    uint32_t qh[4][4], ql[4][4];
    {
        const uint32_t* qph = g_qh + bh*SEQ*HP;
        const uint32_t* qpl = g_ql + bh*SEQ*HP;
        int q0 = frow0*HP, q1 = frow1*HP;
        #pragma unroll
        for (int ks = 0; ks < 4; ks++) {
            int kb = ks*8 + tg;
            qh[ks][0] = qph[q0 + kb];   qh[ks][1] = qph[q1 + kb];
            qh[ks][2] = qph[q0 + kb+4]; qh[ks][3] = qph[q1 + kb+4];
            ql[ks][0] = qpl[q0 + kb];   ql[ks][1] = qpl[q1 + kb];
            ql[ks][2] = qpl[q0 + kb+4]; ql[ks][3] = qpl[q1 + kb+4];
        }
    }

    const uint32_t* kbh = g_kh + bh*SEQ*HP;
    const uint32_t* kbl = g_kl + bh*SEQ*HP;
    const uint32_t* vbh = g_vh + bh*SEQ*HP;
    const uint32_t* vbl = g_vl + bh*SEQ*HP;
    const unsigned char* mfl = &g_mflag[(b*16 + blockIdx.x)*32];

    float m0 = -1e30f, m1 = -1e30f;
    float l0s = 0.0f, l1s = 0.0f;
    float O[8][4] = {};

    const int cr  = tid >> 3;
    const int cc4 = (tid & 7) * 4;

    for (int t0 = 0; t0 < SEQ; t0 += 64) {
        __syncthreads();
        {
            *(uint4*)&KH[cr*36 + cc4]      = *(const uint4*)&kbh[(t0+cr)*HP + cc4];
            *(uint4*)&KH[(cr+32)*36 + cc4] = *(const uint4*)&kbh[(t0+cr+32)*HP + cc4];
            *(uint4*)&KL[cr*36 + cc4]      = *(const uint4*)&kbl[(t0+cr)*HP + cc4];
            *(uint4*)&KL[(cr+32)*36 + cc4] = *(const uint4*)&kbl[(t0+cr+32)*HP + cc4];
            *(uint4*)&VH[cr*36 + cc4]      = *(const uint4*)&vbh[(t0+cr)*HP + cc4];
            *(uint4*)&VH[(cr+32)*36 + cc4] = *(const uint4*)&vbh[(t0+cr+32)*HP + cc4];
            *(uint4*)&VL[cr*36 + cc4]      = *(const uint4*)&vbl[(t0+cr)*HP + cc4];
            *(uint4*)&VL[(cr+32)*36 + cc4] = *(const uint4*)&vbl[(t0+cr+32)*HP + cc4];
        }
        __syncthreads();

        float s[8][4] = {};
        #pragma unroll
        for (int ks = 0; ks < 4; ks++) {
            int kb = ks * 8;
            #pragma unroll
            for (int ntp = 0; ntp < 4; ntp++) {
                uint32_t off = (uint32_t)(ntp*16*36 + koffK + kb) * 4u;
                uint32_t h0,h1,h2,h3, x0,x1,x2,x3;
                ldsm_x4(h0,h1,h2,h3, khB + off);
                ldsm_x4(x0,x1,x2,x3, klB + off);
                mma_bf16(s[2*ntp],   qh[ks][0],qh[ks][1],qh[ks][2],qh[ks][3], h0, h1);
                mma_bf16(s[2*ntp],   qh[ks][0],qh[ks][1],qh[ks][2],qh[ks][3], x0, x1);
                mma_bf16(s[2*ntp],   ql[ks][0],ql[ks][1],ql[ks][2],ql[ks][3], h0, h1);
                mma_bf16(s[2*ntp+1], qh[ks][0],qh[ks][1],qh[ks][2],qh[ks][3], h2, h3);
                mma_bf16(s[2*ntp+1], qh[ks][0],qh[ks][1],qh[ks][2],qh[ks][3], x2, x3);
                mma_bf16(s[2*ntp+1], ql[ks][0],ql[ks][1],ql[ks][2],ql[ks][3], h2, h3);
            }
        }

        float rmax0 = -1e30f, rmax1 = -1e30f;
        if (mfl[t0 >> 6]) {
            #pragma unroll
            for (int nt = 0; nt < 8; nt++) {
                s[nt][0] *= 0.125f; s[nt][1] *= 0.125f;
                s[nt][2] *= 0.125f; s[nt][3] *= 0.125f;
                rmax0 = fmaxf(rmax0, fmaxf(s[nt][0], s[nt][1]));
                rmax1 = fmaxf(rmax1, fmaxf(s[nt][2], s[nt][3]));
            }
        } else {
            #pragma unroll
            for (int nt = 0; nt < 8; nt++) {
                int tc = t0 + nt*8 + 2*tg;
                int2 mk0 = *(const int2*)&mask[(b*SEQ + frow0)*SEQ + tc];
                int2 mk1 = *(const int2*)&mask[(b*SEQ + frow1)*SEQ + tc];
                s[nt][0] = s[nt][0]*0.125f + (1.0f - (float)mk0.x) * -10000.0f;
                s[nt][1] = s[nt][1]*0.125f + (1.0f - (float)mk0.y) * -10000.0f;
                s[nt][2] = s[nt][2]*0.125f + (1.0f - (float)mk1.x) * -10000.0f;
                s[nt][3] = s[nt][3]*0.125f + (1.0f - (float)mk1.y) * -10000.0f;
                rmax0 = fmaxf(rmax0, fmaxf(s[nt][0], s[nt][1]));
                rmax1 = fmaxf(rmax1, fmaxf(s[nt][2], s[nt][3]));
            }
        }
        rmax0 = fmaxf(rmax0, __shfl_xor_sync(0xffffffffu, rmax0, 1));
        rmax0 = fmaxf(rmax0, __shfl_xor_sync(0xffffffffu, rmax0, 2));
        rmax1 = fmaxf(rmax1, __shfl_xor_sync(0xffffffffu, rmax1, 1));
        rmax1 = fmaxf(rmax1, __shfl_xor_sync(0xffffffffu, rmax1, 2));

        float mn0 = fmaxf(m0, rmax0), mn1 = fmaxf(m1, rmax1);
        float a0 = __expf(m0 - mn0),  a1 = __expf(m1 - mn1);
        m0 = mn0; m1 = mn1;

        uint32_t ph0[8], ph1[8], pl0[8], pl1[8];
        float ps0 = 0.0f, ps1 = 0.0f;
        #pragma unroll
        for (int nt = 0; nt < 8; nt++) {
            float p00 = __expf(s[nt][0] - mn0);
            float p01 = __expf(s[nt][1] - mn0);
            float p10 = __expf(s[nt][2] - mn1);
            float p11 = __expf(s[nt][3] - mn1);
            ps0 += p00 + p01;
            ps1 += p10 + p11;
            split_pair(p00, p01, ph0[nt], pl0[nt]);
            split_pair(p10, p11, ph1[nt], pl1[nt]);
        }
        ps0 += __shfl_xor_sync(0xffffffffu, ps0, 1);
        ps0 += __shfl_xor_sync(0xffffffffu, ps0, 2);
        ps1 += __shfl_xor_sync(0xffffffffu, ps1, 1);
        ps1 += __shfl_xor_sync(0xffffffffu, ps1, 2);
        l0s = l0s * a0 + ps0;
        l1s = l1s * a1 + ps1;

        #pragma unroll
        for (int ht = 0; ht < 8; ht++) {
            O[ht][0] *= a0; O[ht][1] *= a0;
            O[ht][2] *= a1; O[ht][3] *= a1;
        }

        #pragma unroll
        for (int ks = 0; ks < 4; ks++) {
            uint32_t ah0 = ph0[2*ks],   ah1 = ph1[2*ks];
            uint32_t ah2 = ph0[2*ks+1], ah3 = ph1[2*ks+1];
            uint32_t al0 = pl0[2*ks],   al1 = pl1[2*ks];
            uint32_t al2 = pl0[2*ks+1], al3 = pl1[2*ks+1];
            #pragma unroll
            for (int htp = 0; htp < 4; htp++) {
                uint32_t off = (uint32_t)(ks*16*36 + htp*8 + koffV) * 4u;
                uint32_t h0,h1,h2,h3, x0,x1,x2,x3;
                ldsm_x4_trans(h0,h1,h2,h3, vhB + off);
                ldsm_x4_trans(x0,x1,x2,x3, vlB + off);
                mma_bf16(O[2*htp],   ah0,ah1,ah2,ah3, h0, h1);
                mma_bf16(O[2*htp],   ah0,ah1,ah2,ah3, x0, x1);
                mma_bf16(O[2*htp],   al0,al1,al2,al3, h0, h1);
                mma_bf16(O[2*htp+1], ah0,ah1,ah2,ah3, h2, h3);
                mma_bf16(O[2*htp+1], ah0,ah1,ah2,ah3, x2, x3);
                mma_bf16(O[2*htp+1], al0,al1,al2,al3, h2, h3);
            }
        }
    }

    float inv0 = 1.0f / l0s;
    float inv1 = 1.0f / l1s;
    #pragma unroll
    for (int ht = 0; ht < 8; ht++) {
        int h = ht*8 + 2*tg;
        float2 r0 = make_float2(O[ht][0]*inv0, O[ht][1]*inv0);
        float2 r1 = make_float2(O[ht][2]*inv1, O[ht][3]*inv1);
        *(float2*)&out[(b*SEQ + frow0)*DMODEL + head*HDIM + h] = r0;
        *(float2*)&out[(b*SEQ + frow1)*DMODEL + head*HDIM + h] = r1;
    }
}

// ---------------------------------------------------------------------------
extern "C" void kernel_launch(void* const* d_in, const int* in_sizes, int n_in,
                              void* d_out, int out_size)
{
    const float* from_t = (const float*)d_in[0];
    const float* to_t   = (const float*)d_in[1];
    const int*   mask   = (const int*)  d_in[2];
    const float* Wq = (const float*)d_in[3];
    const float* bq = (const float*)d_in[4];
    const float* Wk = (const float*)d_in[5];
    const float* bk = (const float*)d_in[6];
    const float* Wv = (const float*)d_in[7];
    const float* bv = (const float*)d_in[8];
    float* out = (float*)d_out;

    pack_x_kernel<<<2*BSROWS, 256>>>(from_t, to_t);
    pack_w_kernel<<<dim3(16, 16, 3), 256>>>(Wq, Wk, Wv);
    mask_flags_kernel<<<dim3(32, 16, BATCH), 256>>>(mask);

    const int proj_smem = 2 * PSTG * 4;   // 61440 B
    cudaFuncSetAttribute(qkv_proj_kernel,
                         cudaFuncAttributeMaxDynamicSharedMemorySize, proj_smem);
    dim3 pgrid(DMODEL/64, BSROWS/128, 3);
    qkv_proj_kernel<<<pgrid, 256, proj_smem>>>(bq, bk, bv);

    dim3 agrid(SEQ/128, NHEADS, BATCH);
    attn_kernel<<<agrid, 256>>>(mask, out);
}

// round 8
// speedup vs baseline: 2.9035x; 1.0042x over previous
#include <cuda_runtime.h>
#include <cuda_bf16.h>
#include <cstdint>

#define NHEADS 16
#define HDIM   64
#define DMODEL 1024
#define BATCH  2
#define SEQ    2048
#define BSROWS 4096          // BATCH*SEQ
#define HP     32            // HDIM/2  (bf16 pairs per head row)
#define KPD    512           // DMODEL/2

// --- packed bf16 hi/lo global scratch ---------------------------------------
__device__ uint32_t g_xh[2*BSROWS*KPD],  g_xl[2*BSROWS*KPD];     // from(0)+to(1), [m][k/2]
__device__ uint32_t g_wh[3*DMODEL*KPD],  g_wl[3*DMODEL*KPD];     // [z][n][k/2]
__device__ uint32_t g_qh[BATCH*NHEADS*SEQ*HP], g_ql[BATCH*NHEADS*SEQ*HP];   // [bh][s][h/2]
__device__ uint32_t g_kh[BATCH*NHEADS*SEQ*HP], g_kl[BATCH*NHEADS*SEQ*HP];
__device__ uint32_t g_vh[BATCH*NHEADS*SEQ*HP], g_vl[BATCH*NHEADS*SEQ*HP];
__device__ unsigned char g_mflag[BATCH*16*32];   // [b][f-tile(128)][t-chunk(64)]

// ---------------------------------------------------------------------------
__device__ __forceinline__ void split_pair(float x, float y, uint32_t& hi, uint32_t& lo)
{
    __nv_bfloat16 xh = __float2bfloat16(x);
    __nv_bfloat16 yh = __float2bfloat16(y);
    __nv_bfloat16 xl = __float2bfloat16(x - __bfloat162float(xh));
    __nv_bfloat16 yl = __float2bfloat16(y - __bfloat162float(yh));
    __nv_bfloat162 h2 = __halves2bfloat162(xh, yh);
    __nv_bfloat162 l2 = __halves2bfloat162(xl, yl);
    hi = *reinterpret_cast<uint32_t*>(&h2);
    lo = *reinterpret_cast<uint32_t*>(&l2);
}

__device__ __forceinline__ void mma_bf16(float* d,
    uint32_t a0, uint32_t a1, uint32_t a2, uint32_t a3,
    uint32_t b0, uint32_t b1)
{
    asm volatile(
        "mma.sync.aligned.m16n8k16.row.col.f32.bf16.bf16.f32 "
        "{%0,%1,%2,%3}, {%4,%5,%6,%7}, {%8,%9}, {%0,%1,%2,%3};\n"
        : "+f"(d[0]), "+f"(d[1]), "+f"(d[2]), "+f"(d[3])
        : "r"(a0), "r"(a1), "r"(a2), "r"(a3), "r"(b0), "r"(b1));
}

__device__ __forceinline__ void ldsm_x4(uint32_t& r0, uint32_t& r1,
                                        uint32_t& r2, uint32_t& r3, uint32_t addr)
{
    asm volatile("ldmatrix.sync.aligned.m8n8.x4.shared.b16 {%0,%1,%2,%3}, [%4];\n"
        : "=r"(r0), "=r"(r1), "=r"(r2), "=r"(r3) : "r"(addr));
}

__device__ __forceinline__ void ldsm_x4_trans(uint32_t& r0, uint32_t& r1,
                                              uint32_t& r2, uint32_t& r3, uint32_t addr)
{
    asm volatile("ldmatrix.sync.aligned.m8n8.x4.trans.shared.b16 {%0,%1,%2,%3}, [%4];\n"
        : "=r"(r0), "=r"(r1), "=r"(r2), "=r"(r3) : "r"(addr));
}

// ---- cp.async helpers ------------------------------------------------------
__device__ __forceinline__ void cp16(uint32_t dst_smem, const void* src)
{
    asm volatile("cp.async.cg.shared.global [%0], [%1], 16;"
                 :: "r"(dst_smem), "l"(src));
}
__device__ __forceinline__ void cp_commit()
{
    asm volatile("cp.async.commit_group;" ::: "memory");
}
__device__ __forceinline__ void cp_wait1()
{
    asm volatile("cp.async.wait_group 1;" ::: "memory");
}

// ---------------------------------------------------------------------------
// Prep 1: split X into bf16 pairs
// ---------------------------------------------------------------------------
__global__ __launch_bounds__(256) void pack_x_kernel(
    const float* __restrict__ from_t, const float* __restrict__ to_t)
{
    int r = blockIdx.x;
    int c4 = threadIdx.x;
    const float* src = (r < BSROWS) ? (from_t + r*DMODEL)
                                    : (to_t + (r - BSROWS)*DMODEL);
    float4 f = *(const float4*)&src[c4*4];
    uint32_t h0,l0,h1,l1;
    split_pair(f.x, f.y, h0, l0);
    split_pair(f.z, f.w, h1, l1);
    *(uint2*)&g_xh[r*KPD + c4*2] = make_uint2(h0, h1);
    *(uint2*)&g_xl[r*KPD + c4*2] = make_uint2(l0, l1);
}

// ---------------------------------------------------------------------------
// Prep 2: pack W into transposed [z][n][k/2] bf16-pair layout
// ---------------------------------------------------------------------------
__global__ __launch_bounds__(256) void pack_w_kernel(
    const float* __restrict__ Wq, const float* __restrict__ Wk,
    const float* __restrict__ Wv)
{
    __shared__ float T[64][65];
    const int z  = blockIdx.z;
    const int kt = blockIdx.y * 64;
    const int nt = blockIdx.x * 64;
    const float* W = (z == 0) ? Wq : (z == 1 ? Wk : Wv);

    #pragma unroll
    for (int p = 0; p < 4; p++) {
        int idx = threadIdx.x + p*256;
        int kr = idx >> 4;
        int c4 = (idx & 15) * 4;
        float4 v = *(const float4*)&W[(kt+kr)*DMODEL + nt + c4];
        T[kr][c4+0] = v.x; T[kr][c4+1] = v.y;
        T[kr][c4+2] = v.z; T[kr][c4+3] = v.w;
    }
    __syncthreads();

    const int kt2 = kt >> 1;
    #pragma unroll
    for (int p = 0; p < 8; p++) {
        int o = threadIdx.x + p*256;
        int n  = o >> 5;
        int kp = o & 31;
        uint32_t hi, lo;
        split_pair(T[2*kp][n], T[2*kp+1][n], hi, lo);
        int gidx = (z*DMODEL + nt + n)*KPD + kt2 + kp;
        g_wh[gidx] = hi;
        g_wl[gidx] = lo;
    }
}

// ---------------------------------------------------------------------------
// Prep 3: per-(b, 128f-tile, 64t-chunk) all-ones mask flags
// ---------------------------------------------------------------------------
__global__ __launch_bounds__(256) void mask_flags_kernel(const int* __restrict__ mask)
{
    int b  = blockIdx.z;
    int f  = blockIdx.y*128 + (threadIdx.x >> 1);
    int tc = blockIdx.x*64  + (threadIdx.x & 1)*32;
    const int4* p = (const int4*)&mask[(b*SEQ + f)*SEQ + tc];
    int ok = 1;
    #pragma unroll
    for (int i = 0; i < 8; i++) {
        int4 v = p[i];
        ok &= (v.x == 1) & (v.y == 1) & (v.z == 1) & (v.w == 1);
    }
    ok = __syncthreads_and(ok);
    if (threadIdx.x == 0)
        g_mflag[(b*16 + blockIdx.y)*32 + blockIdx.x] = (unsigned char)ok;
}

// ---------------------------------------------------------------------------
// Kernel: QKV projection GEMM, bf16x3, ldmatrix fragments, cp.async pipeline.
// Block 128m x 64n, 8 warps (4m x 2n), warp 32x32, K-step 32.
// ---------------------------------------------------------------------------
#define PSTG 7680            // u32 per stage
#define PA_L 2560
#define PB_H 5120
#define PB_L 6400

__global__ __launch_bounds__(256, 2) void qkv_proj_kernel(
    const float* __restrict__ bq, const float* __restrict__ bk,
    const float* __restrict__ bv)
{
    extern __shared__ uint32_t dsm[];

    const int z = blockIdx.z;
    const uint32_t* Xh = g_xh + (z == 0 ? 0 : BSROWS*KPD);
    const uint32_t* Xl = g_xl + (z == 0 ? 0 : BSROWS*KPD);
    const uint32_t* Wh = g_wh + z*DMODEL*KPD;
    const uint32_t* Wl = g_wl + z*DMODEL*KPD;
    const float* bias  = (z == 0) ? bq : (z == 1 ? bk : bv);
    uint32_t* dsth = (z == 0) ? g_qh : (z == 1 ? g_kh : g_vh);
    uint32_t* dstl = (z == 0) ? g_ql : (z == 1 ? g_kl : g_vl);

    const int m0 = blockIdx.y * 128;
    const int n0 = blockIdx.x * 64;
    const int tid  = threadIdx.x;
    const int wid  = tid >> 5;
    const int lane = tid & 31;
    const int g  = lane >> 2;
    const int tg = lane & 3;
    const int wm = (wid >> 1) * 32;
    const int wn = (wid & 1) * 32;

    // loaders
    const int ar = tid >> 2;          // A/B row (0..63); A also +64
    const int aq = (tid & 3) * 4;     // uint4 col within 16 k-pairs

    const int koffA = (lane & 15)*20 + (lane >> 4)*4;
    const uint32_t sBase = (uint32_t)__cvta_generic_to_shared(dsm);

    auto prefetch = [&](int stage, int kq) {
        uint32_t sb = sBase + (uint32_t)(stage * PSTG) * 4u;
        cp16(sb + (ar*20 + aq)*4u,             &Xh[(m0+ar)*KPD + kq + aq]);
        cp16(sb + ((ar+64)*20 + aq)*4u,        &Xh[(m0+ar+64)*KPD + kq + aq]);
        cp16(sb + (PA_L + ar*20 + aq)*4u,      &Xl[(m0+ar)*KPD + kq + aq]);
        cp16(sb + (PA_L + (ar+64)*20 + aq)*4u, &Xl[(m0+ar+64)*KPD + kq + aq]);
        cp16(sb + (PB_H + ar*20 + aq)*4u,      &Wh[(n0+ar)*KPD + kq + aq]);
        cp16(sb + (PB_L + ar*20 + aq)*4u,      &Wl[(n0+ar)*KPD + kq + aq]);
    };

    float acc[2][4][4] = {};

    prefetch(0, 0);
    cp_commit();

    for (int it = 0; it < 32; it++) {
        if (it + 1 < 32) prefetch((it + 1) & 1, (it + 1) * 16);
        cp_commit();
        cp_wait1();
        __syncthreads();

        const uint32_t aB = sBase + (uint32_t)((it & 1) * PSTG) * 4u;
        #pragma unroll
        for (int ks = 0; ks < 2; ks++) {
            int kb = ks * 8;
            uint32_t ah[2][4], al[2][4], bh[2][4], bl[2][4];
            #pragma unroll
            for (int mi = 0; mi < 2; mi++) {
                uint32_t off = (uint32_t)((wm + mi*16)*20 + kb + koffA) * 4u;
                ldsm_x4(ah[mi][0], ah[mi][1], ah[mi][2], ah[mi][3], aB + off);
                ldsm_x4(al[mi][0], al[mi][1], al[mi][2], al[mi][3], aB + PA_L*4u + off);
            }
            #pragma unroll
            for (int nip = 0; nip < 2; nip++) {
                uint32_t off = (uint32_t)((wn + nip*16)*20 + kb + koffA) * 4u;
                ldsm_x4(bh[nip][0], bh[nip][1], bh[nip][2], bh[nip][3], aB + PB_H*4u + off);
                ldsm_x4(bl[nip][0], bl[nip][1], bl[nip][2], bl[nip][3], aB + PB_L*4u + off);
            }
            #pragma unroll
            for (int nip = 0; nip < 2; nip++) {
                #pragma unroll
                for (int j = 0; j < 2; j++) {
                    int ni = nip*2 + j;
                    uint32_t b0h = bh[nip][j], b1h = bh[nip][2+j];
                    uint32_t b0l = bl[nip][j], b1l = bl[nip][2+j];
                    #pragma unroll
                    for (int mi = 0; mi < 2; mi++) {
                        mma_bf16(acc[mi][ni], ah[mi][0],ah[mi][1],ah[mi][2],ah[mi][3], b0h, b1h);
                        mma_bf16(acc[mi][ni], ah[mi][0],ah[mi][1],ah[mi][2],ah[mi][3], b0l, b1l);
                        mma_bf16(acc[mi][ni], al[mi][0],al[mi][1],al[mi][2],al[mi][3], b0h, b1h);
                    }
                }
            }
        }
        __syncthreads();
    }

    // --- epilogue: bias, split, write packed scratch [bh][s][h/2] ---
    const int head = n0 >> 6;
    #pragma unroll
    for (int ni = 0; ni < 4; ni++) {
        int h = wn + ni*8 + 2*tg;
        int hp = h >> 1;
        float2 b2 = *(const float2*)&bias[n0 + h];
        #pragma unroll
        for (int mi = 0; mi < 2; mi++) {
            int r0 = m0 + wm + mi*16 + g;
            int r1 = r0 + 8;
            int b0i = r0 >> 11, s0 = r0 & (SEQ-1);
            int b1i = r1 >> 11, s1 = r1 & (SEQ-1);
            uint32_t hi, lo;
            split_pair(acc[mi][ni][0] + b2.x, acc[mi][ni][1] + b2.y, hi, lo);
            dsth[((b0i*NHEADS + head)*SEQ + s0)*HP + hp] = hi;
            dstl[((b0i*NHEADS + head)*SEQ + s0)*HP + hp] = lo;
            split_pair(acc[mi][ni][2] + b2.x, acc[mi][ni][3] + b2.y, hi, lo);
            dsth[((b1i*NHEADS + head)*SEQ + s1)*HP + hp] = hi;
            dstl[((b1i*NHEADS + head)*SEQ + s1)*HP + hp] = lo;
        }
    }
}

// ---------------------------------------------------------------------------
// Kernel: flash attention, bf16x3 tensor cores, cp.async K/V pipeline.
// Dynamic smem: 2 stages x (KH|KL|VH|VL, each 64x36 u32) = 73728 B.
// ---------------------------------------------------------------------------
#define ASTG 9216            // u32 per stage
#define A_KL 2304
#define A_VH 4608
#define A_VL 6912

__global__ __launch_bounds__(256, 2) void attn_kernel(
    const int* __restrict__ mask, float* __restrict__ out)
{
    extern __shared__ uint32_t asm_dsm[];

    const int f0   = blockIdx.x * 128;
    const int head = blockIdx.y;
    const int b    = blockIdx.z;
    const int bh   = b*NHEADS + head;
    const int tid  = threadIdx.x;
    const int lane = tid & 31;
    const int g  = lane >> 2;
    const int tg = lane & 3;
    const int fb = (tid >> 5) * 16;

    const int frow0 = f0 + fb + g;
    const int frow1 = frow0 + 8;

    const int koffK = ((((lane>>4)&1)*8 + (lane&7))*36 + ((lane>>3)&1)*4);
    const int koffV = ((((lane>>3)&1)*8 + (lane&7))*36 + ((lane>>4)&1)*4);

    const uint32_t sBase = (uint32_t)__cvta_generic_to_shared(asm_dsm);

    uint32_t qh[4][4], ql[4][4];
    {
        const uint32_t* qph = g_qh + bh*SEQ*HP;
        const uint32_t* qpl = g_ql + bh*SEQ*HP;
        int q0 = frow0*HP, q1 = frow1*HP;
        #pragma unroll
        for (int ks = 0; ks < 4; ks++) {
            int kb = ks*8 + tg;
            qh[ks][0] = qph[q0 + kb];   qh[ks][1] = qph[q1 + kb];
            qh[ks][2] = qph[q0 + kb+4]; qh[ks][3] = qph[q1 + kb+4];
            ql[ks][0] = qpl[q0 + kb];   ql[ks][1] = qpl[q1 + kb];
            ql[ks][2] = qpl[q0 + kb+4]; ql[ks][3] = qpl[q1 + kb+4];
        }
    }

    const uint32_t* kbh = g_kh + bh*SEQ*HP;
    const uint32_t* kbl = g_kl + bh*SEQ*HP;
    const uint32_t* vbh = g_vh + bh*SEQ*HP;
    const uint32_t* vbl = g_vl + bh*SEQ*HP;
    const unsigned char* mfl = &g_mflag[(b*16 + blockIdx.x)*32];

    float m0 = -1e30f, m1 = -1e30f;
    float l0s = 0.0f, l1s = 0.0f;
    float O[8][4] = {};

    const int cr  = tid >> 3;        // 0..31 -> rows cr, cr+32
    const int cc4 = (tid & 7) * 4;

    auto prefetch = [&](int stage, int t0) {
        uint32_t sb = sBase + (uint32_t)(stage * ASTG) * 4u;
        cp16(sb + (cr*36 + cc4)*4u,               &kbh[(t0+cr)*HP + cc4]);
        cp16(sb + ((cr+32)*36 + cc4)*4u,          &kbh[(t0+cr+32)*HP + cc4]);
        cp16(sb + (A_KL + cr*36 + cc4)*4u,        &kbl[(t0+cr)*HP + cc4]);
        cp16(sb + (A_KL + (cr+32)*36 + cc4)*4u,   &kbl[(t0+cr+32)*HP + cc4]);
        cp16(sb + (A_VH + cr*36 + cc4)*4u,        &vbh[(t0+cr)*HP + cc4]);
        cp16(sb + (A_VH + (cr+32)*36 + cc4)*4u,   &vbh[(t0+cr+32)*HP + cc4]);
        cp16(sb + (A_VL + cr*36 + cc4)*4u,        &vbl[(t0+cr)*HP + cc4]);
        cp16(sb + (A_VL + (cr+32)*36 + cc4)*4u,   &vbl[(t0+cr+32)*HP + cc4]);
    };

    prefetch(0, 0);
    cp_commit();

    for (int it = 0; it < SEQ/64; it++) {
        const int t0 = it * 64;
        if (it + 1 < SEQ/64) prefetch((it + 1) & 1, t0 + 64);
        cp_commit();
        cp_wait1();
        __syncthreads();

        const uint32_t sb = sBase + (uint32_t)((it & 1) * ASTG) * 4u;
        const uint32_t khB = sb;
        const uint32_t klB = sb + A_KL*4u;
        const uint32_t vhB = sb + A_VH*4u;
        const uint32_t vlB = sb + A_VL*4u;

        float s[8][4] = {};
        #pragma unroll
        for (int ks = 0; ks < 4; ks++) {
            int kb = ks * 8;
            #pragma unroll
            for (int ntp = 0; ntp < 4; ntp++) {
                uint32_t off = (uint32_t)(ntp*16*36 + koffK + kb) * 4u;
                uint32_t h0,h1,h2,h3, x0,x1,x2,x3;
                ldsm_x4(h0,h1,h2,h3, khB + off);
                ldsm_x4(x0,x1,x2,x3, klB + off);
                mma_bf16(s[2*ntp],   qh[ks][0],qh[ks][1],qh[ks][2],qh[ks][3], h0, h1);
                mma_bf16(s[2*ntp],   qh[ks][0],qh[ks][1],qh[ks][2],qh[ks][3], x0, x1);
                mma_bf16(s[2*ntp],   ql[ks][0],ql[ks][1],ql[ks][2],ql[ks][3], h0, h1);
                mma_bf16(s[2*ntp+1], qh[ks][0],qh[ks][1],qh[ks][2],qh[ks][3], h2, h3);
                mma_bf16(s[2*ntp+1], qh[ks][0],qh[ks][1],qh[ks][2],qh[ks][3], x2, x3);
                mma_bf16(s[2*ntp+1], ql[ks][0],ql[ks][1],ql[ks][2],ql[ks][3], h2, h3);
            }
        }

        float rmax0 = -1e30f, rmax1 = -1e30f;
        if (mfl[it]) {
            #pragma unroll
            for (int nt = 0; nt < 8; nt++) {
                s[nt][0] *= 0.125f; s[nt][1] *= 0.125f;
                s[nt][2] *= 0.125f; s[nt][3] *= 0.125f;
                rmax0 = fmaxf(rmax0, fmaxf(s[nt][0], s[nt][1]));
                rmax1 = fmaxf(rmax1, fmaxf(s[nt][2], s[nt][3]));
            }
        } else {
            #pragma unroll
            for (int nt = 0; nt < 8; nt++) {
                int tc = t0 + nt*8 + 2*tg;
                int2 mk0 = *(const int2*)&mask[(b*SEQ + frow0)*SEQ + tc];
                int2 mk1 = *(const int2*)&mask[(b*SEQ + frow1)*SEQ + tc];
                s[nt][0] = s[nt][0]*0.125f + (1.0f - (float)mk0.x) * -10000.0f;
                s[nt][1] = s[nt][1]*0.125f + (1.0f - (float)mk0.y) * -10000.0f;
                s[nt][2] = s[nt][2]*0.125f + (1.0f - (float)mk1.x) * -10000.0f;
                s[nt][3] = s[nt][3]*0.125f + (1.0f - (float)mk1.y) * -10000.0f;
                rmax0 = fmaxf(rmax0, fmaxf(s[nt][0], s[nt][1]));
                rmax1 = fmaxf(rmax1, fmaxf(s[nt][2], s[nt][3]));
            }
        }
        rmax0 = fmaxf(rmax0, __shfl_xor_sync(0xffffffffu, rmax0, 1));
        rmax0 = fmaxf(rmax0, __shfl_xor_sync(0xffffffffu, rmax0, 2));
        rmax1 = fmaxf(rmax1, __shfl_xor_sync(0xffffffffu, rmax1, 1));
        rmax1 = fmaxf(rmax1, __shfl_xor_sync(0xffffffffu, rmax1, 2));

        float mn0 = fmaxf(m0, rmax0), mn1 = fmaxf(m1, rmax1);
        float a0 = __expf(m0 - mn0),  a1 = __expf(m1 - mn1);
        m0 = mn0; m1 = mn1;

        uint32_t ph0[8], ph1[8], pl0[8], pl1[8];
        float ps0 = 0.0f, ps1 = 0.0f;
        #pragma unroll
        for (int nt = 0; nt < 8; nt++) {
            float p00 = __expf(s[nt][0] - mn0);
            float p01 = __expf(s[nt][1] - mn0);
            float p10 = __expf(s[nt][2] - mn1);
            float p11 = __expf(s[nt][3] - mn1);
            ps0 += p00 + p01;
            ps1 += p10 + p11;
            split_pair(p00, p01, ph0[nt], pl0[nt]);
            split_pair(p10, p11, ph1[nt], pl1[nt]);
        }
        ps0 += __shfl_xor_sync(0xffffffffu, ps0, 1);
        ps0 += __shfl_xor_sync(0xffffffffu, ps0, 2);
        ps1 += __shfl_xor_sync(0xffffffffu, ps1, 1);
        ps1 += __shfl_xor_sync(0xffffffffu, ps1, 2);
        l0s = l0s * a0 + ps0;
        l1s = l1s * a1 + ps1;

        #pragma unroll
        for (int ht = 0; ht < 8; ht++) {
            O[ht][0] *= a0; O[ht][1] *= a0;
            O[ht][2] *= a1; O[ht][3] *= a1;
        }

        #pragma unroll
        for (int ks = 0; ks < 4; ks++) {
            uint32_t ah0 = ph0[2*ks],   ah1 = ph1[2*ks];
            uint32_t ah2 = ph0[2*ks+1], ah3 = ph1[2*ks+1];
            uint32_t al0 = pl0[2*ks],   al1 = pl1[2*ks];
            uint32_t al2 = pl0[2*ks+1], al3 = pl1[2*ks+1];
            #pragma unroll
            for (int htp = 0; htp < 4; htp++) {
                uint32_t off = (uint32_t)(ks*16*36 + htp*8 + koffV) * 4u;
                uint32_t h0,h1,h2,h3, x0,x1,x2,x3;
                ldsm_x4_trans(h0,h1,h2,h3, vhB + off);
                ldsm_x4_trans(x0,x1,x2,x3, vlB + off);
                mma_bf16(O[2*htp],   ah0,ah1,ah2,ah3, h0, h1);
                mma_bf16(O[2*htp],   ah0,ah1,ah2,ah3, x0, x1);
                mma_bf16(O[2*htp],   al0,al1,al2,al3, h0, h1);
                mma_bf16(O[2*htp+1], ah0,ah1,ah2,ah3, h2, h3);
                mma_bf16(O[2*htp+1], ah0,ah1,ah2,ah3, x2, x3);
                mma_bf16(O[2*htp+1], al0,al1,al2,al3, h2, h3);
            }
        }
        __syncthreads();
    }

    float inv0 = 1.0f / l0s;
    float inv1 = 1.0f / l1s;
    #pragma unroll
    for (int ht = 0; ht < 8; ht++) {
        int h = ht*8 + 2*tg;
        float2 r0 = make_float2(O[ht][0]*inv0, O[ht][1]*inv0);
        float2 r1 = make_float2(O[ht][2]*inv1, O[ht][3]*inv1);
        *(float2*)&out[(b*SEQ + frow0)*DMODEL + head*HDIM + h] = r0;
        *(float2*)&out[(b*SEQ + frow1)*DMODEL + head*HDIM + h] = r1;
    }
}

// ---------------------------------------------------------------------------
extern "C" void kernel_launch(void* const* d_in, const int* in_sizes, int n_in,
                              void* d_out, int out_size)
{
    const float* from_t = (const float*)d_in[0];
    const float* to_t   = (const float*)d_in[1];
    const int*   mask   = (const int*)  d_in[2];
    const float* Wq = (const float*)d_in[3];
    const float* bq = (const float*)d_in[4];
    const float* Wk = (const float*)d_in[5];
    const float* bk = (const float*)d_in[6];
    const float* Wv = (const float*)d_in[7];
    const float* bv = (const float*)d_in[8];
    float* out = (float*)d_out;

    pack_x_kernel<<<2*BSROWS, 256>>>(from_t, to_t);
    pack_w_kernel<<<dim3(16, 16, 3), 256>>>(Wq, Wk, Wv);
    mask_flags_kernel<<<dim3(32, 16, BATCH), 256>>>(mask);

    const int proj_smem = 2 * PSTG * 4;   // 61440 B
    cudaFuncSetAttribute(qkv_proj_kernel,
                         cudaFuncAttributeMaxDynamicSharedMemorySize, proj_smem);
    dim3 pgrid(DMODEL/64, BSROWS/128, 3);
    qkv_proj_kernel<<<pgrid, 256, proj_smem>>>(bq, bk, bv);

    const int attn_smem = 2 * ASTG * 4;   // 73728 B
    cudaFuncSetAttribute(attn_kernel,
                         cudaFuncAttributeMaxDynamicSharedMemorySize, attn_smem);
    dim3 agrid(SEQ/128, NHEADS, BATCH);
    attn_kernel<<<agrid, 256, attn_smem>>>(mask, out);
}

// round 9
// speedup vs baseline: 2.9886x; 1.0293x over previous
#include <cuda_runtime.h>
#include <cuda_bf16.h>
#include <cstdint>

#define NHEADS 16
#define HDIM   64
#define DMODEL 1024
#define BATCH  2
#define SEQ    2048
#define BSROWS 4096          // BATCH*SEQ
#define HP     32            // HDIM/2  (bf16 pairs per head row)
#define KPD    512           // DMODEL/2

// --- packed bf16 hi/lo global scratch ---------------------------------------
__device__ uint32_t g_xh[2*BSROWS*KPD],  g_xl[2*BSROWS*KPD];     // from(0)+to(1), [m][k/2]
__device__ uint32_t g_wh[3*DMODEL*KPD],  g_wl[3*DMODEL*KPD];     // [z][n][k/2]
__device__ uint32_t g_qh[BATCH*NHEADS*SEQ*HP], g_ql[BATCH*NHEADS*SEQ*HP];   // [bh][s][h/2]
__device__ uint32_t g_kh[BATCH*NHEADS*SEQ*HP], g_kl[BATCH*NHEADS*SEQ*HP];
__device__ uint32_t g_vh[BATCH*NHEADS*SEQ*HP], g_vl[BATCH*NHEADS*SEQ*HP];
__device__ unsigned char g_mflag[BATCH*16*32];   // [b][f-tile(128)][t-chunk(64)]

// ---------------------------------------------------------------------------
__device__ __forceinline__ void split_pair(float x, float y, uint32_t& hi, uint32_t& lo)
{
    __nv_bfloat16 xh = __float2bfloat16(x);
    __nv_bfloat16 yh = __float2bfloat16(y);
    __nv_bfloat16 xl = __float2bfloat16(x - __bfloat162float(xh));
    __nv_bfloat16 yl = __float2bfloat16(y - __bfloat162float(yh));
    __nv_bfloat162 h2 = __halves2bfloat162(xh, yh);
    __nv_bfloat162 l2 = __halves2bfloat162(xl, yl);
    hi = *reinterpret_cast<uint32_t*>(&h2);
    lo = *reinterpret_cast<uint32_t*>(&l2);
}

// NOTE: non-volatile — outputs create the dependencies; ptxas may schedule.
__device__ __forceinline__ void mma_bf16(float* d,
    uint32_t a0, uint32_t a1, uint32_t a2, uint32_t a3,
    uint32_t b0, uint32_t b1)
{
    asm("mma.sync.aligned.m16n8k16.row.col.f32.bf16.bf16.f32 "
        "{%0,%1,%2,%3}, {%4,%5,%6,%7}, {%8,%9}, {%0,%1,%2,%3};\n"
        : "+f"(d[0]), "+f"(d[1]), "+f"(d[2]), "+f"(d[3])
        : "r"(a0), "r"(a1), "r"(a2), "r"(a3), "r"(b0), "r"(b1));
}

__device__ __forceinline__ void ldsm_x4(uint32_t& r0, uint32_t& r1,
                                        uint32_t& r2, uint32_t& r3, uint32_t addr)
{
    asm volatile("ldmatrix.sync.aligned.m8n8.x4.shared.b16 {%0,%1,%2,%3}, [%4];\n"
        : "=r"(r0), "=r"(r1), "=r"(r2), "=r"(r3) : "r"(addr));
}

__device__ __forceinline__ void ldsm_x4_trans(uint32_t& r0, uint32_t& r1,
                                              uint32_t& r2, uint32_t& r3, uint32_t addr)
{
    asm volatile("ldmatrix.sync.aligned.m8n8.x4.trans.shared.b16 {%0,%1,%2,%3}, [%4];\n"
        : "=r"(r0), "=r"(r1), "=r"(r2), "=r"(r3) : "r"(addr));
}

// ---- cp.async helpers ------------------------------------------------------
__device__ __forceinline__ void cp16(uint32_t dst_smem, const void* src)
{
    asm volatile("cp.async.cg.shared.global [%0], [%1], 16;"
                 :: "r"(dst_smem), "l"(src));
}
__device__ __forceinline__ void cp_commit()
{
    asm volatile("cp.async.commit_group;" ::: "memory");
}
__device__ __forceinline__ void cp_wait1()
{
    asm volatile("cp.async.wait_group 1;" ::: "memory");
}

// ---------------------------------------------------------------------------
// Prep 1: split X into bf16 pairs
// ---------------------------------------------------------------------------
__global__ __launch_bounds__(256) void pack_x_kernel(
    const float* __restrict__ from_t, const float* __restrict__ to_t)
{
    int r = blockIdx.x;
    int c4 = threadIdx.x;
    const float* src = (r < BSROWS) ? (from_t + r*DMODEL)
                                    : (to_t + (r - BSROWS)*DMODEL);
    float4 f = *(const float4*)&src[c4*4];
    uint32_t h0,l0,h1,l1;
    split_pair(f.x, f.y, h0, l0);
    split_pair(f.z, f.w, h1, l1);
    *(uint2*)&g_xh[r*KPD + c4*2] = make_uint2(h0, h1);
    *(uint2*)&g_xl[r*KPD + c4*2] = make_uint2(l0, l1);
}

// ---------------------------------------------------------------------------
// Prep 2: pack W into transposed [z][n][k/2] bf16-pair layout
// ---------------------------------------------------------------------------
__global__ __launch_bounds__(256) void pack_w_kernel(
    const float* __restrict__ Wq, const float* __restrict__ Wk,
    const float* __restrict__ Wv)
{
    __shared__ float T[64][65];
    const int z  = blockIdx.z;
    const int kt = blockIdx.y * 64;
    const int nt = blockIdx.x * 64;
    const float* W = (z == 0) ? Wq : (z == 1 ? Wk : Wv);

    #pragma unroll
    for (int p = 0; p < 4; p++) {
        int idx = threadIdx.x + p*256;
        int kr = idx >> 4;
        int c4 = (idx & 15) * 4;
        float4 v = *(const float4*)&W[(kt+kr)*DMODEL + nt + c4];
        T[kr][c4+0] = v.x; T[kr][c4+1] = v.y;
        T[kr][c4+2] = v.z; T[kr][c4+3] = v.w;
    }
    __syncthreads();

    const int kt2 = kt >> 1;
    #pragma unroll
    for (int p = 0; p < 8; p++) {
        int o = threadIdx.x + p*256;
        int n  = o >> 5;
        int kp = o & 31;
        uint32_t hi, lo;
        split_pair(T[2*kp][n], T[2*kp+1][n], hi, lo);
        int gidx = (z*DMODEL + nt + n)*KPD + kt2 + kp;
        g_wh[gidx] = hi;
        g_wl[gidx] = lo;
    }
}

// ---------------------------------------------------------------------------
// Prep 3: per-(b, 128f-tile, 64t-chunk) all-ones mask flags
// ---------------------------------------------------------------------------
__global__ __launch_bounds__(256) void mask_flags_kernel(const int* __restrict__ mask)
{
    int b  = blockIdx.z;
    int f  = blockIdx.y*128 + (threadIdx.x >> 1);
    int tc = blockIdx.x*64  + (threadIdx.x & 1)*32;
    const int4* p = (const int4*)&mask[(b*SEQ + f)*SEQ + tc];
    int ok = 1;
    #pragma unroll
    for (int i = 0; i < 8; i++) {
        int4 v = p[i];
        ok &= (v.x == 1) & (v.y == 1) & (v.z == 1) & (v.w == 1);
    }
    ok = __syncthreads_and(ok);
    if (threadIdx.x == 0)
        g_mflag[(b*16 + blockIdx.y)*32 + blockIdx.x] = (unsigned char)ok;
}

// ---------------------------------------------------------------------------
// Kernel: QKV projection GEMM, bf16x3, ldmatrix, 3-stage cp.async ring.
// Block 128m x 64n, 8 warps (4m x 2n), warp 32x32, K-step 32.
// ---------------------------------------------------------------------------
#define PSTG 7680            // u32 per stage
#define PA_L 2560
#define PB_H 5120
#define PB_L 6400

__global__ __launch_bounds__(256, 2) void qkv_proj_kernel(
    const float* __restrict__ bq, const float* __restrict__ bk,
    const float* __restrict__ bv)
{
    extern __shared__ uint32_t dsm[];

    const int z = blockIdx.z;
    const uint32_t* Xh = g_xh + (z == 0 ? 0 : BSROWS*KPD);
    const uint32_t* Xl = g_xl + (z == 0 ? 0 : BSROWS*KPD);
    const uint32_t* Wh = g_wh + z*DMODEL*KPD;
    const uint32_t* Wl = g_wl + z*DMODEL*KPD;
    const float* bias  = (z == 0) ? bq : (z == 1 ? bk : bv);
    uint32_t* dsth = (z == 0) ? g_qh : (z == 1 ? g_kh : g_vh);
    uint32_t* dstl = (z == 0) ? g_ql : (z == 1 ? g_kl : g_vl);

    const int m0 = blockIdx.y * 128;
    const int n0 = blockIdx.x * 64;
    const int tid  = threadIdx.x;
    const int wid  = tid >> 5;
    const int lane = tid & 31;
    const int g  = lane >> 2;
    const int tg = lane & 3;
    const int wm = (wid >> 1) * 32;
    const int wn = (wid & 1) * 32;

    const int ar = tid >> 2;          // A/B row (0..63); A also +64
    const int aq = (tid & 3) * 4;     // uint4 col within 16 k-pairs

    const int koffA = (lane & 15)*20 + (lane >> 4)*4;
    const uint32_t sBase = (uint32_t)__cvta_generic_to_shared(dsm);

    auto prefetch = [&](int stage, int kq) {
        uint32_t sb = sBase + (uint32_t)(stage * PSTG) * 4u;
        cp16(sb + (ar*20 + aq)*4u,             &Xh[(m0+ar)*KPD + kq + aq]);
        cp16(sb + ((ar+64)*20 + aq)*4u,        &Xh[(m0+ar+64)*KPD + kq + aq]);
        cp16(sb + (PA_L + ar*20 + aq)*4u,      &Xl[(m0+ar)*KPD + kq + aq]);
        cp16(sb + (PA_L + (ar+64)*20 + aq)*4u, &Xl[(m0+ar+64)*KPD + kq + aq]);
        cp16(sb + (PB_H + ar*20 + aq)*4u,      &Wh[(n0+ar)*KPD + kq + aq]);
        cp16(sb + (PB_L + ar*20 + aq)*4u,      &Wl[(n0+ar)*KPD + kq + aq]);
    };

    float acc[2][4][4] = {};

    prefetch(0, 0);
    cp_commit();

    for (int it = 0; it < 32; it++) {
        if (it + 1 < 32) prefetch((it + 1) % 3, (it + 1) * 16);
        cp_commit();
        cp_wait1();
        __syncthreads();

        const uint32_t aB = sBase + (uint32_t)((it % 3) * PSTG) * 4u;
        #pragma unroll
        for (int ks = 0; ks < 2; ks++) {
            int kb = ks * 8;
            uint32_t ah[2][4], al[2][4], bh[2][4], bl[2][4];
            #pragma unroll
            for (int mi = 0; mi < 2; mi++) {
                uint32_t off = (uint32_t)((wm + mi*16)*20 + kb + koffA) * 4u;
                ldsm_x4(ah[mi][0], ah[mi][1], ah[mi][2], ah[mi][3], aB + off);
                ldsm_x4(al[mi][0], al[mi][1], al[mi][2], al[mi][3], aB + PA_L*4u + off);
            }
            #pragma unroll
            for (int nip = 0; nip < 2; nip++) {
                uint32_t off = (uint32_t)((wn + nip*16)*20 + kb + koffA) * 4u;
                ldsm_x4(bh[nip][0], bh[nip][1], bh[nip][2], bh[nip][3], aB + PB_H*4u + off);
                ldsm_x4(bl[nip][0], bl[nip][1], bl[nip][2], bl[nip][3], aB + PB_L*4u + off);
            }
            // term-major emission: same-acc reuse distance = 8
            #pragma unroll
            for (int t = 0; t < 3; t++) {
                #pragma unroll
                for (int nip = 0; nip < 2; nip++) {
                    #pragma unroll
                    for (int j = 0; j < 2; j++) {
                        int ni = nip*2 + j;
                        #pragma unroll
                        for (int mi = 0; mi < 2; mi++) {
                            if (t == 0)
                                mma_bf16(acc[mi][ni], ah[mi][0],ah[mi][1],ah[mi][2],ah[mi][3],
                                         bh[nip][j], bh[nip][2+j]);
                            else if (t == 1)
                                mma_bf16(acc[mi][ni], ah[mi][0],ah[mi][1],ah[mi][2],ah[mi][3],
                                         bl[nip][j], bl[nip][2+j]);
                            else
                                mma_bf16(acc[mi][ni], al[mi][0],al[mi][1],al[mi][2],al[mi][3],
                                         bh[nip][j], bh[nip][2+j]);
                        }
                    }
                }
            }
        }
    }

    __syncthreads();
    // --- epilogue: bias, split, write packed scratch [bh][s][h/2] ---
    const int head = n0 >> 6;
    #pragma unroll
    for (int ni = 0; ni < 4; ni++) {
        int h = wn + ni*8 + 2*tg;
        int hp = h >> 1;
        float2 b2 = *(const float2*)&bias[n0 + h];
        #pragma unroll
        for (int mi = 0; mi < 2; mi++) {
            int r0 = m0 + wm + mi*16 + g;
            int r1 = r0 + 8;
            int b0i = r0 >> 11, s0 = r0 & (SEQ-1);
            int b1i = r1 >> 11, s1 = r1 & (SEQ-1);
            uint32_t hi, lo;
            split_pair(acc[mi][ni][0] + b2.x, acc[mi][ni][1] + b2.y, hi, lo);
            dsth[((b0i*NHEADS + head)*SEQ + s0)*HP + hp] = hi;
            dstl[((b0i*NHEADS + head)*SEQ + s0)*HP + hp] = lo;
            split_pair(acc[mi][ni][2] + b2.x, acc[mi][ni][3] + b2.y, hi, lo);
            dsth[((b1i*NHEADS + head)*SEQ + s1)*HP + hp] = hi;
            dstl[((b1i*NHEADS + head)*SEQ + s1)*HP + hp] = lo;
        }
    }
}

// ---------------------------------------------------------------------------
// Kernel: flash attention, bf16x3, 3-stage cp.async ring, interleaved MMAs.
// Dynamic smem: 3 stages x (KH|KL|VH|VL, each 64x36 u32) = 110592 B.
// ---------------------------------------------------------------------------
#define ASTG 9216            // u32 per stage
#define A_KL 2304
#define A_VH 4608
#define A_VL 6912

__global__ __launch_bounds__(256, 2) void attn_kernel(
    const int* __restrict__ mask, float* __restrict__ out)
{
    extern __shared__ uint32_t asm_dsm[];

    const int f0   = blockIdx.x * 128;
    const int head = blockIdx.y;
    const int b    = blockIdx.z;
    const int bh   = b*NHEADS + head;
    const int tid  = threadIdx.x;
    const int lane = tid & 31;
    const int g  = lane >> 2;
    const int tg = lane & 3;
    const int fb = (tid >> 5) * 16;

    const int frow0 = f0 + fb + g;
    const int frow1 = frow0 + 8;

    const int koffK = ((((lane>>4)&1)*8 + (lane&7))*36 + ((lane>>3)&1)*4);
    const int koffV = ((((lane>>3)&1)*8 + (lane&7))*36 + ((lane>>4)&1)*4);

    const uint32_t sBase = (uint32_t)__cvta_generic_to_shared(asm_dsm);

    uint32_t qh[4][4], ql[4][4];
    {
        const uint32_t* qph = g_qh + bh*SEQ*HP;
        const uint32_t* qpl = g_ql + bh*SEQ*HP;
        int q0 = frow0*HP, q1 = frow1*HP;
        #pragma unroll
        for (int ks = 0; ks < 4; ks++) {
            int kb = ks*8 + tg;
            qh[ks][0] = qph[q0 + kb];   qh[ks][1] = qph[q1 + kb];
            qh[ks][2] = qph[q0 + kb+4]; qh[ks][3] = qph[q1 + kb+4];
            ql[ks][0] = qpl[q0 + kb];   ql[ks][1] = qpl[q1 + kb];
            ql[ks][2] = qpl[q0 + kb+4]; ql[ks][3] = qpl[q1 + kb+4];
        }
    }

    const uint32_t* kbh = g_kh + bh*SEQ*HP;
    const uint32_t* kbl = g_kl + bh*SEQ*HP;
    const uint32_t* vbh = g_vh + bh*SEQ*HP;
    const uint32_t* vbl = g_vl + bh*SEQ*HP;
    const unsigned char* mfl = &g_mflag[(b*16 + blockIdx.x)*32];

    float m0 = -1e30f, m1 = -1e30f;
    float l0s = 0.0f, l1s = 0.0f;
    float O[8][4] = {};

    const int cr  = tid >> 3;        // 0..31 -> rows cr, cr+32
    const int cc4 = (tid & 7) * 4;

    auto prefetch = [&](int stage, int t0) {
        uint32_t sb = sBase + (uint32_t)(stage * ASTG) * 4u;
        cp16(sb + (cr*36 + cc4)*4u,               &kbh[(t0+cr)*HP + cc4]);
        cp16(sb + ((cr+32)*36 + cc4)*4u,          &kbh[(t0+cr+32)*HP + cc4]);
        cp16(sb + (A_KL + cr*36 + cc4)*4u,        &kbl[(t0+cr)*HP + cc4]);
        cp16(sb + (A_KL + (cr+32)*36 + cc4)*4u,   &kbl[(t0+cr+32)*HP + cc4]);
        cp16(sb + (A_VH + cr*36 + cc4)*4u,        &vbh[(t0+cr)*HP + cc4]);
        cp16(sb + (A_VH + (cr+32)*36 + cc4)*4u,   &vbh[(t0+cr+32)*HP + cc4]);
        cp16(sb + (A_VL + cr*36 + cc4)*4u,        &vbl[(t0+cr)*HP + cc4]);
        cp16(sb + (A_VL + (cr+32)*36 + cc4)*4u,   &vbl[(t0+cr+32)*HP + cc4]);
    };

    prefetch(0, 0);
    cp_commit();

    for (int it = 0; it < SEQ/64; it++) {
        const int t0 = it * 64;
        if (it + 1 < SEQ/64) prefetch((it + 1) % 3, t0 + 64);
        cp_commit();
        cp_wait1();
        __syncthreads();

        const uint32_t sb = sBase + (uint32_t)((it % 3) * ASTG) * 4u;
        const uint32_t khB = sb;
        const uint32_t klB = sb + A_KL*4u;
        const uint32_t vhB = sb + A_VH*4u;
        const uint32_t vlB = sb + A_VL*4u;

        // --- S = Q K^T (interleaved same-acc spacing 2) ---
        float s[8][4] = {};
        #pragma unroll
        for (int ks = 0; ks < 4; ks++) {
            int kb = ks * 8;
            #pragma unroll
            for (int ntp = 0; ntp < 4; ntp++) {
                uint32_t off = (uint32_t)(ntp*16*36 + koffK + kb) * 4u;
                uint32_t h0,h1,h2,h3, x0,x1,x2,x3;
                ldsm_x4(h0,h1,h2,h3, khB + off);
                ldsm_x4(x0,x1,x2,x3, klB + off);
                float* sA = s[2*ntp];
                float* sB = s[2*ntp+1];
                mma_bf16(sA, qh[ks][0],qh[ks][1],qh[ks][2],qh[ks][3], h0, h1);
                mma_bf16(sB, qh[ks][0],qh[ks][1],qh[ks][2],qh[ks][3], h2, h3);
                mma_bf16(sA, qh[ks][0],qh[ks][1],qh[ks][2],qh[ks][3], x0, x1);
                mma_bf16(sB, qh[ks][0],qh[ks][1],qh[ks][2],qh[ks][3], x2, x3);
                mma_bf16(sA, ql[ks][0],ql[ks][1],ql[ks][2],ql[ks][3], h0, h1);
                mma_bf16(sB, ql[ks][0],ql[ks][1],ql[ks][2],ql[ks][3], h2, h3);
            }
        }

        float rmax0 = -1e30f, rmax1 = -1e30f;
        if (mfl[it]) {
            #pragma unroll
            for (int nt = 0; nt < 8; nt++) {
                s[nt][0] *= 0.125f; s[nt][1] *= 0.125f;
                s[nt][2] *= 0.125f; s[nt][3] *= 0.125f;
                rmax0 = fmaxf(rmax0, fmaxf(s[nt][0], s[nt][1]));
                rmax1 = fmaxf(rmax1, fmaxf(s[nt][2], s[nt][3]));
            }
        } else {
            #pragma unroll
            for (int nt = 0; nt < 8; nt++) {
                int tc = t0 + nt*8 + 2*tg;
                int2 mk0 = *(const int2*)&mask[(b*SEQ + frow0)*SEQ + tc];
                int2 mk1 = *(const int2*)&mask[(b*SEQ + frow1)*SEQ + tc];
                s[nt][0] = s[nt][0]*0.125f + (1.0f - (float)mk0.x) * -10000.0f;
                s[nt][1] = s[nt][1]*0.125f + (1.0f - (float)mk0.y) * -10000.0f;
                s[nt][2] = s[nt][2]*0.125f + (1.0f - (float)mk1.x) * -10000.0f;
                s[nt][3] = s[nt][3]*0.125f + (1.0f - (float)mk1.y) * -10000.0f;
                rmax0 = fmaxf(rmax0, fmaxf(s[nt][0], s[nt][1]));
                rmax1 = fmaxf(rmax1, fmaxf(s[nt][2], s[nt][3]));
            }
        }
        rmax0 = fmaxf(rmax0, __shfl_xor_sync(0xffffffffu, rmax0, 1));
        rmax0 = fmaxf(rmax0, __shfl_xor_sync(0xffffffffu, rmax0, 2));
        rmax1 = fmaxf(rmax1, __shfl_xor_sync(0xffffffffu, rmax1, 1));
        rmax1 = fmaxf(rmax1, __shfl_xor_sync(0xffffffffu, rmax1, 2));

        float mn0 = fmaxf(m0, rmax0), mn1 = fmaxf(m1, rmax1);
        float a0 = __expf(m0 - mn0),  a1 = __expf(m1 - mn1);
        m0 = mn0; m1 = mn1;

        uint32_t ph0[8], ph1[8], pl0[8], pl1[8];
        float ps0 = 0.0f, ps1 = 0.0f;
        #pragma unroll
        for (int nt = 0; nt < 8; nt++) {
            float p00 = __expf(s[nt][0] - mn0);
            float p01 = __expf(s[nt][1] - mn0);
            float p10 = __expf(s[nt][2] - mn1);
            float p11 = __expf(s[nt][3] - mn1);
            ps0 += p00 + p01;
            ps1 += p10 + p11;
            split_pair(p00, p01, ph0[nt], pl0[nt]);
            split_pair(p10, p11, ph1[nt], pl1[nt]);
        }
        ps0 += __shfl_xor_sync(0xffffffffu, ps0, 1);
        ps0 += __shfl_xor_sync(0xffffffffu, ps0, 2);
        ps1 += __shfl_xor_sync(0xffffffffu, ps1, 1);
        ps1 += __shfl_xor_sync(0xffffffffu, ps1, 2);
        l0s = l0s * a0 + ps0;
        l1s = l1s * a1 + ps1;

        #pragma unroll
        for (int ht = 0; ht < 8; ht++) {
            O[ht][0] *= a0; O[ht][1] *= a0;
            O[ht][2] *= a1; O[ht][3] *= a1;
        }

        // --- O += P V (interleaved same-acc spacing 2) ---
        #pragma unroll
        for (int ks = 0; ks < 4; ks++) {
            uint32_t ah0 = ph0[2*ks],   ah1 = ph1[2*ks];
            uint32_t ah2 = ph0[2*ks+1], ah3 = ph1[2*ks+1];
            uint32_t al0 = pl0[2*ks],   al1 = pl1[2*ks];
            uint32_t al2 = pl0[2*ks+1], al3 = pl1[2*ks+1];
            #pragma unroll
            for (int htp = 0; htp < 4; htp++) {
                uint32_t off = (uint32_t)(ks*16*36 + htp*8 + koffV) * 4u;
                uint32_t h0,h1,h2,h3, x0,x1,x2,x3;
                ldsm_x4_trans(h0,h1,h2,h3, vhB + off);
                ldsm_x4_trans(x0,x1,x2,x3, vlB + off);
                float* oA = O[2*htp];
                float* oB = O[2*htp+1];
                mma_bf16(oA, ah0,ah1,ah2,ah3, h0, h1);
                mma_bf16(oB, ah0,ah1,ah2,ah3, h2, h3);
                mma_bf16(oA, ah0,ah1,ah2,ah3, x0, x1);
                mma_bf16(oB, ah0,ah1,ah2,ah3, x2, x3);
                mma_bf16(oA, al0,al1,al2,al3, h0, h1);
                mma_bf16(oB, al0,al1,al2,al3, h2, h3);
            }
        }
    }

    float inv0 = 1.0f / l0s;
    float inv1 = 1.0f / l1s;
    #pragma unroll
    for (int ht = 0; ht < 8; ht++) {
        int h = ht*8 + 2*tg;
        float2 r0 = make_float2(O[ht][0]*inv0, O[ht][1]*inv0);
        float2 r1 = make_float2(O[ht][2]*inv1, O[ht][3]*inv1);
        *(float2*)&out[(b*SEQ + frow0)*DMODEL + head*HDIM + h] = r0;
        *(float2*)&out[(b*SEQ + frow1)*DMODEL + head*HDIM + h] = r1;
    }
}

// ---------------------------------------------------------------------------
extern "C" void kernel_launch(void* const* d_in, const int* in_sizes, int n_in,
                              void* d_out, int out_size)
{
    const float* from_t = (const float*)d_in[0];
    const float* to_t   = (const float*)d_in[1];
    const int*   mask   = (const int*)  d_in[2];
    const float* Wq = (const float*)d_in[3];
    const float* bq = (const float*)d_in[4];
    const float* Wk = (const float*)d_in[5];
    const float* bk = (const float*)d_in[6];
    const float* Wv = (const float*)d_in[7];
    const float* bv = (const float*)d_in[8];
    float* out = (float*)d_out;

    pack_x_kernel<<<2*BSROWS, 256>>>(from_t, to_t);
    pack_w_kernel<<<dim3(16, 16, 3), 256>>>(Wq, Wk, Wv);
    mask_flags_kernel<<<dim3(32, 16, BATCH), 256>>>(mask);

    const int proj_smem = 3 * PSTG * 4;   // 92160 B
    cudaFuncSetAttribute(qkv_proj_kernel,
                         cudaFuncAttributeMaxDynamicSharedMemorySize, proj_smem);
    dim3 pgrid(DMODEL/64, BSROWS/128, 3);
    qkv_proj_kernel<<<pgrid, 256, proj_smem>>>(bq, bk, bv);

    const int attn_smem = 3 * ASTG * 4;   // 110592 B
    cudaFuncSetAttribute(attn_kernel,
                         cudaFuncAttributeMaxDynamicSharedMemorySize, attn_smem);
    dim3 agrid(SEQ/128, NHEADS, BATCH);
    attn_kernel<<<agrid, 256, attn_smem>>>(mask, out);
}

// round 10
// speedup vs baseline: 4.1577x; 1.3912x over previous
#include <cuda_runtime.h>
#include <cuda_fp16.h>
#include <cstdint>

#define NHEADS 16
#define HDIM   64
#define DMODEL 1024
#define BATCH  2
#define SEQ    2048
#define BSROWS 4096          // BATCH*SEQ
#define HP     32            // HDIM/2  (fp16 pairs per head row)
#define KPD    512           // DMODEL/2

// --- packed fp16 global scratch ---------------------------------------------
// X split exactly into hi+lo fp16 pairs; W rounded to single fp16.
__device__ uint32_t g_xh[2*BSROWS*KPD],  g_xl[2*BSROWS*KPD];     // from(0)+to(1), [m][k/2]
__device__ uint32_t g_w[3*DMODEL*KPD];                           // [z][n][k/2] single fp16
__device__ uint32_t g_qh[BATCH*NHEADS*SEQ*HP], g_ql[BATCH*NHEADS*SEQ*HP];   // Q split
__device__ uint32_t g_k[BATCH*NHEADS*SEQ*HP];                    // K single fp16
__device__ uint32_t g_v[BATCH*NHEADS*SEQ*HP];                    // V single fp16
__device__ unsigned char g_mflag[BATCH*16*32];   // [b][f-tile(128)][t-chunk(64)]

// ---------------------------------------------------------------------------
__device__ __forceinline__ void split_pair_h(float x, float y, uint32_t& hi, uint32_t& lo)
{
    __half xh = __float2half_rn(x);
    __half yh = __float2half_rn(y);
    __half xl = __float2half_rn(x - __half2float(xh));
    __half yl = __float2half_rn(y - __half2float(yh));
    __half2 h2 = __halves2half2(xh, yh);
    __half2 l2 = __halves2half2(xl, yl);
    hi = *reinterpret_cast<uint32_t*>(&h2);
    lo = *reinterpret_cast<uint32_t*>(&l2);
}

__device__ __forceinline__ uint32_t round_pair_h(float x, float y)
{
    __half2 h2 = __halves2half2(__float2half_rn(x), __float2half_rn(y));
    return *reinterpret_cast<uint32_t*>(&h2);
}

// fp16 inputs, fp32 accumulate. Non-volatile: ptxas may schedule.
__device__ __forceinline__ void mma_f16(float* d,
    uint32_t a0, uint32_t a1, uint32_t a2, uint32_t a3,
    uint32_t b0, uint32_t b1)
{
    asm("mma.sync.aligned.m16n8k16.row.col.f32.f16.f16.f32 "
        "{%0,%1,%2,%3}, {%4,%5,%6,%7}, {%8,%9}, {%0,%1,%2,%3};\n"
        : "+f"(d[0]), "+f"(d[1]), "+f"(d[2]), "+f"(d[3])
        : "r"(a0), "r"(a1), "r"(a2), "r"(a3), "r"(b0), "r"(b1));
}

__device__ __forceinline__ void ldsm_x4(uint32_t& r0, uint32_t& r1,
                                        uint32_t& r2, uint32_t& r3, uint32_t addr)
{
    asm volatile("ldmatrix.sync.aligned.m8n8.x4.shared.b16 {%0,%1,%2,%3}, [%4];\n"
        : "=r"(r0), "=r"(r1), "=r"(r2), "=r"(r3) : "r"(addr));
}

__device__ __forceinline__ void ldsm_x4_trans(uint32_t& r0, uint32_t& r1,
                                              uint32_t& r2, uint32_t& r3, uint32_t addr)
{
    asm volatile("ldmatrix.sync.aligned.m8n8.x4.trans.shared.b16 {%0,%1,%2,%3}, [%4];\n"
        : "=r"(r0), "=r"(r1), "=r"(r2), "=r"(r3) : "r"(addr));
}

// ---- cp.async helpers ------------------------------------------------------
__device__ __forceinline__ void cp16(uint32_t dst_smem, const void* src)
{
    asm volatile("cp.async.cg.shared.global [%0], [%1], 16;"
                 :: "r"(dst_smem), "l"(src));
}
__device__ __forceinline__ void cp_commit()
{
    asm volatile("cp.async.commit_group;" ::: "memory");
}
__device__ __forceinline__ void cp_wait1()
{
    asm volatile("cp.async.wait_group 1;" ::: "memory");
}

// ---------------------------------------------------------------------------
// Prep 1: split X into fp16 hi/lo pairs
// ---------------------------------------------------------------------------
__global__ __launch_bounds__(256) void pack_x_kernel(
    const float* __restrict__ from_t, const float* __restrict__ to_t)
{
    int r = blockIdx.x;
    int c4 = threadIdx.x;
    const float* src = (r < BSROWS) ? (from_t + r*DMODEL)
                                    : (to_t + (r - BSROWS)*DMODEL);
    float4 f = *(const float4*)&src[c4*4];
    uint32_t h0,l0,h1,l1;
    split_pair_h(f.x, f.y, h0, l0);
    split_pair_h(f.z, f.w, h1, l1);
    *(uint2*)&g_xh[r*KPD + c4*2] = make_uint2(h0, h1);
    *(uint2*)&g_xl[r*KPD + c4*2] = make_uint2(l0, l1);
}

// ---------------------------------------------------------------------------
// Prep 2: pack W into transposed [z][n][k/2] single-fp16 layout
// ---------------------------------------------------------------------------
__global__ __launch_bounds__(256) void pack_w_kernel(
    const float* __restrict__ Wq, const float* __restrict__ Wk,
    const float* __restrict__ Wv)
{
    __shared__ float T[64][65];
    const int z  = blockIdx.z;
    const int kt = blockIdx.y * 64;
    const int nt = blockIdx.x * 64;
    const float* W = (z == 0) ? Wq : (z == 1 ? Wk : Wv);

    #pragma unroll
    for (int p = 0; p < 4; p++) {
        int idx = threadIdx.x + p*256;
        int kr = idx >> 4;
        int c4 = (idx & 15) * 4;
        float4 v = *(const float4*)&W[(kt+kr)*DMODEL + nt + c4];
        T[kr][c4+0] = v.x; T[kr][c4+1] = v.y;
        T[kr][c4+2] = v.z; T[kr][c4+3] = v.w;
    }
    __syncthreads();

    const int kt2 = kt >> 1;
    #pragma unroll
    for (int p = 0; p < 8; p++) {
        int o = threadIdx.x + p*256;
        int n  = o >> 5;
        int kp = o & 31;
        int gidx = (z*DMODEL + nt + n)*KPD + kt2 + kp;
        g_w[gidx] = round_pair_h(T[2*kp][n], T[2*kp+1][n]);
    }
}

// ---------------------------------------------------------------------------
// Prep 3: per-(b, 128f-tile, 64t-chunk) all-ones mask flags
// ---------------------------------------------------------------------------
__global__ __launch_bounds__(256) void mask_flags_kernel(const int* __restrict__ mask)
{
    int b  = blockIdx.z;
    int f  = blockIdx.y*128 + (threadIdx.x >> 1);
    int tc = blockIdx.x*64  + (threadIdx.x & 1)*32;
    const int4* p = (const int4*)&mask[(b*SEQ + f)*SEQ + tc];
    int ok = 1;
    #pragma unroll
    for (int i = 0; i < 8; i++) {
        int4 v = p[i];
        ok &= (v.x == 1) & (v.y == 1) & (v.z == 1) & (v.w == 1);
    }
    ok = __syncthreads_and(ok);
    if (threadIdx.x == 0)
        g_mflag[(b*16 + blockIdx.y)*32 + blockIdx.x] = (unsigned char)ok;
}

// ---------------------------------------------------------------------------
// Kernel: QKV projection GEMM, fp16x2 (X split, W single), 3-stage cp.async.
// Block 128m x 64n, 8 warps (4m x 2n), warp 32x32, K-step 32.
// Stage: XH 128x20 | XL 128x20 | WH 64x20  = 6400 u32.
// ---------------------------------------------------------------------------
#define PSTG 6400
#define PA_L 2560
#define PB_H 5120

__global__ __launch_bounds__(256, 2) void qkv_proj_kernel(
    const float* __restrict__ bq, const float* __restrict__ bk,
    const float* __restrict__ bv)
{
    extern __shared__ uint32_t dsm[];

    const int z = blockIdx.z;
    const uint32_t* Xh = g_xh + (z == 0 ? 0 : BSROWS*KPD);
    const uint32_t* Xl = g_xl + (z == 0 ? 0 : BSROWS*KPD);
    const uint32_t* Wp = g_w + z*DMODEL*KPD;
    const float* bias  = (z == 0) ? bq : (z == 1 ? bk : bv);

    const int m0 = blockIdx.y * 128;
    const int n0 = blockIdx.x * 64;
    const int tid  = threadIdx.x;
    const int wid  = tid >> 5;
    const int lane = tid & 31;
    const int g  = lane >> 2;
    const int tg = lane & 3;
    const int wm = (wid >> 1) * 32;
    const int wn = (wid & 1) * 32;

    const int ar = tid >> 2;          // row 0..63 (A also +64)
    const int aq = (tid & 3) * 4;     // uint4 col within 16 k-pairs

    const int koffA = (lane & 15)*20 + (lane >> 4)*4;
    const uint32_t sBase = (uint32_t)__cvta_generic_to_shared(dsm);

    auto prefetch = [&](int stage, int kq) {
        uint32_t sb = sBase + (uint32_t)(stage * PSTG) * 4u;
        cp16(sb + (ar*20 + aq)*4u,             &Xh[(m0+ar)*KPD + kq + aq]);
        cp16(sb + ((ar+64)*20 + aq)*4u,        &Xh[(m0+ar+64)*KPD + kq + aq]);
        cp16(sb + (PA_L + ar*20 + aq)*4u,      &Xl[(m0+ar)*KPD + kq + aq]);
        cp16(sb + (PA_L + (ar+64)*20 + aq)*4u, &Xl[(m0+ar+64)*KPD + kq + aq]);
        cp16(sb + (PB_H + ar*20 + aq)*4u,      &Wp[(n0+ar)*KPD + kq + aq]);
    };

    float acc[2][4][4] = {};

    prefetch(0, 0);
    cp_commit();

    for (int it = 0; it < 32; it++) {
        if (it + 1 < 32) prefetch((it + 1) % 3, (it + 1) * 16);
        cp_commit();
        cp_wait1();
        __syncthreads();

        const uint32_t aB = sBase + (uint32_t)((it % 3) * PSTG) * 4u;
        #pragma unroll
        for (int ks = 0; ks < 2; ks++) {
            int kb = ks * 8;
            uint32_t ah[2][4], al[2][4], bh[2][4];
            #pragma unroll
            for (int mi = 0; mi < 2; mi++) {
                uint32_t off = (uint32_t)((wm + mi*16)*20 + kb + koffA) * 4u;
                ldsm_x4(ah[mi][0], ah[mi][1], ah[mi][2], ah[mi][3], aB + off);
                ldsm_x4(al[mi][0], al[mi][1], al[mi][2], al[mi][3], aB + PA_L*4u + off);
            }
            #pragma unroll
            for (int nip = 0; nip < 2; nip++) {
                uint32_t off = (uint32_t)((wn + nip*16)*20 + kb + koffA) * 4u;
                ldsm_x4(bh[nip][0], bh[nip][1], bh[nip][2], bh[nip][3], aB + PB_H*4u + off);
            }
            // term-major: hi-term for all 8 accs, then lo-term
            #pragma unroll
            for (int t = 0; t < 2; t++) {
                #pragma unroll
                for (int nip = 0; nip < 2; nip++) {
                    #pragma unroll
                    for (int j = 0; j < 2; j++) {
                        int ni = nip*2 + j;
                        #pragma unroll
                        for (int mi = 0; mi < 2; mi++) {
                            if (t == 0)
                                mma_f16(acc[mi][ni], ah[mi][0],ah[mi][1],ah[mi][2],ah[mi][3],
                                        bh[nip][j], bh[nip][2+j]);
                            else
                                mma_f16(acc[mi][ni], al[mi][0],al[mi][1],al[mi][2],al[mi][3],
                                        bh[nip][j], bh[nip][2+j]);
                        }
                    }
                }
            }
        }
    }

    __syncthreads();
    // --- epilogue: bias; Q -> split fp16x2 scratch; K/V -> single fp16 ---
    const int head = n0 >> 6;
    #pragma unroll
    for (int ni = 0; ni < 4; ni++) {
        int h = wn + ni*8 + 2*tg;
        int hp = h >> 1;
        float2 b2 = *(const float2*)&bias[n0 + h];
        #pragma unroll
        for (int mi = 0; mi < 2; mi++) {
            int r0 = m0 + wm + mi*16 + g;
            int r1 = r0 + 8;
            int b0i = r0 >> 11, s0 = r0 & (SEQ-1);
            int b1i = r1 >> 11, s1 = r1 & (SEQ-1);
            size_t i0 = ((size_t)(b0i*NHEADS + head)*SEQ + s0)*HP + hp;
            size_t i1 = ((size_t)(b1i*NHEADS + head)*SEQ + s1)*HP + hp;
            float v00 = acc[mi][ni][0] + b2.x, v01 = acc[mi][ni][1] + b2.y;
            float v10 = acc[mi][ni][2] + b2.x, v11 = acc[mi][ni][3] + b2.y;
            if (z == 0) {
                uint32_t hi, lo;
                split_pair_h(v00, v01, hi, lo);
                g_qh[i0] = hi; g_ql[i0] = lo;
                split_pair_h(v10, v11, hi, lo);
                g_qh[i1] = hi; g_ql[i1] = lo;
            } else {
                uint32_t* dst = (z == 1) ? g_k : g_v;
                dst[i0] = round_pair_h(v00, v01);
                dst[i1] = round_pair_h(v10, v11);
            }
        }
    }
}

// ---------------------------------------------------------------------------
// Kernel: flash attention, fp16x2 (Q/P split, K/V single), 3-stage cp.async.
// Stage: K 64x36 | V 64x36 = 4608 u32.
// ---------------------------------------------------------------------------
#define ASTG 4608
#define A_VH 2304

__global__ __launch_bounds__(256, 2) void attn_kernel(
    const int* __restrict__ mask, float* __restrict__ out)
{
    extern __shared__ uint32_t asm_dsm[];

    const int f0   = blockIdx.x * 128;
    const int head = blockIdx.y;
    const int b    = blockIdx.z;
    const int bh   = b*NHEADS + head;
    const int tid  = threadIdx.x;
    const int lane = tid & 31;
    const int g  = lane >> 2;
    const int tg = lane & 3;
    const int fb = (tid >> 5) * 16;

    const int frow0 = f0 + fb + g;
    const int frow1 = frow0 + 8;

    const int koffK = ((((lane>>4)&1)*8 + (lane&7))*36 + ((lane>>3)&1)*4);
    const int koffV = ((((lane>>3)&1)*8 + (lane&7))*36 + ((lane>>4)&1)*4);

    const uint32_t sBase = (uint32_t)__cvta_generic_to_shared(asm_dsm);

    // --- preload Q fragments (hi/lo) ---
    uint32_t qh[4][4], ql[4][4];
    {
        const uint32_t* qph = g_qh + bh*SEQ*HP;
        const uint32_t* qpl = g_ql + bh*SEQ*HP;
        int q0 = frow0*HP, q1 = frow1*HP;
        #pragma unroll
        for (int ks = 0; ks < 4; ks++) {
            int kb = ks*8 + tg;
            qh[ks][0] = qph[q0 + kb];   qh[ks][1] = qph[q1 + kb];
            qh[ks][2] = qph[q0 + kb+4]; qh[ks][3] = qph[q1 + kb+4];
            ql[ks][0] = qpl[q0 + kb];   ql[ks][1] = qpl[q1 + kb];
            ql[ks][2] = qpl[q0 + kb+4]; ql[ks][3] = qpl[q1 + kb+4];
        }
    }

    const uint32_t* kb_g = g_k + bh*SEQ*HP;
    const uint32_t* vb_g = g_v + bh*SEQ*HP;
    const unsigned char* mfl = &g_mflag[(b*16 + blockIdx.x)*32];

    float m0 = -1e30f, m1 = -1e30f;
    float l0s = 0.0f, l1s = 0.0f;
    float O[8][4] = {};

    const int cr  = tid >> 3;        // 0..31 -> rows cr, cr+32
    const int cc4 = (tid & 7) * 4;

    auto prefetch = [&](int stage, int t0) {
        uint32_t sb = sBase + (uint32_t)(stage * ASTG) * 4u;
        cp16(sb + (cr*36 + cc4)*4u,               &kb_g[(t0+cr)*HP + cc4]);
        cp16(sb + ((cr+32)*36 + cc4)*4u,          &kb_g[(t0+cr+32)*HP + cc4]);
        cp16(sb + (A_VH + cr*36 + cc4)*4u,        &vb_g[(t0+cr)*HP + cc4]);
        cp16(sb + (A_VH + (cr+32)*36 + cc4)*4u,   &vb_g[(t0+cr+32)*HP + cc4]);
    };

    prefetch(0, 0);
    cp_commit();

    for (int it = 0; it < SEQ/64; it++) {
        const int t0 = it * 64;
        if (it + 1 < SEQ/64) prefetch((it + 1) % 3, t0 + 64);
        cp_commit();
        cp_wait1();
        __syncthreads();

        const uint32_t sb = sBase + (uint32_t)((it % 3) * ASTG) * 4u;
        const uint32_t khB = sb;
        const uint32_t vhB = sb + A_VH*4u;

        // --- S = Q K^T ---
        float s[8][4] = {};
        #pragma unroll
        for (int ks = 0; ks < 4; ks++) {
            int kb = ks * 8;
            #pragma unroll
            for (int ntp = 0; ntp < 4; ntp++) {
                uint32_t off = (uint32_t)(ntp*16*36 + koffK + kb) * 4u;
                uint32_t k0,k1,k2,k3;
                ldsm_x4(k0,k1,k2,k3, khB + off);
                float* sA = s[2*ntp];
                float* sB = s[2*ntp+1];
                mma_f16(sA, qh[ks][0],qh[ks][1],qh[ks][2],qh[ks][3], k0, k1);
                mma_f16(sB, qh[ks][0],qh[ks][1],qh[ks][2],qh[ks][3], k2, k3);
                mma_f16(sA, ql[ks][0],ql[ks][1],ql[ks][2],ql[ks][3], k0, k1);
                mma_f16(sB, ql[ks][0],ql[ks][1],ql[ks][2],ql[ks][3], k2, k3);
            }
        }

        // --- scale + mask (skippable) + chunk row max ---
        float rmax0 = -1e30f, rmax1 = -1e30f;
        if (mfl[it]) {
            #pragma unroll
            for (int nt = 0; nt < 8; nt++) {
                s[nt][0] *= 0.125f; s[nt][1] *= 0.125f;
                s[nt][2] *= 0.125f; s[nt][3] *= 0.125f;
                rmax0 = fmaxf(rmax0, fmaxf(s[nt][0], s[nt][1]));
                rmax1 = fmaxf(rmax1, fmaxf(s[nt][2], s[nt][3]));
            }
        } else {
            #pragma unroll
            for (int nt = 0; nt < 8; nt++) {
                int tc = t0 + nt*8 + 2*tg;
                int2 mk0 = *(const int2*)&mask[(b*SEQ + frow0)*SEQ + tc];
                int2 mk1 = *(const int2*)&mask[(b*SEQ + frow1)*SEQ + tc];
                s[nt][0] = s[nt][0]*0.125f + (1.0f - (float)mk0.x) * -10000.0f;
                s[nt][1] = s[nt][1]*0.125f + (1.0f - (float)mk0.y) * -10000.0f;
                s[nt][2] = s[nt][2]*0.125f + (1.0f - (float)mk1.x) * -10000.0f;
                s[nt][3] = s[nt][3]*0.125f + (1.0f - (float)mk1.y) * -10000.0f;
                rmax0 = fmaxf(rmax0, fmaxf(s[nt][0], s[nt][1]));
                rmax1 = fmaxf(rmax1, fmaxf(s[nt][2], s[nt][3]));
            }
        }
        rmax0 = fmaxf(rmax0, __shfl_xor_sync(0xffffffffu, rmax0, 1));
        rmax0 = fmaxf(rmax0, __shfl_xor_sync(0xffffffffu, rmax0, 2));
        rmax1 = fmaxf(rmax1, __shfl_xor_sync(0xffffffffu, rmax1, 1));
        rmax1 = fmaxf(rmax1, __shfl_xor_sync(0xffffffffu, rmax1, 2));

        float mn0 = fmaxf(m0, rmax0), mn1 = fmaxf(m1, rmax1);
        float a0 = __expf(m0 - mn0),  a1 = __expf(m1 - mn1);
        m0 = mn0; m1 = mn1;

        // --- exp + split P fragments (hi/lo fp16) in registers ---
        uint32_t ph0[8], ph1[8], pl0[8], pl1[8];
        float ps0 = 0.0f, ps1 = 0.0f;
        #pragma unroll
        for (int nt = 0; nt < 8; nt++) {
            float p00 = __expf(s[nt][0] - mn0);
            float p01 = __expf(s[nt][1] - mn0);
            float p10 = __expf(s[nt][2] - mn1);
            float p11 = __expf(s[nt][3] - mn1);
            ps0 += p00 + p01;
            ps1 += p10 + p11;
            split_pair_h(p00, p01, ph0[nt], pl0[nt]);
            split_pair_h(p10, p11, ph1[nt], pl1[nt]);
        }
        ps0 += __shfl_xor_sync(0xffffffffu, ps0, 1);
        ps0 += __shfl_xor_sync(0xffffffffu, ps0, 2);
        ps1 += __shfl_xor_sync(0xffffffffu, ps1, 1);
        ps1 += __shfl_xor_sync(0xffffffffu, ps1, 2);
        l0s = l0s * a0 + ps0;
        l1s = l1s * a1 + ps1;

        #pragma unroll
        for (int ht = 0; ht < 8; ht++) {
            O[ht][0] *= a0; O[ht][1] *= a0;
            O[ht][2] *= a1; O[ht][3] *= a1;
        }

        // --- O += P V ---
        #pragma unroll
        for (int ks = 0; ks < 4; ks++) {
            uint32_t ah0 = ph0[2*ks],   ah1 = ph1[2*ks];
            uint32_t ah2 = ph0[2*ks+1], ah3 = ph1[2*ks+1];
            uint32_t al0 = pl0[2*ks],   al1 = pl1[2*ks];
            uint32_t al2 = pl0[2*ks+1], al3 = pl1[2*ks+1];
            #pragma unroll
            for (int htp = 0; htp < 4; htp++) {
                uint32_t off = (uint32_t)(ks*16*36 + htp*8 + koffV) * 4u;
                uint32_t v0,v1,v2,v3;
                ldsm_x4_trans(v0,v1,v2,v3, vhB + off);
                float* oA = O[2*htp];
                float* oB = O[2*htp+1];
                mma_f16(oA, ah0,ah1,ah2,ah3, v0, v1);
                mma_f16(oB, ah0,ah1,ah2,ah3, v2, v3);
                mma_f16(oA, al0,al1,al2,al3, v0, v1);
                mma_f16(oB, al0,al1,al2,al3, v2, v3);
            }
        }
    }

    float inv0 = 1.0f / l0s;
    float inv1 = 1.0f / l1s;
    #pragma unroll
    for (int ht = 0; ht < 8; ht++) {
        int h = ht*8 + 2*tg;
        float2 r0 = make_float2(O[ht][0]*inv0, O[ht][1]*inv0);
        float2 r1 = make_float2(O[ht][2]*inv1, O[ht][3]*inv1);
        *(float2*)&out[(b*SEQ + frow0)*DMODEL + head*HDIM + h] = r0;
        *(float2*)&out[(b*SEQ + frow1)*DMODEL + head*HDIM + h] = r1;
    }
}

// ---------------------------------------------------------------------------
extern "C" void kernel_launch(void* const* d_in, const int* in_sizes, int n_in,
                              void* d_out, int out_size)
{
    const float* from_t = (const float*)d_in[0];
    const float* to_t   = (const float*)d_in[1];
    const int*   mask   = (const int*)  d_in[2];
    const float* Wq = (const float*)d_in[3];
    const float* bq = (const float*)d_in[4];
    const float* Wk = (const float*)d_in[5];
    const float* bk = (const float*)d_in[6];
    const float* Wv = (const float*)d_in[7];
    const float* bv = (const float*)d_in[8];
    float* out = (float*)d_out;

    pack_x_kernel<<<2*BSROWS, 256>>>(from_t, to_t);
    pack_w_kernel<<<dim3(16, 16, 3), 256>>>(Wq, Wk, Wv);
    mask_flags_kernel<<<dim3(32, 16, BATCH), 256>>>(mask);

    const int proj_smem = 3 * PSTG * 4;   // 76800 B
    cudaFuncSetAttribute(qkv_proj_kernel,
                         cudaFuncAttributeMaxDynamicSharedMemorySize, proj_smem);
    dim3 pgrid(DMODEL/64, BSROWS/128, 3);
    qkv_proj_kernel<<<pgrid, 256, proj_smem>>>(bq, bk, bv);

    const int attn_smem = 3 * ASTG * 4;   // 55296 B
    cudaFuncSetAttribute(attn_kernel,
                         cudaFuncAttributeMaxDynamicSharedMemorySize, attn_smem);
    dim3 agrid(SEQ/128, NHEADS, BATCH);
    attn_kernel<<<agrid, 256, attn_smem>>>(mask, out);
}

// round 11
// speedup vs baseline: 5.2717x; 1.2679x over previous
#include <cuda_runtime.h>
#include <cuda_fp16.h>
#include <cstdint>

#define NHEADS 16
#define HDIM   64
#define DMODEL 1024
#define BATCH  2
#define SEQ    2048
#define BSROWS 4096          // BATCH*SEQ
#define HP     32            // HDIM/2  (fp16 pairs per head row)
#define KPD    512           // DMODEL/2

// --- packed fp16 global scratch ---------------------------------------------
// X split exactly into hi+lo fp16 pairs (protects proj); W single fp16.
// Q/K/V all stored as single fp16 pairs.
__device__ uint32_t g_xh[2*BSROWS*KPD],  g_xl[2*BSROWS*KPD];     // from(0)+to(1), [m][k/2]
__device__ uint32_t g_w[3*DMODEL*KPD];                           // [z][n][k/2] single fp16
__device__ uint32_t g_q[BATCH*NHEADS*SEQ*HP];                    // [bh][s][h/2]
__device__ uint32_t g_k[BATCH*NHEADS*SEQ*HP];
__device__ uint32_t g_v[BATCH*NHEADS*SEQ*HP];
__device__ unsigned char g_mflag[BATCH*16*32];   // [b][f-tile(128)][t-chunk(64)]

// ---------------------------------------------------------------------------
__device__ __forceinline__ void split_pair_h(float x, float y, uint32_t& hi, uint32_t& lo)
{
    __half xh = __float2half_rn(x);
    __half yh = __float2half_rn(y);
    __half xl = __float2half_rn(x - __half2float(xh));
    __half yl = __float2half_rn(y - __half2float(yh));
    __half2 h2 = __halves2half2(xh, yh);
    __half2 l2 = __halves2half2(xl, yl);
    hi = *reinterpret_cast<uint32_t*>(&h2);
    lo = *reinterpret_cast<uint32_t*>(&l2);
}

__device__ __forceinline__ uint32_t round_pair_h(float x, float y)
{
    __half2 h2 = __halves2half2(__float2half_rn(x), __float2half_rn(y));
    return *reinterpret_cast<uint32_t*>(&h2);
}

// fp16 inputs, fp32 accumulate. Non-volatile: ptxas may schedule.
__device__ __forceinline__ void mma_f16(float* d,
    uint32_t a0, uint32_t a1, uint32_t a2, uint32_t a3,
    uint32_t b0, uint32_t b1)
{
    asm("mma.sync.aligned.m16n8k16.row.col.f32.f16.f16.f32 "
        "{%0,%1,%2,%3}, {%4,%5,%6,%7}, {%8,%9}, {%0,%1,%2,%3};\n"
        : "+f"(d[0]), "+f"(d[1]), "+f"(d[2]), "+f"(d[3])
        : "r"(a0), "r"(a1), "r"(a2), "r"(a3), "r"(b0), "r"(b1));
}

__device__ __forceinline__ void ldsm_x4(uint32_t& r0, uint32_t& r1,
                                        uint32_t& r2, uint32_t& r3, uint32_t addr)
{
    asm volatile("ldmatrix.sync.aligned.m8n8.x4.shared.b16 {%0,%1,%2,%3}, [%4];\n"
        : "=r"(r0), "=r"(r1), "=r"(r2), "=r"(r3) : "r"(addr));
}

__device__ __forceinline__ void ldsm_x4_trans(uint32_t& r0, uint32_t& r1,
                                              uint32_t& r2, uint32_t& r3, uint32_t addr)
{
    asm volatile("ldmatrix.sync.aligned.m8n8.x4.trans.shared.b16 {%0,%1,%2,%3}, [%4];\n"
        : "=r"(r0), "=r"(r1), "=r"(r2), "=r"(r3) : "r"(addr));
}

// ---- cp.async helpers ------------------------------------------------------
__device__ __forceinline__ void cp16(uint32_t dst_smem, const void* src)
{
    asm volatile("cp.async.cg.shared.global [%0], [%1], 16;"
                 :: "r"(dst_smem), "l"(src));
}
__device__ __forceinline__ void cp_commit()
{
    asm volatile("cp.async.commit_group;" ::: "memory");
}
__device__ __forceinline__ void cp_wait1()
{
    asm volatile("cp.async.wait_group 1;" ::: "memory");
}

// ---------------------------------------------------------------------------
// Prep 1: split X into fp16 hi/lo pairs
// ---------------------------------------------------------------------------
__global__ __launch_bounds__(256) void pack_x_kernel(
    const float* __restrict__ from_t, const float* __restrict__ to_t)
{
    int r = blockIdx.x;
    int c4 = threadIdx.x;
    const float* src = (r < BSROWS) ? (from_t + r*DMODEL)
                                    : (to_t + (r - BSROWS)*DMODEL);
    float4 f = *(const float4*)&src[c4*4];
    uint32_t h0,l0,h1,l1;
    split_pair_h(f.x, f.y, h0, l0);
    split_pair_h(f.z, f.w, h1, l1);
    *(uint2*)&g_xh[r*KPD + c4*2] = make_uint2(h0, h1);
    *(uint2*)&g_xl[r*KPD + c4*2] = make_uint2(l0, l1);
}

// ---------------------------------------------------------------------------
// Prep 2: pack W into transposed [z][n][k/2] single-fp16 layout
// ---------------------------------------------------------------------------
__global__ __launch_bounds__(256) void pack_w_kernel(
    const float* __restrict__ Wq, const float* __restrict__ Wk,
    const float* __restrict__ Wv)
{
    __shared__ float T[64][65];
    const int z  = blockIdx.z;
    const int kt = blockIdx.y * 64;
    const int nt = blockIdx.x * 64;
    const float* W = (z == 0) ? Wq : (z == 1 ? Wk : Wv);

    #pragma unroll
    for (int p = 0; p < 4; p++) {
        int idx = threadIdx.x + p*256;
        int kr = idx >> 4;
        int c4 = (idx & 15) * 4;
        float4 v = *(const float4*)&W[(kt+kr)*DMODEL + nt + c4];
        T[kr][c4+0] = v.x; T[kr][c4+1] = v.y;
        T[kr][c4+2] = v.z; T[kr][c4+3] = v.w;
    }
    __syncthreads();

    const int kt2 = kt >> 1;
    #pragma unroll
    for (int p = 0; p < 8; p++) {
        int o = threadIdx.x + p*256;
        int n  = o >> 5;
        int kp = o & 31;
        int gidx = (z*DMODEL + nt + n)*KPD + kt2 + kp;
        g_w[gidx] = round_pair_h(T[2*kp][n], T[2*kp+1][n]);
    }
}

// ---------------------------------------------------------------------------
// Prep 3: per-(b, 128f-tile, 64t-chunk) all-ones mask flags
// ---------------------------------------------------------------------------
__global__ __launch_bounds__(256) void mask_flags_kernel(const int* __restrict__ mask)
{
    int b  = blockIdx.z;
    int f  = blockIdx.y*128 + (threadIdx.x >> 1);
    int tc = blockIdx.x*64  + (threadIdx.x & 1)*32;
    const int4* p = (const int4*)&mask[(b*SEQ + f)*SEQ + tc];
    int ok = 1;
    #pragma unroll
    for (int i = 0; i < 8; i++) {
        int4 v = p[i];
        ok &= (v.x == 1) & (v.y == 1) & (v.z == 1) & (v.w == 1);
    }
    ok = __syncthreads_and(ok);
    if (threadIdx.x == 0)
        g_mflag[(b*16 + blockIdx.y)*32 + blockIdx.x] = (unsigned char)ok;
}

// ---------------------------------------------------------------------------
// Kernel: QKV projection GEMM, fp16x2 (X split, W single), 3-stage cp.async.
// Block 128m x 64n, 8 warps (4m x 2n), warp 32x32, K-step 32.
// ---------------------------------------------------------------------------
#define PSTG 6400
#define PA_L 2560
#define PB_H 5120

__global__ __launch_bounds__(256, 2) void qkv_proj_kernel(
    const float* __restrict__ bq, const float* __restrict__ bk,
    const float* __restrict__ bv)
{
    extern __shared__ uint32_t dsm[];

    const int z = blockIdx.z;
    const uint32_t* Xh = g_xh + (z == 0 ? 0 : BSROWS*KPD);
    const uint32_t* Xl = g_xl + (z == 0 ? 0 : BSROWS*KPD);
    const uint32_t* Wp = g_w + z*DMODEL*KPD;
    const float* bias  = (z == 0) ? bq : (z == 1 ? bk : bv);
    uint32_t* dst      = (z == 0) ? g_q : (z == 1 ? g_k : g_v);

    const int m0 = blockIdx.y * 128;
    const int n0 = blockIdx.x * 64;
    const int tid  = threadIdx.x;
    const int wid  = tid >> 5;
    const int lane = tid & 31;
    const int g  = lane >> 2;
    const int tg = lane & 3;
    const int wm = (wid >> 1) * 32;
    const int wn = (wid & 1) * 32;

    const int ar = tid >> 2;          // row 0..63 (A also +64)
    const int aq = (tid & 3) * 4;     // uint4 col within 16 k-pairs

    const int koffA = (lane & 15)*20 + (lane >> 4)*4;
    const uint32_t sBase = (uint32_t)__cvta_generic_to_shared(dsm);

    auto prefetch = [&](int stage, int kq) {
        uint32_t sb = sBase + (uint32_t)(stage * PSTG) * 4u;
        cp16(sb + (ar*20 + aq)*4u,             &Xh[(m0+ar)*KPD + kq + aq]);
        cp16(sb + ((ar+64)*20 + aq)*4u,        &Xh[(m0+ar+64)*KPD + kq + aq]);
        cp16(sb + (PA_L + ar*20 + aq)*4u,      &Xl[(m0+ar)*KPD + kq + aq]);
        cp16(sb + (PA_L + (ar+64)*20 + aq)*4u, &Xl[(m0+ar+64)*KPD + kq + aq]);
        cp16(sb + (PB_H + ar*20 + aq)*4u,      &Wp[(n0+ar)*KPD + kq + aq]);
    };

    float acc[2][4][4] = {};

    prefetch(0, 0);
    cp_commit();

    for (int it = 0; it < 32; it++) {
        if (it + 1 < 32) prefetch((it + 1) % 3, (it + 1) * 16);
        cp_commit();
        cp_wait1();
        __syncthreads();

        const uint32_t aB = sBase + (uint32_t)((it % 3) * PSTG) * 4u;
        #pragma unroll
        for (int ks = 0; ks < 2; ks++) {
            int kb = ks * 8;
            uint32_t ah[2][4], al[2][4], bh[2][4];
            #pragma unroll
            for (int mi = 0; mi < 2; mi++) {
                uint32_t off = (uint32_t)((wm + mi*16)*20 + kb + koffA) * 4u;
                ldsm_x4(ah[mi][0], ah[mi][1], ah[mi][2], ah[mi][3], aB + off);
                ldsm_x4(al[mi][0], al[mi][1], al[mi][2], al[mi][3], aB + PA_L*4u + off);
            }
            #pragma unroll
            for (int nip = 0; nip < 2; nip++) {
                uint32_t off = (uint32_t)((wn + nip*16)*20 + kb + koffA) * 4u;
                ldsm_x4(bh[nip][0], bh[nip][1], bh[nip][2], bh[nip][3], aB + PB_H*4u + off);
            }
            #pragma unroll
            for (int t = 0; t < 2; t++) {
                #pragma unroll
                for (int nip = 0; nip < 2; nip++) {
                    #pragma unroll
                    for (int j = 0; j < 2; j++) {
                        int ni = nip*2 + j;
                        #pragma unroll
                        for (int mi = 0; mi < 2; mi++) {
                            if (t == 0)
                                mma_f16(acc[mi][ni], ah[mi][0],ah[mi][1],ah[mi][2],ah[mi][3],
                                        bh[nip][j], bh[nip][2+j]);
                            else
                                mma_f16(acc[mi][ni], al[mi][0],al[mi][1],al[mi][2],al[mi][3],
                                        bh[nip][j], bh[nip][2+j]);
                        }
                    }
                }
            }
        }
    }

    __syncthreads();
    // --- epilogue: bias, round to single fp16 pairs, write scratch ---
    const int head = n0 >> 6;
    #pragma unroll
    for (int ni = 0; ni < 4; ni++) {
        int h = wn + ni*8 + 2*tg;
        int hp = h >> 1;
        float2 b2 = *(const float2*)&bias[n0 + h];
        #pragma unroll
        for (int mi = 0; mi < 2; mi++) {
            int r0 = m0 + wm + mi*16 + g;
            int r1 = r0 + 8;
            int b0i = r0 >> 11, s0 = r0 & (SEQ-1);
            int b1i = r1 >> 11, s1 = r1 & (SEQ-1);
            size_t i0 = ((size_t)(b0i*NHEADS + head)*SEQ + s0)*HP + hp;
            size_t i1 = ((size_t)(b1i*NHEADS + head)*SEQ + s1)*HP + hp;
            dst[i0] = round_pair_h(acc[mi][ni][0] + b2.x, acc[mi][ni][1] + b2.y);
            dst[i1] = round_pair_h(acc[mi][ni][2] + b2.x, acc[mi][ni][3] + b2.y);
        }
    }
}

// ---------------------------------------------------------------------------
// Kernel: flash attention, pure fp16 tensor cores (Q/K/V/P all single fp16,
// fp32 accumulate), 3-stage cp.async. Stage: K 64x36 | V 64x36 = 4608 u32.
// ---------------------------------------------------------------------------
#define ASTG 4608
#define A_VH 2304

__global__ __launch_bounds__(256, 2) void attn_kernel(
    const int* __restrict__ mask, float* __restrict__ out)
{
    extern __shared__ uint32_t asm_dsm[];

    const int f0   = blockIdx.x * 128;
    const int head = blockIdx.y;
    const int b    = blockIdx.z;
    const int bh   = b*NHEADS + head;
    const int tid  = threadIdx.x;
    const int lane = tid & 31;
    const int g  = lane >> 2;
    const int tg = lane & 3;
    const int fb = (tid >> 5) * 16;

    const int frow0 = f0 + fb + g;
    const int frow1 = frow0 + 8;

    const int koffK = ((((lane>>4)&1)*8 + (lane&7))*36 + ((lane>>3)&1)*4);
    const int koffV = ((((lane>>3)&1)*8 + (lane&7))*36 + ((lane>>4)&1)*4);

    const uint32_t sBase = (uint32_t)__cvta_generic_to_shared(asm_dsm);

    // --- preload Q fragments (single fp16) ---
    uint32_t qh[4][4];
    {
        const uint32_t* qp = g_q + bh*SEQ*HP;
        int q0 = frow0*HP, q1 = frow1*HP;
        #pragma unroll
        for (int ks = 0; ks < 4; ks++) {
            int kb = ks*8 + tg;
            qh[ks][0] = qp[q0 + kb];   qh[ks][1] = qp[q1 + kb];
            qh[ks][2] = qp[q0 + kb+4]; qh[ks][3] = qp[q1 + kb+4];
        }
    }

    const uint32_t* kb_g = g_k + bh*SEQ*HP;
    const uint32_t* vb_g = g_v + bh*SEQ*HP;
    const unsigned char* mfl = &g_mflag[(b*16 + blockIdx.x)*32];

    float m0 = -1e30f, m1 = -1e30f;
    float l0s = 0.0f, l1s = 0.0f;
    float O[8][4] = {};

    const int cr  = tid >> 3;        // 0..31 -> rows cr, cr+32
    const int cc4 = (tid & 7) * 4;

    auto prefetch = [&](int stage, int t0) {
        uint32_t sb = sBase + (uint32_t)(stage * ASTG) * 4u;
        cp16(sb + (cr*36 + cc4)*4u,               &kb_g[(t0+cr)*HP + cc4]);
        cp16(sb + ((cr+32)*36 + cc4)*4u,          &kb_g[(t0+cr+32)*HP + cc4]);
        cp16(sb + (A_VH + cr*36 + cc4)*4u,        &vb_g[(t0+cr)*HP + cc4]);
        cp16(sb + (A_VH + (cr+32)*36 + cc4)*4u,   &vb_g[(t0+cr+32)*HP + cc4]);
    };

    prefetch(0, 0);
    cp_commit();

    for (int it = 0; it < SEQ/64; it++) {
        const int t0 = it * 64;
        if (it + 1 < SEQ/64) prefetch((it + 1) % 3, t0 + 64);
        cp_commit();
        cp_wait1();
        __syncthreads();

        const uint32_t sb = sBase + (uint32_t)((it % 3) * ASTG) * 4u;
        const uint32_t khB = sb;
        const uint32_t vhB = sb + A_VH*4u;

        // --- S = Q K^T (single term) ---
        float s[8][4] = {};
        #pragma unroll
        for (int ks = 0; ks < 4; ks++) {
            int kb = ks * 8;
            #pragma unroll
            for (int ntp = 0; ntp < 4; ntp++) {
                uint32_t off = (uint32_t)(ntp*16*36 + koffK + kb) * 4u;
                uint32_t k0,k1,k2,k3;
                ldsm_x4(k0,k1,k2,k3, khB + off);
                mma_f16(s[2*ntp],   qh[ks][0],qh[ks][1],qh[ks][2],qh[ks][3], k0, k1);
                mma_f16(s[2*ntp+1], qh[ks][0],qh[ks][1],qh[ks][2],qh[ks][3], k2, k3);
            }
        }

        // --- scale + mask (skippable) + chunk row max ---
        float rmax0 = -1e30f, rmax1 = -1e30f;
        if (mfl[it]) {
            #pragma unroll
            for (int nt = 0; nt < 8; nt++) {
                s[nt][0] *= 0.125f; s[nt][1] *= 0.125f;
                s[nt][2] *= 0.125f; s[nt][3] *= 0.125f;
                rmax0 = fmaxf(rmax0, fmaxf(s[nt][0], s[nt][1]));
                rmax1 = fmaxf(rmax1, fmaxf(s[nt][2], s[nt][3]));
            }
        } else {
            #pragma unroll
            for (int nt = 0; nt < 8; nt++) {
                int tc = t0 + nt*8 + 2*tg;
                int2 mk0 = *(const int2*)&mask[(b*SEQ + frow0)*SEQ + tc];
                int2 mk1 = *(const int2*)&mask[(b*SEQ + frow1)*SEQ + tc];
                s[nt][0] = s[nt][0]*0.125f + (1.0f - (float)mk0.x) * -10000.0f;
                s[nt][1] = s[nt][1]*0.125f + (1.0f - (float)mk0.y) * -10000.0f;
                s[nt][2] = s[nt][2]*0.125f + (1.0f - (float)mk1.x) * -10000.0f;
                s[nt][3] = s[nt][3]*0.125f + (1.0f - (float)mk1.y) * -10000.0f;
                rmax0 = fmaxf(rmax0, fmaxf(s[nt][0], s[nt][1]));
                rmax1 = fmaxf(rmax1, fmaxf(s[nt][2], s[nt][3]));
            }
        }
        rmax0 = fmaxf(rmax0, __shfl_xor_sync(0xffffffffu, rmax0, 1));
        rmax0 = fmaxf(rmax0, __shfl_xor_sync(0xffffffffu, rmax0, 2));
        rmax1 = fmaxf(rmax1, __shfl_xor_sync(0xffffffffu, rmax1, 1));
        rmax1 = fmaxf(rmax1, __shfl_xor_sync(0xffffffffu, rmax1, 2));

        float mn0 = fmaxf(m0, rmax0), mn1 = fmaxf(m1, rmax1);
        float a0 = __expf(m0 - mn0),  a1 = __expf(m1 - mn1);
        m0 = mn0; m1 = mn1;

        // --- exp + round P fragments to single fp16 in registers ---
        uint32_t ph0[8], ph1[8];
        float ps0 = 0.0f, ps1 = 0.0f;
        #pragma unroll
        for (int nt = 0; nt < 8; nt++) {
            float p00 = __expf(s[nt][0] - mn0);
            float p01 = __expf(s[nt][1] - mn0);
            float p10 = __expf(s[nt][2] - mn1);
            float p11 = __expf(s[nt][3] - mn1);
            ps0 += p00 + p01;
            ps1 += p10 + p11;
            ph0[nt] = round_pair_h(p00, p01);
            ph1[nt] = round_pair_h(p10, p11);
        }
        ps0 += __shfl_xor_sync(0xffffffffu, ps0, 1);
        ps0 += __shfl_xor_sync(0xffffffffu, ps0, 2);
        ps1 += __shfl_xor_sync(0xffffffffu, ps1, 1);
        ps1 += __shfl_xor_sync(0xffffffffu, ps1, 2);
        l0s = l0s * a0 + ps0;
        l1s = l1s * a1 + ps1;

        #pragma unroll
        for (int ht = 0; ht < 8; ht++) {
            O[ht][0] *= a0; O[ht][1] *= a0;
            O[ht][2] *= a1; O[ht][3] *= a1;
        }

        // --- O += P V (single term) ---
        #pragma unroll
        for (int ks = 0; ks < 4; ks++) {
            uint32_t ah0 = ph0[2*ks],   ah1 = ph1[2*ks];
            uint32_t ah2 = ph0[2*ks+1], ah3 = ph1[2*ks+1];
            #pragma unroll
            for (int htp = 0; htp < 4; htp++) {
                uint32_t off = (uint32_t)(ks*16*36 + htp*8 + koffV) * 4u;
                uint32_t v0,v1,v2,v3;
                ldsm_x4_trans(v0,v1,v2,v3, vhB + off);
                mma_f16(O[2*htp],   ah0,ah1,ah2,ah3, v0, v1);
                mma_f16(O[2*htp+1], ah0,ah1,ah2,ah3, v2, v3);
            }
        }
    }

    float inv0 = 1.0f / l0s;
    float inv1 = 1.0f / l1s;
    #pragma unroll
    for (int ht = 0; ht < 8; ht++) {
        int h = ht*8 + 2*tg;
        float2 r0 = make_float2(O[ht][0]*inv0, O[ht][1]*inv0);
        float2 r1 = make_float2(O[ht][2]*inv1, O[ht][3]*inv1);
        *(float2*)&out[(b*SEQ + frow0)*DMODEL + head*HDIM + h] = r0;
        *(float2*)&out[(b*SEQ + frow1)*DMODEL + head*HDIM + h] = r1;
    }
}

// ---------------------------------------------------------------------------
extern "C" void kernel_launch(void* const* d_in, const int* in_sizes, int n_in,
                              void* d_out, int out_size)
{
    const float* from_t = (const float*)d_in[0];
    const float* to_t   = (const float*)d_in[1];
    const int*   mask   = (const int*)  d_in[2];
    const float* Wq = (const float*)d_in[3];
    const float* bq = (const float*)d_in[4];
    const float* Wk = (const float*)d_in[5];
    const float* bk = (const float*)d_in[6];
    const float* Wv = (const float*)d_in[7];
    const float* bv = (const float*)d_in[8];
    float* out = (float*)d_out;

    pack_x_kernel<<<2*BSROWS, 256>>>(from_t, to_t);
    pack_w_kernel<<<dim3(16, 16, 3), 256>>>(Wq, Wk, Wv);
    mask_flags_kernel<<<dim3(32, 16, BATCH), 256>>>(mask);

    const int proj_smem = 3 * PSTG * 4;   // 76800 B
    cudaFuncSetAttribute(qkv_proj_kernel,
                         cudaFuncAttributeMaxDynamicSharedMemorySize, proj_smem);
    dim3 pgrid(DMODEL/64, BSROWS/128, 3);
    qkv_proj_kernel<<<pgrid, 256, proj_smem>>>(bq, bk, bv);

    const int attn_smem = 3 * ASTG * 4;   // 55296 B
    cudaFuncSetAttribute(attn_kernel,
                         cudaFuncAttributeMaxDynamicSharedMemorySize, attn_smem);
    dim3 agrid(SEQ/128, NHEADS, BATCH);
    attn_kernel<<<agrid, 256, attn_smem>>>(mask, out);
}

// round 12
// speedup vs baseline: 6.9979x; 1.3274x over previous
#include <cuda_runtime.h>
#include <cuda_fp16.h>
#include <cstdint>

#define NHEADS 16
#define HDIM   64
#define DMODEL 1024
#define BATCH  2
#define SEQ    2048
#define BSROWS 4096          // BATCH*SEQ
#define HP     32            // HDIM/2  (fp16 pairs per head row)
#define KPD    512           // DMODEL/2

// --- packed fp16 global scratch ---------------------------------------------
// Everything single fp16 (fp32 accumulate in all GEMMs).
__device__ uint32_t g_x[2*BSROWS*KPD];                           // from(0)+to(1), [m][k/2]
__device__ uint32_t g_w[3*DMODEL*KPD];                           // [z][n][k/2]
__device__ uint32_t g_q[BATCH*NHEADS*SEQ*HP];                    // [bh][s][h/2]
__device__ uint32_t g_k[BATCH*NHEADS*SEQ*HP];
__device__ uint32_t g_v[BATCH*NHEADS*SEQ*HP];
__device__ unsigned char g_mflag[BATCH*16*32];   // [b][f-tile(128)][t-chunk(64)]

// ---------------------------------------------------------------------------
__device__ __forceinline__ uint32_t round_pair_h(float x, float y)
{
    __half2 h2 = __halves2half2(__float2half_rn(x), __float2half_rn(y));
    return *reinterpret_cast<uint32_t*>(&h2);
}

// fp16 inputs, fp32 accumulate. Non-volatile: ptxas may schedule.
__device__ __forceinline__ void mma_f16(float* d,
    uint32_t a0, uint32_t a1, uint32_t a2, uint32_t a3,
    uint32_t b0, uint32_t b1)
{
    asm("mma.sync.aligned.m16n8k16.row.col.f32.f16.f16.f32 "
        "{%0,%1,%2,%3}, {%4,%5,%6,%7}, {%8,%9}, {%0,%1,%2,%3};\n"
        : "+f"(d[0]), "+f"(d[1]), "+f"(d[2]), "+f"(d[3])
        : "r"(a0), "r"(a1), "r"(a2), "r"(a3), "r"(b0), "r"(b1));
}

__device__ __forceinline__ void ldsm_x4(uint32_t& r0, uint32_t& r1,
                                        uint32_t& r2, uint32_t& r3, uint32_t addr)
{
    asm volatile("ldmatrix.sync.aligned.m8n8.x4.shared.b16 {%0,%1,%2,%3}, [%4];\n"
        : "=r"(r0), "=r"(r1), "=r"(r2), "=r"(r3) : "r"(addr));
}

__device__ __forceinline__ void ldsm_x4_trans(uint32_t& r0, uint32_t& r1,
                                              uint32_t& r2, uint32_t& r3, uint32_t addr)
{
    asm volatile("ldmatrix.sync.aligned.m8n8.x4.trans.shared.b16 {%0,%1,%2,%3}, [%4];\n"
        : "=r"(r0), "=r"(r1), "=r"(r2), "=r"(r3) : "r"(addr));
}

// ---- cp.async helpers ------------------------------------------------------
__device__ __forceinline__ void cp16(uint32_t dst_smem, const void* src)
{
    asm volatile("cp.async.cg.shared.global [%0], [%1], 16;"
                 :: "r"(dst_smem), "l"(src));
}
__device__ __forceinline__ void cp_commit()
{
    asm volatile("cp.async.commit_group;" ::: "memory");
}
__device__ __forceinline__ void cp_wait1()
{
    asm volatile("cp.async.wait_group 1;" ::: "memory");
}

// ---------------------------------------------------------------------------
// Prep 1: round X to fp16 pairs
// ---------------------------------------------------------------------------
__global__ __launch_bounds__(256) void pack_x_kernel(
    const float* __restrict__ from_t, const float* __restrict__ to_t)
{
    int r = blockIdx.x;
    int c4 = threadIdx.x;
    const float* src = (r < BSROWS) ? (from_t + r*DMODEL)
                                    : (to_t + (r - BSROWS)*DMODEL);
    float4 f = *(const float4*)&src[c4*4];
    *(uint2*)&g_x[r*KPD + c4*2] =
        make_uint2(round_pair_h(f.x, f.y), round_pair_h(f.z, f.w));
}

// ---------------------------------------------------------------------------
// Prep 2: pack W into transposed [z][n][k/2] fp16 layout
// ---------------------------------------------------------------------------
__global__ __launch_bounds__(256) void pack_w_kernel(
    const float* __restrict__ Wq, const float* __restrict__ Wk,
    const float* __restrict__ Wv)
{
    __shared__ float T[64][65];
    const int z  = blockIdx.z;
    const int kt = blockIdx.y * 64;
    const int nt = blockIdx.x * 64;
    const float* W = (z == 0) ? Wq : (z == 1 ? Wk : Wv);

    #pragma unroll
    for (int p = 0; p < 4; p++) {
        int idx = threadIdx.x + p*256;
        int kr = idx >> 4;
        int c4 = (idx & 15) * 4;
        float4 v = *(const float4*)&W[(kt+kr)*DMODEL + nt + c4];
        T[kr][c4+0] = v.x; T[kr][c4+1] = v.y;
        T[kr][c4+2] = v.z; T[kr][c4+3] = v.w;
    }
    __syncthreads();

    const int kt2 = kt >> 1;
    #pragma unroll
    for (int p = 0; p < 8; p++) {
        int o = threadIdx.x + p*256;
        int n  = o >> 5;
        int kp = o & 31;
        int gidx = (z*DMODEL + nt + n)*KPD + kt2 + kp;
        g_w[gidx] = round_pair_h(T[2*kp][n], T[2*kp+1][n]);
    }
}

// ---------------------------------------------------------------------------
// Prep 3: per-(b, 128f-tile, 64t-chunk) all-ones mask flags
// ---------------------------------------------------------------------------
__global__ __launch_bounds__(256) void mask_flags_kernel(const int* __restrict__ mask)
{
    int b  = blockIdx.z;
    int f  = blockIdx.y*128 + (threadIdx.x >> 1);
    int tc = blockIdx.x*64  + (threadIdx.x & 1)*32;
    const int4* p = (const int4*)&mask[(b*SEQ + f)*SEQ + tc];
    int ok = 1;
    #pragma unroll
    for (int i = 0; i < 8; i++) {
        int4 v = p[i];
        ok &= (v.x == 1) & (v.y == 1) & (v.z == 1) & (v.w == 1);
    }
    ok = __syncthreads_and(ok);
    if (threadIdx.x == 0)
        g_mflag[(b*16 + blockIdx.y)*32 + blockIdx.x] = (unsigned char)ok;
}

// ---------------------------------------------------------------------------
// Kernel: QKV projection GEMM, pure fp16 (fp32 accum), 3-stage cp.async.
// Block 128m x 64n, 8 warps (4m x 2n), warp 32x32, K-step 32.
// Stage: X 128x20 | W 64x20 = 3840 u32.
// ---------------------------------------------------------------------------
#define PSTG 3840
#define PB_H 2560

__global__ __launch_bounds__(256, 2) void qkv_proj_kernel(
    const float* __restrict__ bq, const float* __restrict__ bk,
    const float* __restrict__ bv)
{
    extern __shared__ uint32_t dsm[];

    const int z = blockIdx.z;
    const uint32_t* Xp = g_x + (z == 0 ? 0 : BSROWS*KPD);
    const uint32_t* Wp = g_w + z*DMODEL*KPD;
    const float* bias  = (z == 0) ? bq : (z == 1 ? bk : bv);
    uint32_t* dst      = (z == 0) ? g_q : (z == 1 ? g_k : g_v);

    const int m0 = blockIdx.y * 128;
    const int n0 = blockIdx.x * 64;
    const int tid  = threadIdx.x;
    const int wid  = tid >> 5;
    const int lane = tid & 31;
    const int g  = lane >> 2;
    const int tg = lane & 3;
    const int wm = (wid >> 1) * 32;
    const int wn = (wid & 1) * 32;

    const int ar = tid >> 2;          // row 0..63 (A also +64)
    const int aq = (tid & 3) * 4;     // uint4 col within 16 k-pairs

    const int koffA = (lane & 15)*20 + (lane >> 4)*4;
    const uint32_t sBase = (uint32_t)__cvta_generic_to_shared(dsm);

    auto prefetch = [&](int stage, int kq) {
        uint32_t sb = sBase + (uint32_t)(stage * PSTG) * 4u;
        cp16(sb + (ar*20 + aq)*4u,        &Xp[(m0+ar)*KPD + kq + aq]);
        cp16(sb + ((ar+64)*20 + aq)*4u,   &Xp[(m0+ar+64)*KPD + kq + aq]);
        cp16(sb + (PB_H + ar*20 + aq)*4u, &Wp[(n0+ar)*KPD + kq + aq]);
    };

    float acc[2][4][4] = {};

    prefetch(0, 0);
    cp_commit();

    for (int it = 0; it < 32; it++) {
        if (it + 1 < 32) prefetch((it + 1) % 3, (it + 1) * 16);
        cp_commit();
        cp_wait1();
        __syncthreads();

        const uint32_t aB = sBase + (uint32_t)((it % 3) * PSTG) * 4u;
        #pragma unroll
        for (int ks = 0; ks < 2; ks++) {
            int kb = ks * 8;
            uint32_t ah[2][4], bh[2][4];
            #pragma unroll
            for (int mi = 0; mi < 2; mi++) {
                uint32_t off = (uint32_t)((wm + mi*16)*20 + kb + koffA) * 4u;
                ldsm_x4(ah[mi][0], ah[mi][1], ah[mi][2], ah[mi][3], aB + off);
            }
            #pragma unroll
            for (int nip = 0; nip < 2; nip++) {
                uint32_t off = (uint32_t)((wn + nip*16)*20 + kb + koffA) * 4u;
                ldsm_x4(bh[nip][0], bh[nip][1], bh[nip][2], bh[nip][3], aB + PB_H*4u + off);
            }
            #pragma unroll
            for (int nip = 0; nip < 2; nip++) {
                #pragma unroll
                for (int j = 0; j < 2; j++) {
                    int ni = nip*2 + j;
                    #pragma unroll
                    for (int mi = 0; mi < 2; mi++) {
                        mma_f16(acc[mi][ni], ah[mi][0],ah[mi][1],ah[mi][2],ah[mi][3],
                                bh[nip][j], bh[nip][2+j]);
                    }
                }
            }
        }
    }

    __syncthreads();
    // --- epilogue: bias, round to fp16 pairs, write scratch [bh][s][h/2] ---
    const int head = n0 >> 6;
    #pragma unroll
    for (int ni = 0; ni < 4; ni++) {
        int h = wn + ni*8 + 2*tg;
        int hp = h >> 1;
        float2 b2 = *(const float2*)&bias[n0 + h];
        #pragma unroll
        for (int mi = 0; mi < 2; mi++) {
            int r0 = m0 + wm + mi*16 + g;
            int r1 = r0 + 8;
            int b0i = r0 >> 11, s0 = r0 & (SEQ-1);
            int b1i = r1 >> 11, s1 = r1 & (SEQ-1);
            size_t i0 = ((size_t)(b0i*NHEADS + head)*SEQ + s0)*HP + hp;
            size_t i1 = ((size_t)(b1i*NHEADS + head)*SEQ + s1)*HP + hp;
            dst[i0] = round_pair_h(acc[mi][ni][0] + b2.x, acc[mi][ni][1] + b2.y);
            dst[i1] = round_pair_h(acc[mi][ni][2] + b2.x, acc[mi][ni][3] + b2.y);
        }
    }
}

// ---------------------------------------------------------------------------
// Kernel: flash attention, pure fp16 tensor cores (fp32 accumulate),
// 3-stage cp.async. Stage: K 64x36 | V 64x36 = 4608 u32.
// ---------------------------------------------------------------------------
#define ASTG 4608
#define A_VH 2304

__global__ __launch_bounds__(256, 2) void attn_kernel(
    const int* __restrict__ mask, float* __restrict__ out)
{
    extern __shared__ uint32_t asm_dsm[];

    const int f0   = blockIdx.x * 128;
    const int head = blockIdx.y;
    const int b    = blockIdx.z;
    const int bh   = b*NHEADS + head;
    const int tid  = threadIdx.x;
    const int lane = tid & 31;
    const int g  = lane >> 2;
    const int tg = lane & 3;
    const int fb = (tid >> 5) * 16;

    const int frow0 = f0 + fb + g;
    const int frow1 = frow0 + 8;

    const int koffK = ((((lane>>4)&1)*8 + (lane&7))*36 + ((lane>>3)&1)*4);
    const int koffV = ((((lane>>3)&1)*8 + (lane&7))*36 + ((lane>>4)&1)*4);

    const uint32_t sBase = (uint32_t)__cvta_generic_to_shared(asm_dsm);

    // --- preload Q fragments ---
    uint32_t qh[4][4];
    {
        const uint32_t* qp = g_q + bh*SEQ*HP;
        int q0 = frow0*HP, q1 = frow1*HP;
        #pragma unroll
        for (int ks = 0; ks < 4; ks++) {
            int kb = ks*8 + tg;
            qh[ks][0] = qp[q0 + kb];   qh[ks][1] = qp[q1 + kb];
            qh[ks][2] = qp[q0 + kb+4]; qh[ks][3] = qp[q1 + kb+4];
        }
    }

    const uint32_t* kb_g = g_k + bh*SEQ*HP;
    const uint32_t* vb_g = g_v + bh*SEQ*HP;
    const unsigned char* mfl = &g_mflag[(b*16 + blockIdx.x)*32];

    float m0 = -1e30f, m1 = -1e30f;
    float l0s = 0.0f, l1s = 0.0f;
    float O[8][4] = {};

    const int cr  = tid >> 3;        // 0..31 -> rows cr, cr+32
    const int cc4 = (tid & 7) * 4;

    auto prefetch = [&](int stage, int t0) {
        uint32_t sb = sBase + (uint32_t)(stage * ASTG) * 4u;
        cp16(sb + (cr*36 + cc4)*4u,               &kb_g[(t0+cr)*HP + cc4]);
        cp16(sb + ((cr+32)*36 + cc4)*4u,          &kb_g[(t0+cr+32)*HP + cc4]);
        cp16(sb + (A_VH + cr*36 + cc4)*4u,        &vb_g[(t0+cr)*HP + cc4]);
        cp16(sb + (A_VH + (cr+32)*36 + cc4)*4u,   &vb_g[(t0+cr+32)*HP + cc4]);
    };

    prefetch(0, 0);
    cp_commit();

    for (int it = 0; it < SEQ/64; it++) {
        const int t0 = it * 64;
        if (it + 1 < SEQ/64) prefetch((it + 1) % 3, t0 + 64);
        cp_commit();
        cp_wait1();
        __syncthreads();

        const uint32_t sb = sBase + (uint32_t)((it % 3) * ASTG) * 4u;
        const uint32_t khB = sb;
        const uint32_t vhB = sb + A_VH*4u;

        // --- S = Q K^T ---
        float s[8][4] = {};
        #pragma unroll
        for (int ks = 0; ks < 4; ks++) {
            int kb = ks * 8;
            #pragma unroll
            for (int ntp = 0; ntp < 4; ntp++) {
                uint32_t off = (uint32_t)(ntp*16*36 + koffK + kb) * 4u;
                uint32_t k0,k1,k2,k3;
                ldsm_x4(k0,k1,k2,k3, khB + off);
                mma_f16(s[2*ntp],   qh[ks][0],qh[ks][1],qh[ks][2],qh[ks][3], k0, k1);
                mma_f16(s[2*ntp+1], qh[ks][0],qh[ks][1],qh[ks][2],qh[ks][3], k2, k3);
            }
        }

        // --- scale + mask (skippable) + chunk row max ---
        float rmax0 = -1e30f, rmax1 = -1e30f;
        if (mfl[it]) {
            #pragma unroll
            for (int nt = 0; nt < 8; nt++) {
                s[nt][0] *= 0.125f; s[nt][1] *= 0.125f;
                s[nt][2] *= 0.125f; s[nt][3] *= 0.125f;
                rmax0 = fmaxf(rmax0, fmaxf(s[nt][0], s[nt][1]));
                rmax1 = fmaxf(rmax1, fmaxf(s[nt][2], s[nt][3]));
            }
        } else {
            #pragma unroll
            for (int nt = 0; nt < 8; nt++) {
                int tc = t0 + nt*8 + 2*tg;
                int2 mk0 = *(const int2*)&mask[(b*SEQ + frow0)*SEQ + tc];
                int2 mk1 = *(const int2*)&mask[(b*SEQ + frow1)*SEQ + tc];
                s[nt][0] = s[nt][0]*0.125f + (1.0f - (float)mk0.x) * -10000.0f;
                s[nt][1] = s[nt][1]*0.125f + (1.0f - (float)mk0.y) * -10000.0f;
                s[nt][2] = s[nt][2]*0.125f + (1.0f - (float)mk1.x) * -10000.0f;
                s[nt][3] = s[nt][3]*0.125f + (1.0f - (float)mk1.y) * -10000.0f;
                rmax0 = fmaxf(rmax0, fmaxf(s[nt][0], s[nt][1]));
                rmax1 = fmaxf(rmax1, fmaxf(s[nt][2], s[nt][3]));
            }
        }
        rmax0 = fmaxf(rmax0, __shfl_xor_sync(0xffffffffu, rmax0, 1));
        rmax0 = fmaxf(rmax0, __shfl_xor_sync(0xffffffffu, rmax0, 2));
        rmax1 = fmaxf(rmax1, __shfl_xor_sync(0xffffffffu, rmax1, 1));
        rmax1 = fmaxf(rmax1, __shfl_xor_sync(0xffffffffu, rmax1, 2));

        float mn0 = fmaxf(m0, rmax0), mn1 = fmaxf(m1, rmax1);
        float a0 = __expf(m0 - mn0),  a1 = __expf(m1 - mn1);
        m0 = mn0; m1 = mn1;

        // --- exp + round P fragments to fp16 in registers ---
        uint32_t ph0[8], ph1[8];
        float ps0 = 0.0f, ps1 = 0.0f;
        #pragma unroll
        for (int nt = 0; nt < 8; nt++) {
            float p00 = __expf(s[nt][0] - mn0);
            float p01 = __expf(s[nt][1] - mn0);
            float p10 = __expf(s[nt][2] - mn1);
            float p11 = __expf(s[nt][3] - mn1);
            ps0 += p00 + p01;
            ps1 += p10 + p11;
            ph0[nt] = round_pair_h(p00, p01);
            ph1[nt] = round_pair_h(p10, p11);
        }
        ps0 += __shfl_xor_sync(0xffffffffu, ps0, 1);
        ps0 += __shfl_xor_sync(0xffffffffu, ps0, 2);
        ps1 += __shfl_xor_sync(0xffffffffu, ps1, 1);
        ps1 += __shfl_xor_sync(0xffffffffu, ps1, 2);
        l0s = l0s * a0 + ps0;
        l1s = l1s * a1 + ps1;

        #pragma unroll
        for (int ht = 0; ht < 8; ht++) {
            O[ht][0] *= a0; O[ht][1] *= a0;
            O[ht][2] *= a1; O[ht][3] *= a1;
        }

        // --- O += P V ---
        #pragma unroll
        for (int ks = 0; ks < 4; ks++) {
            uint32_t ah0 = ph0[2*ks],   ah1 = ph1[2*ks];
            uint32_t ah2 = ph0[2*ks+1], ah3 = ph1[2*ks+1];
            #pragma unroll
            for (int htp = 0; htp < 4; htp++) {
                uint32_t off = (uint32_t)(ks*16*36 + htp*8 + koffV) * 4u;
                uint32_t v0,v1,v2,v3;
                ldsm_x4_trans(v0,v1,v2,v3, vhB + off);
                mma_f16(O[2*htp],   ah0,ah1,ah2,ah3, v0, v1);
                mma_f16(O[2*htp+1], ah0,ah1,ah2,ah3, v2, v3);
            }
        }
    }

    float inv0 = 1.0f / l0s;
    float inv1 = 1.0f / l1s;
    #pragma unroll
    for (int ht = 0; ht < 8; ht++) {
        int h = ht*8 + 2*tg;
        float2 r0 = make_float2(O[ht][0]*inv0, O[ht][1]*inv0);
        float2 r1 = make_float2(O[ht][2]*inv1, O[ht][3]*inv1);
        *(float2*)&out[(b*SEQ + frow0)*DMODEL + head*HDIM + h] = r0;
        *(float2*)&out[(b*SEQ + frow1)*DMODEL + head*HDIM + h] = r1;
    }
}

// ---------------------------------------------------------------------------
extern "C" void kernel_launch(void* const* d_in, const int* in_sizes, int n_in,
                              void* d_out, int out_size)
{
    const float* from_t = (const float*)d_in[0];
    const float* to_t   = (const float*)d_in[1];
    const int*   mask   = (const int*)  d_in[2];
    const float* Wq = (const float*)d_in[3];
    const float* bq = (const float*)d_in[4];
    const float* Wk = (const float*)d_in[5];
    const float* bk = (const float*)d_in[6];
    const float* Wv = (const float*)d_in[7];
    const float* bv = (const float*)d_in[8];
    float* out = (float*)d_out;

    pack_x_kernel<<<2*BSROWS, 256>>>(from_t, to_t);
    pack_w_kernel<<<dim3(16, 16, 3), 256>>>(Wq, Wk, Wv);
    mask_flags_kernel<<<dim3(32, 16, BATCH), 256>>>(mask);

    const int proj_smem = 3 * PSTG * 4;   // 46080 B
    cudaFuncSetAttribute(qkv_proj_kernel,
                         cudaFuncAttributeMaxDynamicSharedMemorySize, proj_smem);
    dim3 pgrid(DMODEL/64, BSROWS/128, 3);
    qkv_proj_kernel<<<pgrid, 256, proj_smem>>>(bq, bk, bv);

    const int attn_smem = 3 * ASTG * 4;   // 55296 B
    cudaFuncSetAttribute(attn_kernel,
                         cudaFuncAttributeMaxDynamicSharedMemorySize, attn_smem);
    dim3 agrid(SEQ/128, NHEADS, BATCH);
    attn_kernel<<<agrid, 256, attn_smem>>>(mask, out);
}

// round 13
// speedup vs baseline: 7.1730x; 1.0250x over previous
#include <cuda_runtime.h>
#include <cuda_fp16.h>
#include <cstdint>

#define NHEADS 16
#define HDIM   64
#define DMODEL 1024
#define BATCH  2
#define SEQ    2048
#define BSROWS 4096          // BATCH*SEQ
#define HP     32            // HDIM/2  (fp16 pairs per head row)
#define KPD    512           // DMODEL/2

// --- packed fp16 global scratch ---------------------------------------------
__device__ uint32_t g_x[2*BSROWS*KPD];                           // from(0)+to(1), [m][k/2]
__device__ uint32_t g_w[3*DMODEL*KPD];                           // [z][n][k/2]
__device__ uint32_t g_q[BATCH*NHEADS*SEQ*HP];                    // [bh][s][h/2]
__device__ uint32_t g_k[BATCH*NHEADS*SEQ*HP];
__device__ uint32_t g_v[BATCH*NHEADS*SEQ*HP];
__device__ unsigned char g_mflag[BATCH*16*32];   // [b][f-tile(128)][t-chunk(64)]

// ---------------------------------------------------------------------------
__device__ __forceinline__ uint32_t round_pair_h(float x, float y)
{
    __half2 h2 = __halves2half2(__float2half_rn(x), __float2half_rn(y));
    return *reinterpret_cast<uint32_t*>(&h2);
}

__device__ __forceinline__ void mma_f16(float* d,
    uint32_t a0, uint32_t a1, uint32_t a2, uint32_t a3,
    uint32_t b0, uint32_t b1)
{
    asm("mma.sync.aligned.m16n8k16.row.col.f32.f16.f16.f32 "
        "{%0,%1,%2,%3}, {%4,%5,%6,%7}, {%8,%9}, {%0,%1,%2,%3};\n"
        : "+f"(d[0]), "+f"(d[1]), "+f"(d[2]), "+f"(d[3])
        : "r"(a0), "r"(a1), "r"(a2), "r"(a3), "r"(b0), "r"(b1));
}

__device__ __forceinline__ void ldsm_x4(uint32_t& r0, uint32_t& r1,
                                        uint32_t& r2, uint32_t& r3, uint32_t addr)
{
    asm volatile("ldmatrix.sync.aligned.m8n8.x4.shared.b16 {%0,%1,%2,%3}, [%4];\n"
        : "=r"(r0), "=r"(r1), "=r"(r2), "=r"(r3) : "r"(addr));
}

__device__ __forceinline__ void ldsm_x4_trans(uint32_t& r0, uint32_t& r1,
                                              uint32_t& r2, uint32_t& r3, uint32_t addr)
{
    asm volatile("ldmatrix.sync.aligned.m8n8.x4.trans.shared.b16 {%0,%1,%2,%3}, [%4];\n"
        : "=r"(r0), "=r"(r1), "=r"(r2), "=r"(r3) : "r"(addr));
}

// ---- cp.async helpers ------------------------------------------------------
__device__ __forceinline__ void cp16(uint32_t dst_smem, const void* src)
{
    asm volatile("cp.async.cg.shared.global [%0], [%1], 16;"
                 :: "r"(dst_smem), "l"(src));
}
__device__ __forceinline__ void cp_commit()
{
    asm volatile("cp.async.commit_group;" ::: "memory");
}
__device__ __forceinline__ void cp_wait1()
{
    asm volatile("cp.async.wait_group 1;" ::: "memory");
}

// ---------------------------------------------------------------------------
// Fused prep kernel (single launch):
//   blocks [0, 8192)       : pack X rows -> fp16 pairs
//   blocks [8192, 8960)    : pack W tiles -> transposed fp16 pairs
//   blocks [8960, 9984)    : mask all-ones flags
// ---------------------------------------------------------------------------
__global__ __launch_bounds__(256) void prep_kernel(
    const float* __restrict__ from_t, const float* __restrict__ to_t,
    const float* __restrict__ Wq, const float* __restrict__ Wk,
    const float* __restrict__ Wv, const int* __restrict__ mask)
{
    __shared__ float T[64][65];
    const int bidx = blockIdx.x;

    if (bidx < 8192) {
        // --- pack X ---
        int r = bidx;
        int c4 = threadIdx.x;
        const float* src = (r < BSROWS) ? (from_t + r*DMODEL)
                                        : (to_t + (r - BSROWS)*DMODEL);
        float4 f = *(const float4*)&src[c4*4];
        *(uint2*)&g_x[r*KPD + c4*2] =
            make_uint2(round_pair_h(f.x, f.y), round_pair_h(f.z, f.w));
    } else if (bidx < 8960) {
        // --- pack W (64k x 64n tile with smem transpose) ---
        int idx = bidx - 8192;          // 0..767
        int z   = idx >> 8;             // /256
        int rem = idx & 255;
        int kt  = (rem >> 4) * 64;
        int nt  = (rem & 15) * 64;
        const float* W = (z == 0) ? Wq : (z == 1 ? Wk : Wv);

        #pragma unroll
        for (int p = 0; p < 4; p++) {
            int i2 = threadIdx.x + p*256;
            int kr = i2 >> 4;
            int c4 = (i2 & 15) * 4;
            float4 v = *(const float4*)&W[(kt+kr)*DMODEL + nt + c4];
            T[kr][c4+0] = v.x; T[kr][c4+1] = v.y;
            T[kr][c4+2] = v.z; T[kr][c4+3] = v.w;
        }
        __syncthreads();

        const int kt2 = kt >> 1;
        #pragma unroll
        for (int p = 0; p < 8; p++) {
            int o = threadIdx.x + p*256;
            int n  = o >> 5;
            int kp = o & 31;
            int gidx = (z*DMODEL + nt + n)*KPD + kt2 + kp;
            g_w[gidx] = round_pair_h(T[2*kp][n], T[2*kp+1][n]);
        }
    } else {
        // --- mask flags ---
        int idx = bidx - 8960;          // 0..1023
        int b   = idx >> 9;             // /512
        int rem = idx & 511;
        int fy  = rem >> 5;             // f-tile 0..15
        int tx  = rem & 31;             // t-chunk 0..31
        int f   = fy*128 + (threadIdx.x >> 1);
        int tc  = tx*64  + (threadIdx.x & 1)*32;
        const int4* p = (const int4*)&mask[(b*SEQ + f)*SEQ + tc];
        int ok = 1;
        #pragma unroll
        for (int i = 0; i < 8; i++) {
            int4 v = p[i];
            ok &= (v.x == 1) & (v.y == 1) & (v.z == 1) & (v.w == 1);
        }
        ok = __syncthreads_and(ok);
        if (threadIdx.x == 0)
            g_mflag[(b*16 + fy)*32 + tx] = (unsigned char)ok;
    }
}

// ---------------------------------------------------------------------------
// Kernel: QKV projection GEMM, pure fp16 (fp32 accum), depth-2 cp.async ring.
// Block 128m x 64n, 8 warps (4m x 2n), warp 32x32, K-step 32.
// Stage: X 128x20 | W 64x20 = 3840 u32; 3 stages.
// ---------------------------------------------------------------------------
#define PSTG 3840
#define PB_H 2560

__global__ __launch_bounds__(256, 2) void qkv_proj_kernel(
    const float* __restrict__ bq, const float* __restrict__ bk,
    const float* __restrict__ bv)
{
    extern __shared__ uint32_t dsm[];

    const int z = blockIdx.z;
    const uint32_t* Xp = g_x + (z == 0 ? 0 : BSROWS*KPD);
    const uint32_t* Wp = g_w + z*DMODEL*KPD;
    const float* bias  = (z == 0) ? bq : (z == 1 ? bk : bv);
    uint32_t* dst      = (z == 0) ? g_q : (z == 1 ? g_k : g_v);

    const int m0 = blockIdx.y * 128;
    const int n0 = blockIdx.x * 64;
    const int tid  = threadIdx.x;
    const int wid  = tid >> 5;
    const int lane = tid & 31;
    const int g  = lane >> 2;
    const int tg = lane & 3;
    const int wm = (wid >> 1) * 32;
    const int wn = (wid & 1) * 32;

    const int ar = tid >> 2;          // row 0..63 (A also +64)
    const int aq = (tid & 3) * 4;     // uint4 col within 16 k-pairs

    const int koffA = (lane & 15)*20 + (lane >> 4)*4;
    const uint32_t sBase = (uint32_t)__cvta_generic_to_shared(dsm);

    auto prefetch = [&](int stage, int kq) {
        uint32_t sb = sBase + (uint32_t)(stage * PSTG) * 4u;
        cp16(sb + (ar*20 + aq)*4u,        &Xp[(m0+ar)*KPD + kq + aq]);
        cp16(sb + ((ar+64)*20 + aq)*4u,   &Xp[(m0+ar+64)*KPD + kq + aq]);
        cp16(sb + (PB_H + ar*20 + aq)*4u, &Wp[(n0+ar)*KPD + kq + aq]);
    };

    float acc[2][4][4] = {};

    // depth-2 prologue
    prefetch(0, 0);  cp_commit();
    prefetch(1, 16); cp_commit();

    for (int it = 0; it < 32; it++) {
        cp_wait1();          // all but newest 1 group done -> stage it ready
        __syncthreads();     // all warps done reading stage (it-1)%3
        if (it + 2 < 32) prefetch((it + 2) % 3, (it + 2) * 16);
        cp_commit();         // unconditional: keeps group accounting uniform

        const uint32_t aB = sBase + (uint32_t)((it % 3) * PSTG) * 4u;
        #pragma unroll
        for (int ks = 0; ks < 2; ks++) {
            int kb = ks * 8;
            uint32_t ah[2][4], bh[2][4];
            #pragma unroll
            for (int mi = 0; mi < 2; mi++) {
                uint32_t off = (uint32_t)((wm + mi*16)*20 + kb + koffA) * 4u;
                ldsm_x4(ah[mi][0], ah[mi][1], ah[mi][2], ah[mi][3], aB + off);
            }
            #pragma unroll
            for (int nip = 0; nip < 2; nip++) {
                uint32_t off = (uint32_t)((wn + nip*16)*20 + kb + koffA) * 4u;
                ldsm_x4(bh[nip][0], bh[nip][1], bh[nip][2], bh[nip][3], aB + PB_H*4u + off);
            }
            #pragma unroll
            for (int nip = 0; nip < 2; nip++) {
                #pragma unroll
                for (int j = 0; j < 2; j++) {
                    int ni = nip*2 + j;
                    #pragma unroll
                    for (int mi = 0; mi < 2; mi++) {
                        mma_f16(acc[mi][ni], ah[mi][0],ah[mi][1],ah[mi][2],ah[mi][3],
                                bh[nip][j], bh[nip][2+j]);
                    }
                }
            }
        }
        __syncthreads();     // stage it fully consumed before it is overwritten
    }

    // --- epilogue: bias, round to fp16 pairs, write scratch [bh][s][h/2] ---
    const int head = n0 >> 6;
    #pragma unroll
    for (int ni = 0; ni < 4; ni++) {
        int h = wn + ni*8 + 2*tg;
        int hp = h >> 1;
        float2 b2 = *(const float2*)&bias[n0 + h];
        #pragma unroll
        for (int mi = 0; mi < 2; mi++) {
            int r0 = m0 + wm + mi*16 + g;
            int r1 = r0 + 8;
            int b0i = r0 >> 11, s0 = r0 & (SEQ-1);
            int b1i = r1 >> 11, s1 = r1 & (SEQ-1);
            size_t i0 = ((size_t)(b0i*NHEADS + head)*SEQ + s0)*HP + hp;
            size_t i1 = ((size_t)(b1i*NHEADS + head)*SEQ + s1)*HP + hp;
            dst[i0] = round_pair_h(acc[mi][ni][0] + b2.x, acc[mi][ni][1] + b2.y);
            dst[i1] = round_pair_h(acc[mi][ni][2] + b2.x, acc[mi][ni][3] + b2.y);
        }
    }
}

// ---------------------------------------------------------------------------
// Kernel: flash attention, pure fp16 (fp32 accum), depth-2 cp.async ring.
// Stage: K 64x36 | V 64x36 = 4608 u32; 3 stages.
// ---------------------------------------------------------------------------
#define ASTG 4608
#define A_VH 2304

__global__ __launch_bounds__(256, 2) void attn_kernel(
    const int* __restrict__ mask, float* __restrict__ out)
{
    extern __shared__ uint32_t asm_dsm[];

    const int f0   = blockIdx.x * 128;
    const int head = blockIdx.y;
    const int b    = blockIdx.z;
    const int bh   = b*NHEADS + head;
    const int tid  = threadIdx.x;
    const int lane = tid & 31;
    const int g  = lane >> 2;
    const int tg = lane & 3;
    const int fb = (tid >> 5) * 16;

    const int frow0 = f0 + fb + g;
    const int frow1 = frow0 + 8;

    const int koffK = ((((lane>>4)&1)*8 + (lane&7))*36 + ((lane>>3)&1)*4);
    const int koffV = ((((lane>>3)&1)*8 + (lane&7))*36 + ((lane>>4)&1)*4);

    const uint32_t sBase = (uint32_t)__cvta_generic_to_shared(asm_dsm);

    // --- preload Q fragments ---
    uint32_t qh[4][4];
    {
        const uint32_t* qp = g_q + bh*SEQ*HP;
        int q0 = frow0*HP, q1 = frow1*HP;
        #pragma unroll
        for (int ks = 0; ks < 4; ks++) {
            int kb = ks*8 + tg;
            qh[ks][0] = qp[q0 + kb];   qh[ks][1] = qp[q1 + kb];
            qh[ks][2] = qp[q0 + kb+4]; qh[ks][3] = qp[q1 + kb+4];
        }
    }

    const uint32_t* kb_g = g_k + bh*SEQ*HP;
    const uint32_t* vb_g = g_v + bh*SEQ*HP;
    const unsigned char* mfl = &g_mflag[(b*16 + blockIdx.x)*32];

    float m0 = -1e30f, m1 = -1e30f;
    float l0s = 0.0f, l1s = 0.0f;
    float O[8][4] = {};

    const int cr  = tid >> 3;        // 0..31 -> rows cr, cr+32
    const int cc4 = (tid & 7) * 4;

    auto prefetch = [&](int stage, int t0) {
        uint32_t sb = sBase + (uint32_t)(stage * ASTG) * 4u;
        cp16(sb + (cr*36 + cc4)*4u,               &kb_g[(t0+cr)*HP + cc4]);
        cp16(sb + ((cr+32)*36 + cc4)*4u,          &kb_g[(t0+cr+32)*HP + cc4]);
        cp16(sb + (A_VH + cr*36 + cc4)*4u,        &vb_g[(t0+cr)*HP + cc4]);
        cp16(sb + (A_VH + (cr+32)*36 + cc4)*4u,   &vb_g[(t0+cr+32)*HP + cc4]);
    };

    // depth-2 prologue
    prefetch(0, 0);   cp_commit();
    prefetch(1, 64);  cp_commit();

    for (int it = 0; it < SEQ/64; it++) {
        const int t0 = it * 64;
        cp_wait1();
        __syncthreads();
        if (it + 2 < SEQ/64) prefetch((it + 2) % 3, t0 + 128);
        cp_commit();

        const uint32_t sb = sBase + (uint32_t)((it % 3) * ASTG) * 4u;
        const uint32_t khB = sb;
        const uint32_t vhB = sb + A_VH*4u;

        // --- S = Q K^T ---
        float s[8][4] = {};
        #pragma unroll
        for (int ks = 0; ks < 4; ks++) {
            int kb = ks * 8;
            #pragma unroll
            for (int ntp = 0; ntp < 4; ntp++) {
                uint32_t off = (uint32_t)(ntp*16*36 + koffK + kb) * 4u;
                uint32_t k0,k1,k2,k3;
                ldsm_x4(k0,k1,k2,k3, khB + off);
                mma_f16(s[2*ntp],   qh[ks][0],qh[ks][1],qh[ks][2],qh[ks][3], k0, k1);
                mma_f16(s[2*ntp+1], qh[ks][0],qh[ks][1],qh[ks][2],qh[ks][3], k2, k3);
            }
        }

        // --- scale + mask (skippable) + chunk row max ---
        float rmax0 = -1e30f, rmax1 = -1e30f;
        if (mfl[it]) {
            #pragma unroll
            for (int nt = 0; nt < 8; nt++) {
                s[nt][0] *= 0.125f; s[nt][1] *= 0.125f;
                s[nt][2] *= 0.125f; s[nt][3] *= 0.125f;
                rmax0 = fmaxf(rmax0, fmaxf(s[nt][0], s[nt][1]));
                rmax1 = fmaxf(rmax1, fmaxf(s[nt][2], s[nt][3]));
            }
        } else {
            #pragma unroll
            for (int nt = 0; nt < 8; nt++) {
                int tc = t0 + nt*8 + 2*tg;
                int2 mk0 = *(const int2*)&mask[(b*SEQ + frow0)*SEQ + tc];
                int2 mk1 = *(const int2*)&mask[(b*SEQ + frow1)*SEQ + tc];
                s[nt][0] = s[nt][0]*0.125f + (1.0f - (float)mk0.x) * -10000.0f;
                s[nt][1] = s[nt][1]*0.125f + (1.0f - (float)mk0.y) * -10000.0f;
                s[nt][2] = s[nt][2]*0.125f + (1.0f - (float)mk1.x) * -10000.0f;
                s[nt][3] = s[nt][3]*0.125f + (1.0f - (float)mk1.y) * -10000.0f;
                rmax0 = fmaxf(rmax0, fmaxf(s[nt][0], s[nt][1]));
                rmax1 = fmaxf(rmax1, fmaxf(s[nt][2], s[nt][3]));
            }
        }
        rmax0 = fmaxf(rmax0, __shfl_xor_sync(0xffffffffu, rmax0, 1));
        rmax0 = fmaxf(rmax0, __shfl_xor_sync(0xffffffffu, rmax0, 2));
        rmax1 = fmaxf(rmax1, __shfl_xor_sync(0xffffffffu, rmax1, 1));
        rmax1 = fmaxf(rmax1, __shfl_xor_sync(0xffffffffu, rmax1, 2));

        float mn0 = fmaxf(m0, rmax0), mn1 = fmaxf(m1, rmax1);
        float a0 = __expf(m0 - mn0),  a1 = __expf(m1 - mn1);
        m0 = mn0; m1 = mn1;

        // --- exp + round P fragments to fp16 in registers ---
        uint32_t ph0[8], ph1[8];
        float ps0 = 0.0f, ps1 = 0.0f;
        #pragma unroll
        for (int nt = 0; nt < 8; nt++) {
            float p00 = __expf(s[nt][0] - mn0);
            float p01 = __expf(s[nt][1] - mn0);
            float p10 = __expf(s[nt][2] - mn1);
            float p11 = __expf(s[nt][3] - mn1);
            ps0 += p00 + p01;
            ps1 += p10 + p11;
            ph0[nt] = round_pair_h(p00, p01);
            ph1[nt] = round_pair_h(p10, p11);
        }
        ps0 += __shfl_xor_sync(0xffffffffu, ps0, 1);
        ps0 += __shfl_xor_sync(0xffffffffu, ps0, 2);
        ps1 += __shfl_xor_sync(0xffffffffu, ps1, 1);
        ps1 += __shfl_xor_sync(0xffffffffu, ps1, 2);
        l0s = l0s * a0 + ps0;
        l1s = l1s * a1 + ps1;

        #pragma unroll
        for (int ht = 0; ht < 8; ht++) {
            O[ht][0] *= a0; O[ht][1] *= a0;
            O[ht][2] *= a1; O[ht][3] *= a1;
        }

        // --- O += P V ---
        #pragma unroll
        for (int ks = 0; ks < 4; ks++) {
            uint32_t ah0 = ph0[2*ks],   ah1 = ph1[2*ks];
            uint32_t ah2 = ph0[2*ks+1], ah3 = ph1[2*ks+1];
            #pragma unroll
            for (int htp = 0; htp < 4; htp++) {
                uint32_t off = (uint32_t)(ks*16*36 + htp*8 + koffV) * 4u;
                uint32_t v0,v1,v2,v3;
                ldsm_x4_trans(v0,v1,v2,v3, vhB + off);
                mma_f16(O[2*htp],   ah0,ah1,ah2,ah3, v0, v1);
                mma_f16(O[2*htp+1], ah0,ah1,ah2,ah3, v2, v3);
            }
        }
    }

    float inv0 = 1.0f / l0s;
    float inv1 = 1.0f / l1s;
    #pragma unroll
    for (int ht = 0; ht < 8; ht++) {
        int h = ht*8 + 2*tg;
        float2 r0 = make_float2(O[ht][0]*inv0, O[ht][1]*inv0);
        float2 r1 = make_float2(O[ht][2]*inv1, O[ht][3]*inv1);
        *(float2*)&out[(b*SEQ + frow0)*DMODEL + head*HDIM + h] = r0;
        *(float2*)&out[(b*SEQ + frow1)*DMODEL + head*HDIM + h] = r1;
    }
}

// ---------------------------------------------------------------------------
extern "C" void kernel_launch(void* const* d_in, const int* in_sizes, int n_in,
                              void* d_out, int out_size)
{
    const float* from_t = (const float*)d_in[0];
    const float* to_t   = (const float*)d_in[1];
    const int*   mask   = (const int*)  d_in[2];
    const float* Wq = (const float*)d_in[3];
    const float* bq = (const float*)d_in[4];
    const float* Wk = (const float*)d_in[5];
    const float* bk = (const float*)d_in[6];
    const float* Wv = (const float*)d_in[7];
    const float* bv = (const float*)d_in[8];
    float* out = (float*)d_out;

    prep_kernel<<<9984, 256>>>(from_t, to_t, Wq, Wk, Wv, mask);

    const int proj_smem = 3 * PSTG * 4;   // 46080 B
    cudaFuncSetAttribute(qkv_proj_kernel,
                         cudaFuncAttributeMaxDynamicSharedMemorySize, proj_smem);
    dim3 pgrid(DMODEL/64, BSROWS/128, 3);
    qkv_proj_kernel<<<pgrid, 256, proj_smem>>>(bq, bk, bv);

    const int attn_smem = 3 * ASTG * 4;   // 55296 B
    cudaFuncSetAttribute(attn_kernel,
                         cudaFuncAttributeMaxDynamicSharedMemorySize, attn_smem);
    dim3 agrid(SEQ/128, NHEADS, BATCH);
    attn_kernel<<<agrid, 256, attn_smem>>>(mask, out);
}